// round 4
// baseline (speedup 1.0000x reference)
#include <cuda_runtime.h>
#include <math.h>

// ---------------------------------------------------------------------------
// BERT-base forward, fp32 baseline.
// B=8 S=512 D=768 H=12 DK=64 F=3072 L=12
// ---------------------------------------------------------------------------
#define BB 8
#define SS 512
#define DD 768
#define HH 12
#define DKK 64
#define FF 3072
#define LL 12
#define MTOK (BB*SS)          // 4096 tokens
#define NHB (BB*HH)           // 96 (batch*heads)
#define SCALE 0.125f          // 1/sqrt(64)

// ------------------------------- scratch -----------------------------------
__device__ float g_x[MTOK*DD];
__device__ float g_q[MTOK*DD];
__device__ float g_k[MTOK*DD];
__device__ float g_v[MTOK*DD];
__device__ float g_c[MTOK*DD];
__device__ float g_t[MTOK*DD];
__device__ float g_a[MTOK*DD];
__device__ float g_h[MTOK*FF];
__device__ float g_s[(long)NHB*SS*SS];

// --------------------------- block reductions -------------------------------
__device__ __forceinline__ float block_sum256(float v, float* sh) {
    int lane = threadIdx.x & 31, w = threadIdx.x >> 5;
    #pragma unroll
    for (int o = 16; o > 0; o >>= 1) v += __shfl_xor_sync(0xffffffffu, v, o);
    if (lane == 0) sh[w] = v;
    __syncthreads();
    float r = 0.f;
    #pragma unroll
    for (int i = 0; i < 8; i++) r += sh[i];
    __syncthreads();
    return r;
}

__device__ __forceinline__ float block_max256(float v, float* sh) {
    int lane = threadIdx.x & 31, w = threadIdx.x >> 5;
    #pragma unroll
    for (int o = 16; o > 0; o >>= 1) v = fmaxf(v, __shfl_xor_sync(0xffffffffu, v, o));
    if (lane == 0) sh[w] = v;
    __syncthreads();
    float r = -1e30f;
    #pragma unroll
    for (int i = 0; i < 8; i++) r = fmaxf(r, sh[i]);
    __syncthreads();
    return r;
}

// -------------------------- embedding + LN ----------------------------------
// one block per token, 256 threads, 3 elems/thread over D=768
__global__ void embed_ln_kernel(const int* __restrict__ ids,
                                const int* __restrict__ tt,
                                const float* __restrict__ we,
                                const float* __restrict__ pe,
                                const float* __restrict__ te,
                                const float* __restrict__ gamma,
                                const float* __restrict__ beta,
                                float* __restrict__ out) {
    __shared__ float sh[8];
    int m = blockIdx.x;
    int s = m & (SS - 1);
    int id = ids[m];
    int ty = tt[m];
    int t = threadIdx.x;
    float v[3];
    #pragma unroll
    for (int i = 0; i < 3; i++) {
        int d = t + i * 256;
        v[i] = we[(long)id * DD + d] + te[(long)ty * DD + d] + pe[(long)s * DD + d];
    }
    float sum = block_sum256(v[0] + v[1] + v[2], sh);
    float mu = sum * (1.f / DD);
    float qs = 0.f;
    #pragma unroll
    for (int i = 0; i < 3; i++) { float d0 = v[i] - mu; qs += d0 * d0; }
    qs = block_sum256(qs, sh);
    float rstd = rsqrtf(qs * (1.f / DD) + 1e-12f);
    #pragma unroll
    for (int i = 0; i < 3; i++) {
        int d = t + i * 256;
        out[(long)m * DD + d] = (v[i] - mu) * rstd * gamma[d] + beta[d];
    }
}

// ------------------------------ LN (768) -------------------------------------
// out = LN(in + bias + resid) ; bias/resid nullable
__global__ void ln768_kernel(const float* __restrict__ in,
                             const float* __restrict__ resid,
                             const float* __restrict__ bias,
                             const float* __restrict__ gamma,
                             const float* __restrict__ beta,
                             float* __restrict__ out, float eps) {
    __shared__ float sh[8];
    long m = blockIdx.x;
    int t = threadIdx.x;
    float v[3];
    #pragma unroll
    for (int i = 0; i < 3; i++) {
        int d = t + i * 256;
        float x = in[m * DD + d];
        if (bias) x += bias[d];
        if (resid) x += resid[m * DD + d];
        v[i] = x;
    }
    float sum = block_sum256(v[0] + v[1] + v[2], sh);
    float mu = sum * (1.f / DD);
    float qs = 0.f;
    #pragma unroll
    for (int i = 0; i < 3; i++) { float d0 = v[i] - mu; qs += d0 * d0; }
    qs = block_sum256(qs, sh);
    float rstd = rsqrtf(qs * (1.f / DD) + eps);
    #pragma unroll
    for (int i = 0; i < 3; i++) {
        int d = t + i * 256;
        out[m * DD + d] = (v[i] - mu) * rstd * gamma[d] + beta[d];
    }
}

// ------------------------------ GEMM NT --------------------------------------
// C[m,n] = alpha * sum_k A[m,k]*B[n,k] (+ bias[n])
// A: M x K row-major (+ z*sA), B: N x K row-major (+ z*sB), C offset z*sC.
// mode 0: C[m*N+n].  mode 1: head-permute -> out[((b*H+h)*S+s)*DK+dk]
// Tiles: 64x64x32, 256 threads, 4x4 microtile.
__global__ void gemm_nt_kernel(const float* __restrict__ A, long sA,
                               const float* __restrict__ Bm, long sB,
                               const float* __restrict__ bias,
                               float* __restrict__ C, long sC,
                               int M, int N, int K, float alpha, int mode) {
    __shared__ float As[64][33];
    __shared__ float Bs[64][33];
    int z = blockIdx.z;
    A += (long)z * sA;
    Bm += (long)z * sB;
    C += (long)z * sC;
    int tid = threadIdx.x;
    int tx = tid & 15, ty = tid >> 4;
    int m0 = blockIdx.y * 64;
    int n0 = blockIdx.x * 64;
    float acc[4][4] = {};
    for (int k0 = 0; k0 < K; k0 += 32) {
        #pragma unroll
        for (int i = 0; i < 8; i++) {
            int li = tid + i * 256;
            int r = li >> 5, c = li & 31;
            As[r][c] = A[(long)(m0 + r) * K + k0 + c];
            Bs[r][c] = Bm[(long)(n0 + r) * K + k0 + c];
        }
        __syncthreads();
        #pragma unroll
        for (int kk = 0; kk < 32; kk++) {
            float ra[4], rb[4];
            #pragma unroll
            for (int i = 0; i < 4; i++) ra[i] = As[ty * 4 + i][kk];
            #pragma unroll
            for (int j = 0; j < 4; j++) rb[j] = Bs[tx * 4 + j][kk];
            #pragma unroll
            for (int i = 0; i < 4; i++)
                #pragma unroll
                for (int j = 0; j < 4; j++)
                    acc[i][j] += ra[i] * rb[j];
        }
        __syncthreads();
    }
    #pragma unroll
    for (int i = 0; i < 4; i++) {
        int m = m0 + ty * 4 + i;
        #pragma unroll
        for (int j = 0; j < 4; j++) {
            int n = n0 + tx * 4 + j;
            float val = acc[i][j] * alpha;
            if (bias) val += bias[n];
            if (mode == 0) {
                C[(long)m * N + n] = val;
            } else {
                // permute [token, e] -> [b, h, s, dk]
                int b = m >> 9, s = m & (SS - 1);
                int h = n >> 6, dk = n & (DKK - 1);
                C[(((long)(b * HH + h) * SS) + s) * DKK + dk] = val;
            }
        }
    }
}

// ------------------------------ softmax --------------------------------------
// one block per score row; 256 threads, 2 elems each over S=512
__global__ void softmax_kernel(float* __restrict__ scores,
                               const float* __restrict__ amask) {
    __shared__ float sh[8];
    int z = blockIdx.y;            // b*H + h
    int qr = blockIdx.x;           // query row
    int b = z / HH;
    float* row = scores + ((long)z * SS + qr) * SS;
    int t = threadIdx.x;
    float v[2];
    #pragma unroll
    for (int i = 0; i < 2; i++) {
        int k = t + i * 256;
        float s = row[k];
        if (amask[b * SS + k] == 0.f) s = -1e9f;
        v[i] = s;
    }
    float mx = block_max256(fmaxf(v[0], v[1]), sh);
    float e0 = __expf(v[0] - mx);
    float e1 = __expf(v[1] - mx);
    float sum = block_sum256(e0 + e1, sh);
    float inv = 1.f / sum;
    row[t] = e0 * inv;
    row[t + 256] = e1 * inv;
}

// ------------------------------ P @ V ----------------------------------------
// per z=b*H+h:  ctx[b, q, h*64+dk] = sum_k P[z,q,k] * V[z,k,dk]
// BM=64, BN=64(=DK), BK=32.
__global__ void gemm_pv_kernel(const float* __restrict__ P,
                               const float* __restrict__ V,
                               float* __restrict__ ctx) {
    __shared__ float As[64][33];   // P tile [m][k]
    __shared__ float Bs[32][65];   // V tile [k][n]
    int z = blockIdx.z;
    int b = z / HH, h = z % HH;
    const float* Pz = P + (long)z * SS * SS;
    const float* Vz = V + (long)z * SS * DKK;
    int tid = threadIdx.x;
    int tx = tid & 15, ty = tid >> 4;
    int m0 = blockIdx.y * 64;
    float acc[4][4] = {};
    for (int k0 = 0; k0 < SS; k0 += 32) {
        #pragma unroll
        for (int i = 0; i < 8; i++) {
            int li = tid + i * 256;
            int r = li >> 5, c = li & 31;
            As[r][c] = Pz[(long)(m0 + r) * SS + k0 + c];
            int r2 = li >> 6, c2 = li & 63;
            Bs[r2][c2] = Vz[(long)(k0 + r2) * DKK + c2];
        }
        __syncthreads();
        #pragma unroll
        for (int kk = 0; kk < 32; kk++) {
            float ra[4], rb[4];
            #pragma unroll
            for (int i = 0; i < 4; i++) ra[i] = As[ty * 4 + i][kk];
            #pragma unroll
            for (int j = 0; j < 4; j++) rb[j] = Bs[kk][tx * 4 + j];
            #pragma unroll
            for (int i = 0; i < 4; i++)
                #pragma unroll
                for (int j = 0; j < 4; j++)
                    acc[i][j] += ra[i] * rb[j];
        }
        __syncthreads();
    }
    #pragma unroll
    for (int i = 0; i < 4; i++) {
        int q = m0 + ty * 4 + i;
        #pragma unroll
        for (int j = 0; j < 4; j++) {
            int dk = tx * 4 + j;
            ctx[((long)(b * SS + q) * DD) + h * DKK + dk] = acc[i][j];
        }
    }
}

// ------------------------------- launch --------------------------------------
extern "C" void kernel_launch(void* const* d_in, const int* in_sizes, int n_in,
                              void* d_out, int out_size) {
    const int*   input_ids = (const int*)  d_in[0];
    const int*   type_ids  = (const int*)  d_in[1];
    const float* amask     = (const float*)d_in[2];
    const float* word_emb  = (const float*)d_in[3];
    const float* pos_emb   = (const float*)d_in[4];
    const float* type_emb  = (const float*)d_in[5];
    const float* emb_g     = (const float*)d_in[6];
    const float* emb_b     = (const float*)d_in[7];
    const float* Wq = (const float*)d_in[8];
    const float* bq = (const float*)d_in[9];
    const float* Wk = (const float*)d_in[10];
    const float* bk = (const float*)d_in[11];
    const float* Wv = (const float*)d_in[12];
    const float* bv = (const float*)d_in[13];
    const float* Wo = (const float*)d_in[14];
    const float* bo = (const float*)d_in[15];
    const float* ag = (const float*)d_in[16];
    const float* ab = (const float*)d_in[17];
    const float* W1 = (const float*)d_in[18];
    const float* b1 = (const float*)d_in[19];
    const float* W2 = (const float*)d_in[20];
    const float* b2 = (const float*)d_in[21];
    const float* fg = (const float*)d_in[22];
    const float* fb = (const float*)d_in[23];

    float *x, *q, *k, *v, *c, *t, *a, *h, *s;
    cudaGetSymbolAddress((void**)&x, g_x);
    cudaGetSymbolAddress((void**)&q, g_q);
    cudaGetSymbolAddress((void**)&k, g_k);
    cudaGetSymbolAddress((void**)&v, g_v);
    cudaGetSymbolAddress((void**)&c, g_c);
    cudaGetSymbolAddress((void**)&t, g_t);
    cudaGetSymbolAddress((void**)&a, g_a);
    cudaGetSymbolAddress((void**)&h, g_h);
    cudaGetSymbolAddress((void**)&s, g_s);

    embed_ln_kernel<<<MTOK, 256>>>(input_ids, type_ids, word_emb, pos_emb,
                                   type_emb, emb_g, emb_b, x);

    for (int l = 0; l < LL; l++) {
        const float* wq = Wq + (long)l * DD * DD;
        const float* wk = Wk + (long)l * DD * DD;
        const float* wv = Wv + (long)l * DD * DD;
        const float* wo = Wo + (long)l * DD * DD;
        const float* w1 = W1 + (long)l * FF * DD;
        const float* w2 = W2 + (long)l * DD * FF;

        dim3 gProj(DD / 64, MTOK / 64, 1);
        // Q,K,V projections, written head-permuted [b,h,s,dk]
        gemm_nt_kernel<<<gProj, 256>>>(x, 0, wq, 0, bq + l * DD, q, 0,
                                       MTOK, DD, DD, 1.f, 1);
        gemm_nt_kernel<<<gProj, 256>>>(x, 0, wk, 0, bk + l * DD, k, 0,
                                       MTOK, DD, DD, 1.f, 1);
        gemm_nt_kernel<<<gProj, 256>>>(x, 0, wv, 0, bv + l * DD, v, 0,
                                       MTOK, DD, DD, 1.f, 1);
        // scores = scale * Q K^T  (batched over 96 heads)
        dim3 gSc(SS / 64, SS / 64, NHB);
        gemm_nt_kernel<<<gSc, 256>>>(q, (long)SS * DKK, k, (long)SS * DKK,
                                     nullptr, s, (long)SS * SS,
                                     SS, SS, DKK, SCALE, 0);
        dim3 gSm(SS, NHB, 1);
        softmax_kernel<<<gSm, 256>>>(s, amask);
        // ctx = P V  (writes back to [b,s,e] layout)
        dim3 gPv(1, SS / 64, NHB);
        gemm_pv_kernel<<<gPv, 256>>>(s, v, c);
        // O projection (bias folded into LN)
        gemm_nt_kernel<<<gProj, 256>>>(c, 0, wo, 0, nullptr, t, 0,
                                       MTOK, DD, DD, 1.f, 0);
        ln768_kernel<<<MTOK, 256>>>(t, x, bo + l * DD, ag + l * DD, ab + l * DD,
                                    a, 1e-5f);
        // FFN
        dim3 gF1(FF / 64, MTOK / 64, 1);
        gemm_nt_kernel<<<gF1, 256>>>(a, 0, w1, 0, b1 + l * FF, h, 0,
                                     MTOK, FF, DD, 1.f, 0);
        gemm_nt_kernel<<<gProj, 256>>>(h, 0, w2, 0, nullptr, t, 0,
                                       MTOK, DD, FF, 1.f, 0);
        ln768_kernel<<<MTOK, 256>>>(t, nullptr, b2 + l * DD, fg + l * DD,
                                    fb + l * DD, x, 1e-5f);
    }

    cudaMemcpyAsync(d_out, x, (size_t)MTOK * DD * sizeof(float),
                    cudaMemcpyDeviceToDevice);
}

// round 5
// speedup vs baseline: 1.0002x; 1.0002x over previous
#include <cuda_runtime.h>
#include <math.h>

// ---------------------------------------------------------------------------
// BERT-base forward, fp32 baseline.
// B=8 S=512 D=768 H=12 DK=64 F=3072 L=12
// ---------------------------------------------------------------------------
#define BB 8
#define SS 512
#define DD 768
#define HH 12
#define DKK 64
#define FF 3072
#define LL 12
#define MTOK (BB*SS)          // 4096 tokens
#define NHB (BB*HH)           // 96 (batch*heads)
#define SCALE 0.125f          // 1/sqrt(64)

// ------------------------------- scratch -----------------------------------
__device__ float g_x[MTOK*DD];
__device__ float g_q[MTOK*DD];
__device__ float g_k[MTOK*DD];
__device__ float g_v[MTOK*DD];
__device__ float g_c[MTOK*DD];
__device__ float g_t[MTOK*DD];
__device__ float g_a[MTOK*DD];
__device__ float g_h[MTOK*FF];
__device__ float g_s[(long)NHB*SS*SS];

// --------------------------- block reductions -------------------------------
__device__ __forceinline__ float block_sum256(float v, float* sh) {
    int lane = threadIdx.x & 31, w = threadIdx.x >> 5;
    #pragma unroll
    for (int o = 16; o > 0; o >>= 1) v += __shfl_xor_sync(0xffffffffu, v, o);
    if (lane == 0) sh[w] = v;
    __syncthreads();
    float r = 0.f;
    #pragma unroll
    for (int i = 0; i < 8; i++) r += sh[i];
    __syncthreads();
    return r;
}

__device__ __forceinline__ float block_max256(float v, float* sh) {
    int lane = threadIdx.x & 31, w = threadIdx.x >> 5;
    #pragma unroll
    for (int o = 16; o > 0; o >>= 1) v = fmaxf(v, __shfl_xor_sync(0xffffffffu, v, o));
    if (lane == 0) sh[w] = v;
    __syncthreads();
    float r = -1e30f;
    #pragma unroll
    for (int i = 0; i < 8; i++) r = fmaxf(r, sh[i]);
    __syncthreads();
    return r;
}

// -------------------------- embedding + LN ----------------------------------
// one block per token, 256 threads, 3 elems/thread over D=768
__global__ void embed_ln_kernel(const int* __restrict__ ids,
                                const int* __restrict__ tt,
                                const float* __restrict__ we,
                                const float* __restrict__ pe,
                                const float* __restrict__ te,
                                const float* __restrict__ gamma,
                                const float* __restrict__ beta,
                                float* __restrict__ out) {
    __shared__ float sh[8];
    int m = blockIdx.x;
    int s = m & (SS - 1);
    int id = ids[m];
    int ty = tt[m];
    int t = threadIdx.x;
    float v[3];
    #pragma unroll
    for (int i = 0; i < 3; i++) {
        int d = t + i * 256;
        v[i] = we[(long)id * DD + d] + te[(long)ty * DD + d] + pe[(long)s * DD + d];
    }
    float sum = block_sum256(v[0] + v[1] + v[2], sh);
    float mu = sum * (1.f / DD);
    float qs = 0.f;
    #pragma unroll
    for (int i = 0; i < 3; i++) { float d0 = v[i] - mu; qs += d0 * d0; }
    qs = block_sum256(qs, sh);
    float rstd = rsqrtf(qs * (1.f / DD) + 1e-12f);
    #pragma unroll
    for (int i = 0; i < 3; i++) {
        int d = t + i * 256;
        out[(long)m * DD + d] = (v[i] - mu) * rstd * gamma[d] + beta[d];
    }
}

// ------------------------------ LN (768) -------------------------------------
// out = LN(in + bias + resid) ; bias/resid nullable
__global__ void ln768_kernel(const float* __restrict__ in,
                             const float* __restrict__ resid,
                             const float* __restrict__ bias,
                             const float* __restrict__ gamma,
                             const float* __restrict__ beta,
                             float* __restrict__ out, float eps) {
    __shared__ float sh[8];
    long m = blockIdx.x;
    int t = threadIdx.x;
    float v[3];
    #pragma unroll
    for (int i = 0; i < 3; i++) {
        int d = t + i * 256;
        float x = in[m * DD + d];
        if (bias) x += bias[d];
        if (resid) x += resid[m * DD + d];
        v[i] = x;
    }
    float sum = block_sum256(v[0] + v[1] + v[2], sh);
    float mu = sum * (1.f / DD);
    float qs = 0.f;
    #pragma unroll
    for (int i = 0; i < 3; i++) { float d0 = v[i] - mu; qs += d0 * d0; }
    qs = block_sum256(qs, sh);
    float rstd = rsqrtf(qs * (1.f / DD) + eps);
    #pragma unroll
    for (int i = 0; i < 3; i++) {
        int d = t + i * 256;
        out[m * DD + d] = (v[i] - mu) * rstd * gamma[d] + beta[d];
    }
}

// ------------------------------ GEMM NT --------------------------------------
// C[m,n] = alpha * sum_k A[m,k]*B[n,k] (+ bias[n])
// A: M x K row-major (+ z*sA), B: N x K row-major (+ z*sB), C offset z*sC.
// mode 0: C[m*N+n].  mode 1: head-permute -> out[((b*H+h)*S+s)*DK+dk]
// Tiles: 64x64x32, 256 threads, 4x4 microtile.
__global__ void gemm_nt_kernel(const float* __restrict__ A, long sA,
                               const float* __restrict__ Bm, long sB,
                               const float* __restrict__ bias,
                               float* __restrict__ C, long sC,
                               int M, int N, int K, float alpha, int mode) {
    __shared__ float As[64][33];
    __shared__ float Bs[64][33];
    int z = blockIdx.z;
    A += (long)z * sA;
    Bm += (long)z * sB;
    C += (long)z * sC;
    int tid = threadIdx.x;
    int tx = tid & 15, ty = tid >> 4;
    int m0 = blockIdx.y * 64;
    int n0 = blockIdx.x * 64;
    float acc[4][4] = {};
    for (int k0 = 0; k0 < K; k0 += 32) {
        #pragma unroll
        for (int i = 0; i < 8; i++) {
            int li = tid + i * 256;
            int r = li >> 5, c = li & 31;
            As[r][c] = A[(long)(m0 + r) * K + k0 + c];
            Bs[r][c] = Bm[(long)(n0 + r) * K + k0 + c];
        }
        __syncthreads();
        #pragma unroll
        for (int kk = 0; kk < 32; kk++) {
            float ra[4], rb[4];
            #pragma unroll
            for (int i = 0; i < 4; i++) ra[i] = As[ty * 4 + i][kk];
            #pragma unroll
            for (int j = 0; j < 4; j++) rb[j] = Bs[tx * 4 + j][kk];
            #pragma unroll
            for (int i = 0; i < 4; i++)
                #pragma unroll
                for (int j = 0; j < 4; j++)
                    acc[i][j] += ra[i] * rb[j];
        }
        __syncthreads();
    }
    #pragma unroll
    for (int i = 0; i < 4; i++) {
        int m = m0 + ty * 4 + i;
        #pragma unroll
        for (int j = 0; j < 4; j++) {
            int n = n0 + tx * 4 + j;
            float val = acc[i][j] * alpha;
            if (bias) val += bias[n];
            if (mode == 0) {
                C[(long)m * N + n] = val;
            } else {
                // permute [token, e] -> [b, h, s, dk]
                int b = m >> 9, s = m & (SS - 1);
                int h = n >> 6, dk = n & (DKK - 1);
                C[(((long)(b * HH + h) * SS) + s) * DKK + dk] = val;
            }
        }
    }
}

// ------------------------------ softmax --------------------------------------
// one block per score row; 256 threads, 2 elems each over S=512
__global__ void softmax_kernel(float* __restrict__ scores,
                               const float* __restrict__ amask) {
    __shared__ float sh[8];
    int z = blockIdx.y;            // b*H + h
    int qr = blockIdx.x;           // query row
    int b = z / HH;
    float* row = scores + ((long)z * SS + qr) * SS;
    int t = threadIdx.x;
    float v[2];
    #pragma unroll
    for (int i = 0; i < 2; i++) {
        int k = t + i * 256;
        float s = row[k];
        if (amask[b * SS + k] == 0.f) s = -1e9f;
        v[i] = s;
    }
    float mx = block_max256(fmaxf(v[0], v[1]), sh);
    float e0 = __expf(v[0] - mx);
    float e1 = __expf(v[1] - mx);
    float sum = block_sum256(e0 + e1, sh);
    float inv = 1.f / sum;
    row[t] = e0 * inv;
    row[t + 256] = e1 * inv;
}

// ------------------------------ P @ V ----------------------------------------
// per z=b*H+h:  ctx[b, q, h*64+dk] = sum_k P[z,q,k] * V[z,k,dk]
// BM=64, BN=64(=DK), BK=32.
__global__ void gemm_pv_kernel(const float* __restrict__ P,
                               const float* __restrict__ V,
                               float* __restrict__ ctx) {
    __shared__ float As[64][33];   // P tile [m][k]
    __shared__ float Bs[32][65];   // V tile [k][n]
    int z = blockIdx.z;
    int b = z / HH, h = z % HH;
    const float* Pz = P + (long)z * SS * SS;
    const float* Vz = V + (long)z * SS * DKK;
    int tid = threadIdx.x;
    int tx = tid & 15, ty = tid >> 4;
    int m0 = blockIdx.y * 64;
    float acc[4][4] = {};
    for (int k0 = 0; k0 < SS; k0 += 32) {
        #pragma unroll
        for (int i = 0; i < 8; i++) {
            int li = tid + i * 256;
            int r = li >> 5, c = li & 31;
            As[r][c] = Pz[(long)(m0 + r) * SS + k0 + c];
            int r2 = li >> 6, c2 = li & 63;
            Bs[r2][c2] = Vz[(long)(k0 + r2) * DKK + c2];
        }
        __syncthreads();
        #pragma unroll
        for (int kk = 0; kk < 32; kk++) {
            float ra[4], rb[4];
            #pragma unroll
            for (int i = 0; i < 4; i++) ra[i] = As[ty * 4 + i][kk];
            #pragma unroll
            for (int j = 0; j < 4; j++) rb[j] = Bs[kk][tx * 4 + j];
            #pragma unroll
            for (int i = 0; i < 4; i++)
                #pragma unroll
                for (int j = 0; j < 4; j++)
                    acc[i][j] += ra[i] * rb[j];
        }
        __syncthreads();
    }
    #pragma unroll
    for (int i = 0; i < 4; i++) {
        int q = m0 + ty * 4 + i;
        #pragma unroll
        for (int j = 0; j < 4; j++) {
            int dk = tx * 4 + j;
            ctx[((long)(b * SS + q) * DD) + h * DKK + dk] = acc[i][j];
        }
    }
}

// ------------------------------- launch --------------------------------------
extern "C" void kernel_launch(void* const* d_in, const int* in_sizes, int n_in,
                              void* d_out, int out_size) {
    const int*   input_ids = (const int*)  d_in[0];
    const int*   type_ids  = (const int*)  d_in[1];
    const float* amask     = (const float*)d_in[2];
    const float* word_emb  = (const float*)d_in[3];
    const float* pos_emb   = (const float*)d_in[4];
    const float* type_emb  = (const float*)d_in[5];
    const float* emb_g     = (const float*)d_in[6];
    const float* emb_b     = (const float*)d_in[7];
    const float* Wq = (const float*)d_in[8];
    const float* bq = (const float*)d_in[9];
    const float* Wk = (const float*)d_in[10];
    const float* bk = (const float*)d_in[11];
    const float* Wv = (const float*)d_in[12];
    const float* bv = (const float*)d_in[13];
    const float* Wo = (const float*)d_in[14];
    const float* bo = (const float*)d_in[15];
    const float* ag = (const float*)d_in[16];
    const float* ab = (const float*)d_in[17];
    const float* W1 = (const float*)d_in[18];
    const float* b1 = (const float*)d_in[19];
    const float* W2 = (const float*)d_in[20];
    const float* b2 = (const float*)d_in[21];
    const float* fg = (const float*)d_in[22];
    const float* fb = (const float*)d_in[23];

    float *x, *q, *k, *v, *c, *t, *a, *h, *s;
    cudaGetSymbolAddress((void**)&x, g_x);
    cudaGetSymbolAddress((void**)&q, g_q);
    cudaGetSymbolAddress((void**)&k, g_k);
    cudaGetSymbolAddress((void**)&v, g_v);
    cudaGetSymbolAddress((void**)&c, g_c);
    cudaGetSymbolAddress((void**)&t, g_t);
    cudaGetSymbolAddress((void**)&a, g_a);
    cudaGetSymbolAddress((void**)&h, g_h);
    cudaGetSymbolAddress((void**)&s, g_s);

    embed_ln_kernel<<<MTOK, 256>>>(input_ids, type_ids, word_emb, pos_emb,
                                   type_emb, emb_g, emb_b, x);

    for (int l = 0; l < LL; l++) {
        const float* wq = Wq + (long)l * DD * DD;
        const float* wk = Wk + (long)l * DD * DD;
        const float* wv = Wv + (long)l * DD * DD;
        const float* wo = Wo + (long)l * DD * DD;
        const float* w1 = W1 + (long)l * FF * DD;
        const float* w2 = W2 + (long)l * DD * FF;

        dim3 gProj(DD / 64, MTOK / 64, 1);
        // Q,K,V projections, written head-permuted [b,h,s,dk]
        gemm_nt_kernel<<<gProj, 256>>>(x, 0, wq, 0, bq + l * DD, q, 0,
                                       MTOK, DD, DD, 1.f, 1);
        gemm_nt_kernel<<<gProj, 256>>>(x, 0, wk, 0, bk + l * DD, k, 0,
                                       MTOK, DD, DD, 1.f, 1);
        gemm_nt_kernel<<<gProj, 256>>>(x, 0, wv, 0, bv + l * DD, v, 0,
                                       MTOK, DD, DD, 1.f, 1);
        // scores = scale * Q K^T  (batched over 96 heads)
        dim3 gSc(SS / 64, SS / 64, NHB);
        gemm_nt_kernel<<<gSc, 256>>>(q, (long)SS * DKK, k, (long)SS * DKK,
                                     nullptr, s, (long)SS * SS,
                                     SS, SS, DKK, SCALE, 0);
        dim3 gSm(SS, NHB, 1);
        softmax_kernel<<<gSm, 256>>>(s, amask);
        // ctx = P V  (writes back to [b,s,e] layout)
        dim3 gPv(1, SS / 64, NHB);
        gemm_pv_kernel<<<gPv, 256>>>(s, v, c);
        // O projection (bias folded into LN)
        gemm_nt_kernel<<<gProj, 256>>>(c, 0, wo, 0, nullptr, t, 0,
                                       MTOK, DD, DD, 1.f, 0);
        ln768_kernel<<<MTOK, 256>>>(t, x, bo + l * DD, ag + l * DD, ab + l * DD,
                                    a, 1e-5f);
        // FFN
        dim3 gF1(FF / 64, MTOK / 64, 1);
        gemm_nt_kernel<<<gF1, 256>>>(a, 0, w1, 0, b1 + l * FF, h, 0,
                                     MTOK, FF, DD, 1.f, 0);
        gemm_nt_kernel<<<gProj, 256>>>(h, 0, w2, 0, nullptr, t, 0,
                                       MTOK, DD, FF, 1.f, 0);
        ln768_kernel<<<MTOK, 256>>>(t, nullptr, b2 + l * DD, fg + l * DD,
                                    fb + l * DD, x, 1e-5f);
    }

    cudaMemcpyAsync(d_out, x, (size_t)MTOK * DD * sizeof(float),
                    cudaMemcpyDeviceToDevice);
}

// round 7
// speedup vs baseline: 2.1783x; 2.1778x over previous
#include <cuda_runtime.h>
#include <cuda_bf16.h>
#include <stdint.h>
#include <math.h>

#define BB 8
#define SS 512
#define DD 768
#define HH 12
#define DKK 64
#define FF 3072
#define LL 12
#define MTOK (BB*SS)
#define NHB (BB*HH)
#define SCALE 0.125f

typedef __nv_bfloat16 bf16;

// ------------------------------- scratch -----------------------------------
__device__ __align__(256) float g_x[MTOK*DD];
__device__ __align__(256) float g_t[MTOK*DD];
__device__ __align__(256) float g_sc[(long)NHB*SS*SS];
__device__ __align__(256) bf16 g_xh[MTOK*DD], g_xl[MTOK*DD];
__device__ __align__(256) bf16 g_ah[MTOK*DD], g_al[MTOK*DD];
__device__ __align__(256) bf16 g_qh[MTOK*DD], g_ql[MTOK*DD];
__device__ __align__(256) bf16 g_kh[MTOK*DD], g_kl[MTOK*DD];
__device__ __align__(256) bf16 g_vth[MTOK*DD], g_vtl[MTOK*DD];   // V^T [b,h,dk,s]
__device__ __align__(256) bf16 g_ph[(long)NHB*SS*SS], g_pl[(long)NHB*SS*SS];
__device__ __align__(256) bf16 g_ch[MTOK*DD], g_cl[MTOK*DD];
__device__ __align__(256) bf16 g_hh[MTOK*FF], g_hl[MTOK*FF];
__device__ __align__(256) bf16 g_wqh[LL*DD*DD], g_wql[LL*DD*DD];
__device__ __align__(256) bf16 g_wkh[LL*DD*DD], g_wkl[LL*DD*DD];
__device__ __align__(256) bf16 g_wvh[LL*DD*DD], g_wvl[LL*DD*DD];
__device__ __align__(256) bf16 g_woh[LL*DD*DD], g_wol[LL*DD*DD];
__device__ __align__(256) bf16 g_w1h[(long)LL*FF*DD], g_w1l[(long)LL*FF*DD];
__device__ __align__(256) bf16 g_w2h[(long)LL*DD*FF], g_w2l[(long)LL*DD*FF];

// ----------------------------- helpers --------------------------------------
__device__ __forceinline__ uint32_t smem_u32(const void* p) {
    uint32_t a;
    asm("{ .reg .u64 t; cvta.to.shared.u64 t, %1; cvt.u32.u64 %0, t; }"
        : "=r"(a) : "l"(p));
    return a;
}

__device__ __forceinline__ void cpasync16(uint32_t saddr, const void* gaddr, int sz) {
    asm volatile("cp.async.ca.shared.global [%0], [%1], 16, %2;"
                 :: "r"(saddr), "l"(gaddr), "r"(sz) : "memory");
}

__device__ __forceinline__ void ldmx4(uint32_t* r, uint32_t addr) {
    asm volatile("ldmatrix.sync.aligned.m8n8.x4.shared.b16 {%0,%1,%2,%3}, [%4];"
                 : "=r"(r[0]), "=r"(r[1]), "=r"(r[2]), "=r"(r[3]) : "r"(addr));
}
__device__ __forceinline__ void ldmx2(uint32_t& r0, uint32_t& r1, uint32_t addr) {
    asm volatile("ldmatrix.sync.aligned.m8n8.x2.shared.b16 {%0,%1}, [%2];"
                 : "=r"(r0), "=r"(r1) : "r"(addr));
}

__device__ __forceinline__ void mma16816(float* c, const uint32_t* a,
                                         uint32_t b0, uint32_t b1) {
    asm volatile(
        "mma.sync.aligned.m16n8k16.row.col.f32.bf16.bf16.f32 "
        "{%0,%1,%2,%3}, {%4,%5,%6,%7}, {%8,%9}, {%0,%1,%2,%3};"
        : "+f"(c[0]), "+f"(c[1]), "+f"(c[2]), "+f"(c[3])
        : "r"(a[0]), "r"(a[1]), "r"(a[2]), "r"(a[3]), "r"(b0), "r"(b1));
}

__device__ __forceinline__ void store_hl4(bf16* __restrict__ H, bf16* __restrict__ L,
                                          long dst, const float* v) {
    union { bf16 b[4]; uint2 u; } uh, ul;
    #pragma unroll
    for (int i = 0; i < 4; i++) {
        bf16 h = __float2bfloat16_rn(v[i]);
        uh.b[i] = h;
        ul.b[i] = __float2bfloat16_rn(v[i] - __bfloat162float(h));
    }
    *(uint2*)(H + dst) = uh.u;
    *(uint2*)(L + dst) = ul.u;
}

// ------------------------------ MM kernel ------------------------------------
// C = alpha * A B^T (+bias).  A: M x K hi/lo K-major (+z*sA), B: N x K hi/lo (+z*sB).
// 3-term split: D = AhBh + AhBl + AlBh, fp32 accum (HMMA m16n8k16).
// BM=128, BN=128 (bn=min(128,N)), BK=32, cp.async double buffer.
// smem tile layout per stage: AH | AL | BH | BL, each 128 rows x pitch 40 bf16 (80B).
// mode 0: fp32 row-major*alpha   mode 1: hi/lo row-major
// mode 2: hi/lo [b,h,s,dk]       mode 3: hi/lo V^T [b,h,dk,s]   mode 4: hi/lo ctx
#define MATB 10240          // 128*80 bytes per matrix
#define STGB (4*MATB)       // 40960 per stage
#define MMSMEM 81920        // 2 stages (also covers 128x132 fp32 staging = 67584)

extern __shared__ __align__(16) char smem_[];

__global__ void __launch_bounds__(256, 2) mm_kernel(
    const bf16* __restrict__ Ah, const bf16* __restrict__ Al, long sA,
    const bf16* __restrict__ Bh, const bf16* __restrict__ Bl, long sB,
    const float* __restrict__ bias, float alpha, int M, int N, int K,
    float* __restrict__ outF, bf16* __restrict__ outH, bf16* __restrict__ outL,
    long sC, int mode)
{
    uint32_t su = smem_u32(smem_);
    int tid = threadIdx.x, wid = tid >> 5, lane = tid & 31;
    int wm = wid & 3, wn = wid >> 2;
    int z = blockIdx.z;
    Ah += (long)z * sA;  Al += (long)z * sA;
    Bh += (long)z * sB;  Bl += (long)z * sB;
    int m0 = blockIdx.y * 128, n0 = blockIdx.x * 128;
    int bn = min(128, N - n0);

    const int C = K >> 5;            // chunks of 32
    float acc[2][8][4];
    #pragma unroll
    for (int i = 0; i < 2; i++)
        #pragma unroll
        for (int j = 0; j < 8; j++)
            #pragma unroll
            for (int q = 0; q < 4; q++) acc[i][j][q] = 0.f;

    auto loadst = [&](int c, int s) {
        int k0 = c << 5;
        uint32_t sbase = su + s * STGB;
        #pragma unroll
        for (int i = 0; i < 2; i++) {
            int ch = tid + i * 256;          // 0..511
            int row = ch >> 2, c16 = ch & 3;
            uint32_t so = sbase + row * 80 + c16 * 16;
            long ka = (long)(m0 + row) * K + k0 + c16 * 8;
            cpasync16(so,             Ah + ka, 16);
            cpasync16(so + MATB,      Al + ka, 16);
            int ok = row < bn;
            long kb = ok ? ((long)(n0 + row) * K + k0 + c16 * 8) : 0;
            int sz = ok ? 16 : 0;
            cpasync16(so + 2 * MATB, Bh + kb, sz);
            cpasync16(so + 3 * MATB, Bl + kb, sz);
        }
        asm volatile("cp.async.commit_group;" ::: "memory");
    };

    auto compute = [&](int s) {
        uint32_t tb = su + s * STGB;
        #pragma unroll
        for (int kk = 0; kk < 2; kk++) {
            int kb = kk * 32;                 // 16 bf16 = 32 bytes
            uint32_t ah[2][4], al[2][4];
            #pragma unroll
            for (int mt = 0; mt < 2; mt++) {
                uint32_t ad = tb + (wm * 32 + mt * 16 + (lane & 15)) * 80
                              + kb + ((lane >> 4) * 16);
                ldmx4(ah[mt], ad);
                ldmx4(al[mt], ad + MATB);
            }
            #pragma unroll
            for (int nt = 0; nt < 8; nt++) {
                uint32_t bd = tb + 2 * MATB
                              + (wn * 64 + nt * 8 + (lane & 7)) * 80
                              + kb + (((lane >> 3) & 1) * 16);
                uint32_t bh0, bh1, bl0, bl1;
                ldmx2(bh0, bh1, bd);
                ldmx2(bl0, bl1, bd + MATB);
                #pragma unroll
                for (int mt = 0; mt < 2; mt++) {
                    mma16816(acc[mt][nt], ah[mt], bh0, bh1);
                    mma16816(acc[mt][nt], ah[mt], bl0, bl1);
                    mma16816(acc[mt][nt], al[mt], bh0, bh1);
                }
            }
        }
    };

    loadst(0, 0);
    for (int c = 0; c < C; c++) {
        if (c + 1 < C) {
            loadst(c + 1, (c + 1) & 1);
            asm volatile("cp.async.wait_group 1;" ::: "memory");
        } else {
            asm volatile("cp.async.wait_group 0;" ::: "memory");
        }
        __syncthreads();
        compute(c & 1);
        __syncthreads();
    }

    // ---- stage accumulators to SMEM fp32 [128][132] ----
    float* Cs = (float*)smem_;
    {
        int gr = lane >> 2, gc = (lane & 3) * 2;
        #pragma unroll
        for (int mt = 0; mt < 2; mt++)
            #pragma unroll
            for (int nt = 0; nt < 8; nt++) {
                int row = wm * 32 + mt * 16 + gr;
                int col = wn * 64 + nt * 8 + gc;
                Cs[row * 132 + col]           = acc[mt][nt][0];
                Cs[row * 132 + col + 1]       = acc[mt][nt][1];
                Cs[(row + 8) * 132 + col]     = acc[mt][nt][2];
                Cs[(row + 8) * 132 + col + 1] = acc[mt][nt][3];
            }
    }
    __syncthreads();

    // ---- writeout ----
    if (mode == 3) {
        int b = m0 >> 9, s0v = m0 & 511;
        for (int idx = tid; idx < bn * 32; idx += 256) {
            int n = idx >> 5, rg = (idx & 31) << 2;
            int ng = n0 + n, hh = ng >> 6, dk = ng & 63;
            float badd = bias ? bias[ng] : 0.f;
            float v[4];
            #pragma unroll
            for (int i = 0; i < 4; i++) v[i] = Cs[(rg + i) * 132 + n] + badd;
            long dst = (((long)(b * HH + hh) * DKK + dk) << 9) + s0v + rg;
            store_hl4(outH, outL, dst, v);
        }
    } else {
        int sh = (bn == 64) ? 4 : 5;
        int nv4 = bn >> 2;
        for (int idx = tid; idx < 128 * nv4; idx += 256) {
            int rr = idx >> sh;
            int c4 = (idx & (nv4 - 1)) << 2;
            float4 vv = *(const float4*)(Cs + rr * 132 + c4);
            float v[4] = {vv.x, vv.y, vv.z, vv.w};
            if (mode == 0) {
                v[0] *= alpha; v[1] *= alpha; v[2] *= alpha; v[3] *= alpha;
                *(float4*)(outF + (long)z * sC + (long)(m0 + rr) * N + n0 + c4)
                    = make_float4(v[0], v[1], v[2], v[3]);
            } else {
                if (bias) {
                    float4 bb = *(const float4*)(bias + n0 + c4);
                    v[0] += bb.x; v[1] += bb.y; v[2] += bb.z; v[3] += bb.w;
                }
                long dst;
                if (mode == 1) {
                    dst = (long)(m0 + rr) * N + n0 + c4;
                } else if (mode == 2) {
                    int mg = m0 + rr, ng = n0 + c4;
                    int b = mg >> 9, sI = mg & 511;
                    int hh = ng >> 6, dk = ng & 63;
                    dst = (((long)(b * HH + hh) * SS + sI) << 6) + dk;
                } else {
                    int b = z / HH, hh = z - b * HH;
                    dst = ((long)(b * SS + m0 + rr)) * DD + hh * DKK + n0 + c4;
                }
                store_hl4(outH, outL, dst, v);
            }
        }
    }
}

// --------------------------- elementwise kernels -----------------------------
__device__ __forceinline__ float bsum(float v, float* sh) {
    int lane = threadIdx.x & 31, w = threadIdx.x >> 5;
    #pragma unroll
    for (int o = 16; o > 0; o >>= 1) v += __shfl_xor_sync(0xffffffffu, v, o);
    if (lane == 0) sh[w] = v;
    __syncthreads();
    float r = 0.f;
    #pragma unroll
    for (int i = 0; i < 8; i++) r += sh[i];
    __syncthreads();
    return r;
}
__device__ __forceinline__ float bmax(float v, float* sh) {
    int lane = threadIdx.x & 31, w = threadIdx.x >> 5;
    #pragma unroll
    for (int o = 16; o > 0; o >>= 1) v = fmaxf(v, __shfl_xor_sync(0xffffffffu, v, o));
    if (lane == 0) sh[w] = v;
    __syncthreads();
    float r = -1e30f;
    #pragma unroll
    for (int i = 0; i < 8; i++) r = fmaxf(r, sh[i]);
    __syncthreads();
    return r;
}
__device__ __forceinline__ void wsplit(bf16* H, bf16* L, long i, float v) {
    bf16 h = __float2bfloat16_rn(v);
    H[i] = h;
    L[i] = __float2bfloat16_rn(v - __bfloat162float(h));
}

__global__ void cvt_kernel(const float* __restrict__ in, bf16* __restrict__ hi,
                           bf16* __restrict__ lo, long n) {
    long i = (long)blockIdx.x * 256 + threadIdx.x;
    long stride = (long)gridDim.x * 256;
    for (; i < n; i += stride) wsplit(hi, lo, i, in[i]);
}

__global__ void embed_ln_kernel(const int* __restrict__ ids, const int* __restrict__ tt,
                                const float* __restrict__ we, const float* __restrict__ pe,
                                const float* __restrict__ te, const float* __restrict__ gamma,
                                const float* __restrict__ beta, float* __restrict__ outF,
                                bf16* __restrict__ outH, bf16* __restrict__ outL) {
    __shared__ float sh[8];
    int m = blockIdx.x, s = m & (SS - 1);
    int id = ids[m], ty = tt[m], t = threadIdx.x;
    float v[3];
    #pragma unroll
    for (int i = 0; i < 3; i++) {
        int d = t + i * 256;
        v[i] = we[(long)id * DD + d] + te[(long)ty * DD + d] + pe[(long)s * DD + d];
    }
    float mu = bsum(v[0] + v[1] + v[2], sh) * (1.f / DD);
    float qs = 0.f;
    #pragma unroll
    for (int i = 0; i < 3; i++) { float d0 = v[i] - mu; qs += d0 * d0; }
    float rstd = rsqrtf(bsum(qs, sh) * (1.f / DD) + 1e-12f);
    #pragma unroll
    for (int i = 0; i < 3; i++) {
        int d = t + i * 256;
        float y = (v[i] - mu) * rstd * gamma[d] + beta[d];
        outF[(long)m * DD + d] = y;
        wsplit(outH, outL, (long)m * DD + d, y);
    }
}

__global__ void ln768_kernel(const float* __restrict__ in, const float* __restrict__ resid,
                             const float* __restrict__ bias, const float* __restrict__ gamma,
                             const float* __restrict__ beta, float* __restrict__ outF,
                             bf16* __restrict__ outH, bf16* __restrict__ outL, float eps) {
    __shared__ float sh[8];
    long m = blockIdx.x;
    int t = threadIdx.x;
    float v[3];
    #pragma unroll
    for (int i = 0; i < 3; i++) {
        int d = t + i * 256;
        float x = in[m * DD + d];
        if (bias) x += bias[d];
        if (resid) x += resid[m * DD + d];
        v[i] = x;
    }
    float mu = bsum(v[0] + v[1] + v[2], sh) * (1.f / DD);
    float qs = 0.f;
    #pragma unroll
    for (int i = 0; i < 3; i++) { float d0 = v[i] - mu; qs += d0 * d0; }
    float rstd = rsqrtf(bsum(qs, sh) * (1.f / DD) + eps);
    #pragma unroll
    for (int i = 0; i < 3; i++) {
        int d = t + i * 256;
        float y = (v[i] - mu) * rstd * gamma[d] + beta[d];
        if (outF) outF[m * DD + d] = y;
        wsplit(outH, outL, m * DD + d, y);
    }
}

__global__ void softmax_kernel(const float* __restrict__ scores,
                               const float* __restrict__ amask,
                               bf16* __restrict__ pH, bf16* __restrict__ pL) {
    __shared__ float sh[8];
    int z = blockIdx.y, qr = blockIdx.x, b = z / HH;
    const float* row = scores + ((long)z * SS + qr) * SS;
    long ro = ((long)z * SS + qr) * SS;
    int t = threadIdx.x;
    float v[2];
    #pragma unroll
    for (int i = 0; i < 2; i++) {
        int k = t + i * 256;
        float s = row[k];
        if (amask[b * SS + k] == 0.f) s = -1e9f;
        v[i] = s;
    }
    float mx = bmax(fmaxf(v[0], v[1]), sh);
    float e0 = __expf(v[0] - mx), e1 = __expf(v[1] - mx);
    float inv = 1.f / bsum(e0 + e1, sh);
    wsplit(pH, pL, ro + t, e0 * inv);
    wsplit(pH, pL, ro + t + 256, e1 * inv);
}

// ------------------------------- launch --------------------------------------
extern "C" void kernel_launch(void* const* d_in, const int* in_sizes, int n_in,
                              void* d_out, int out_size) {
    const int*   input_ids = (const int*)  d_in[0];
    const int*   type_ids  = (const int*)  d_in[1];
    const float* amask     = (const float*)d_in[2];
    const float* word_emb  = (const float*)d_in[3];
    const float* pos_emb   = (const float*)d_in[4];
    const float* type_emb  = (const float*)d_in[5];
    const float* emb_g     = (const float*)d_in[6];
    const float* emb_b     = (const float*)d_in[7];
    const float* Wq = (const float*)d_in[8];  const float* bq = (const float*)d_in[9];
    const float* Wk = (const float*)d_in[10]; const float* bk = (const float*)d_in[11];
    const float* Wv = (const float*)d_in[12]; const float* bv = (const float*)d_in[13];
    const float* Wo = (const float*)d_in[14]; const float* bo = (const float*)d_in[15];
    const float* ag = (const float*)d_in[16]; const float* ab = (const float*)d_in[17];
    const float* W1 = (const float*)d_in[18]; const float* b1 = (const float*)d_in[19];
    const float* W2 = (const float*)d_in[20]; const float* b2 = (const float*)d_in[21];
    const float* fg = (const float*)d_in[22]; const float* fb = (const float*)d_in[23];

    static int smem_set = 0;
    if (!smem_set) {
        cudaFuncSetAttribute(mm_kernel, cudaFuncAttributeMaxDynamicSharedMemorySize, MMSMEM);
        smem_set = 1;
    }

    float *x, *t, *sc;
    bf16 *xh, *xl, *ah, *al, *qh, *ql, *kh, *kl, *vth, *vtl, *phb, *plb, *ch, *cl, *hh, *hl;
    bf16 *wqh, *wql, *wkh, *wkl, *wvh, *wvl, *woh, *wol, *w1h, *w1l, *w2h, *w2l;
    cudaGetSymbolAddress((void**)&x, g_x);     cudaGetSymbolAddress((void**)&t, g_t);
    cudaGetSymbolAddress((void**)&sc, g_sc);
    cudaGetSymbolAddress((void**)&xh, g_xh);   cudaGetSymbolAddress((void**)&xl, g_xl);
    cudaGetSymbolAddress((void**)&ah, g_ah);   cudaGetSymbolAddress((void**)&al, g_al);
    cudaGetSymbolAddress((void**)&qh, g_qh);   cudaGetSymbolAddress((void**)&ql, g_ql);
    cudaGetSymbolAddress((void**)&kh, g_kh);   cudaGetSymbolAddress((void**)&kl, g_kl);
    cudaGetSymbolAddress((void**)&vth, g_vth); cudaGetSymbolAddress((void**)&vtl, g_vtl);
    cudaGetSymbolAddress((void**)&phb, g_ph);  cudaGetSymbolAddress((void**)&plb, g_pl);
    cudaGetSymbolAddress((void**)&ch, g_ch);   cudaGetSymbolAddress((void**)&cl, g_cl);
    cudaGetSymbolAddress((void**)&hh, g_hh);   cudaGetSymbolAddress((void**)&hl, g_hl);
    cudaGetSymbolAddress((void**)&wqh, g_wqh); cudaGetSymbolAddress((void**)&wql, g_wql);
    cudaGetSymbolAddress((void**)&wkh, g_wkh); cudaGetSymbolAddress((void**)&wkl, g_wkl);
    cudaGetSymbolAddress((void**)&wvh, g_wvh); cudaGetSymbolAddress((void**)&wvl, g_wvl);
    cudaGetSymbolAddress((void**)&woh, g_woh); cudaGetSymbolAddress((void**)&wol, g_wol);
    cudaGetSymbolAddress((void**)&w1h, g_w1h); cudaGetSymbolAddress((void**)&w1l, g_w1l);
    cudaGetSymbolAddress((void**)&w2h, g_w2h); cudaGetSymbolAddress((void**)&w2l, g_w2l);

    cvt_kernel<<<2048, 256>>>(Wq, wqh, wql, (long)LL * DD * DD);
    cvt_kernel<<<2048, 256>>>(Wk, wkh, wkl, (long)LL * DD * DD);
    cvt_kernel<<<2048, 256>>>(Wv, wvh, wvl, (long)LL * DD * DD);
    cvt_kernel<<<2048, 256>>>(Wo, woh, wol, (long)LL * DD * DD);
    cvt_kernel<<<2048, 256>>>(W1, w1h, w1l, (long)LL * FF * DD);
    cvt_kernel<<<2048, 256>>>(W2, w2h, w2l, (long)LL * DD * FF);

    embed_ln_kernel<<<MTOK, 256>>>(input_ids, type_ids, word_emb, pos_emb,
                                   type_emb, emb_g, emb_b, x, xh, xl);

    for (int l = 0; l < LL; l++) {
        long wofs = (long)l * DD * DD;
        dim3 gProj(6, 32, 1);
        mm_kernel<<<gProj, 256, MMSMEM>>>(xh, xl, 0, wqh + wofs, wql + wofs, 0,
            bq + l * DD, 1.f, MTOK, DD, DD, nullptr, qh, ql, 0, 2);
        mm_kernel<<<gProj, 256, MMSMEM>>>(xh, xl, 0, wkh + wofs, wkl + wofs, 0,
            bk + l * DD, 1.f, MTOK, DD, DD, nullptr, kh, kl, 0, 2);
        mm_kernel<<<gProj, 256, MMSMEM>>>(xh, xl, 0, wvh + wofs, wvl + wofs, 0,
            bv + l * DD, 1.f, MTOK, DD, DD, nullptr, vth, vtl, 0, 3);
        dim3 gSc(4, 4, NHB);
        mm_kernel<<<gSc, 256, MMSMEM>>>(qh, ql, (long)SS * DKK, kh, kl, (long)SS * DKK,
            nullptr, SCALE, SS, SS, DKK, sc, nullptr, nullptr, (long)SS * SS, 0);
        dim3 gSm(SS, NHB, 1);
        softmax_kernel<<<gSm, 256>>>(sc, amask, phb, plb);
        dim3 gPv(1, 4, NHB);
        mm_kernel<<<gPv, 256, MMSMEM>>>(phb, plb, (long)SS * SS, vth, vtl, (long)DKK * SS,
            nullptr, 1.f, SS, DKK, SS, nullptr, ch, cl, 0, 4);
        mm_kernel<<<gProj, 256, MMSMEM>>>(ch, cl, 0, woh + wofs, wol + wofs, 0,
            nullptr, 1.f, MTOK, DD, DD, t, nullptr, nullptr, 0, 0);
        ln768_kernel<<<MTOK, 256>>>(t, x, bo + l * DD, ag + l * DD, ab + l * DD,
                                    nullptr, ah, al, 1e-5f);
        dim3 gF1(24, 32, 1);
        mm_kernel<<<gF1, 256, MMSMEM>>>(ah, al, 0, w1h + (long)l * FF * DD,
            w1l + (long)l * FF * DD, 0, b1 + l * FF, 1.f, MTOK, FF, DD,
            nullptr, hh, hl, 0, 1);
        mm_kernel<<<gProj, 256, MMSMEM>>>(hh, hl, 0, w2h + (long)l * DD * FF,
            w2l + (long)l * DD * FF, 0, nullptr, 1.f, MTOK, DD, FF,
            t, nullptr, nullptr, 0, 0);
        ln768_kernel<<<MTOK, 256>>>(t, nullptr, b2 + l * DD, fg + l * DD,
                                    fb + l * DD, x, xh, xl, 1e-5f);
    }

    cudaMemcpyAsync(d_out, x, (size_t)MTOK * DD * sizeof(float),
                    cudaMemcpyDeviceToDevice);
}

// round 8
// speedup vs baseline: 2.5474x; 1.1695x over previous
#include <cuda_runtime.h>
#include <cuda_bf16.h>
#include <stdint.h>
#include <math.h>

#define BB 8
#define SS 512
#define DD 768
#define HH 12
#define DKK 64
#define FF 3072
#define LL 12
#define MTOK (BB*SS)
#define NHB (BB*HH)
#define SCALE 0.125f
#define NQKV 2304

typedef __nv_bfloat16 bf16;

// ------------------------------- scratch -----------------------------------
__device__ __align__(256) float g_x[MTOK*DD];
__device__ __align__(256) float g_t[MTOK*DD];
__device__ __align__(256) float g_sc[(long)NHB*SS*SS];
__device__ __align__(256) bf16 g_xh[MTOK*DD], g_xl[MTOK*DD];
__device__ __align__(256) bf16 g_ah[MTOK*DD], g_al[MTOK*DD];
__device__ __align__(256) bf16 g_qh[MTOK*DD], g_ql[MTOK*DD];
__device__ __align__(256) bf16 g_kh[MTOK*DD], g_kl[MTOK*DD];
__device__ __align__(256) bf16 g_vth[MTOK*DD], g_vtl[MTOK*DD];   // V^T [b,h,dk,s]
__device__ __align__(256) bf16 g_ph[(long)NHB*SS*SS], g_pl[(long)NHB*SS*SS];
__device__ __align__(256) bf16 g_ch[MTOK*DD], g_cl[MTOK*DD];
__device__ __align__(256) bf16 g_hh[MTOK*FF], g_hl[MTOK*FF];
// fused QKV weights [L][2304][768] + others
__device__ __align__(256) bf16 g_wqkvh[(long)LL*NQKV*DD], g_wqkvl[(long)LL*NQKV*DD];
__device__ __align__(256) bf16 g_woh[LL*DD*DD], g_wol[LL*DD*DD];
__device__ __align__(256) bf16 g_w1h[(long)LL*FF*DD], g_w1l[(long)LL*FF*DD];
__device__ __align__(256) bf16 g_w2h[(long)LL*DD*FF], g_w2l[(long)LL*DD*FF];

// ----------------------------- helpers --------------------------------------
__device__ __forceinline__ uint32_t smem_u32(const void* p) {
    uint32_t a;
    asm("{ .reg .u64 t; cvta.to.shared.u64 t, %1; cvt.u32.u64 %0, t; }"
        : "=r"(a) : "l"(p));
    return a;
}
__device__ __forceinline__ void cpasync16(uint32_t saddr, const void* gaddr) {
    asm volatile("cp.async.ca.shared.global [%0], [%1], 16;"
                 :: "r"(saddr), "l"(gaddr) : "memory");
}
__device__ __forceinline__ void ldmx4(uint32_t* r, uint32_t addr) {
    asm volatile("ldmatrix.sync.aligned.m8n8.x4.shared.b16 {%0,%1,%2,%3}, [%4];"
                 : "=r"(r[0]), "=r"(r[1]), "=r"(r[2]), "=r"(r[3]) : "r"(addr));
}
__device__ __forceinline__ void ldmx2(uint32_t& r0, uint32_t& r1, uint32_t addr) {
    asm volatile("ldmatrix.sync.aligned.m8n8.x2.shared.b16 {%0,%1}, [%2];"
                 : "=r"(r0), "=r"(r1) : "r"(addr));
}
__device__ __forceinline__ void mma16816(float* c, const uint32_t* a,
                                         uint32_t b0, uint32_t b1) {
    asm volatile(
        "mma.sync.aligned.m16n8k16.row.col.f32.bf16.bf16.f32 "
        "{%0,%1,%2,%3}, {%4,%5,%6,%7}, {%8,%9}, {%0,%1,%2,%3};"
        : "+f"(c[0]), "+f"(c[1]), "+f"(c[2]), "+f"(c[3])
        : "r"(a[0]), "r"(a[1]), "r"(a[2]), "r"(a[3]), "r"(b0), "r"(b1));
}
__device__ __forceinline__ void store_hl4(bf16* __restrict__ H, bf16* __restrict__ L,
                                          long dst, const float* v) {
    union { bf16 b[4]; uint2 u; } uh, ul;
    #pragma unroll
    for (int i = 0; i < 4; i++) {
        bf16 h = __float2bfloat16_rn(v[i]);
        uh.b[i] = h;
        ul.b[i] = __float2bfloat16_rn(v[i] - __bfloat162float(h));
    }
    *(uint2*)(H + dst) = uh.u;
    *(uint2*)(L + dst) = ul.u;
}

// ------------------------- mm_kernel (BN=128) --------------------------------
// C = alpha*A B^T (+bias). A: M x K hi/lo, B: N x K hi/lo (N%128==0, M%128==0).
// 3-term: AhBh + AhBl + AlBh, fp32 accum. BM=128 BN=128 BK=32, cp.async 2-stage.
// mode 0: fp32 row-major * alpha (z-batched via sA/sB/sC)
// mode 5: fused QKV epilogue: seg0 Q-permute, seg1 K-permute, seg2 V^T
#define MATB 10240
#define STGB (4*MATB)
#define MMSMEM 81920

extern __shared__ __align__(16) char smem_[];

__global__ void __launch_bounds__(256, 2) mm_kernel(
    const bf16* __restrict__ Ah, const bf16* __restrict__ Al, long sA,
    const bf16* __restrict__ Bh, const bf16* __restrict__ Bl, long sB,
    const float* __restrict__ bias, const float* __restrict__ bias2,
    const float* __restrict__ bias3, float alpha, int M, int N, int K,
    float* __restrict__ outF, bf16* __restrict__ o1H, bf16* __restrict__ o1L,
    bf16* __restrict__ o2H, bf16* __restrict__ o2L,
    bf16* __restrict__ o3H, bf16* __restrict__ o3L, long sC, int mode)
{
    uint32_t su = smem_u32(smem_);
    int tid = threadIdx.x, wid = tid >> 5, lane = tid & 31;
    int wm = wid & 3, wn = wid >> 2;
    int z = blockIdx.z;
    Ah += (long)z * sA;  Al += (long)z * sA;
    Bh += (long)z * sB;  Bl += (long)z * sB;
    int m0 = blockIdx.y * 128, n0 = blockIdx.x * 128;

    const int C = K >> 5;
    float acc[2][8][4];
    #pragma unroll
    for (int i = 0; i < 2; i++)
        #pragma unroll
        for (int j = 0; j < 8; j++)
            #pragma unroll
            for (int q = 0; q < 4; q++) acc[i][j][q] = 0.f;

    auto loadst = [&](int c, int s) {
        int k0 = c << 5;
        uint32_t sbase = su + s * STGB;
        #pragma unroll
        for (int i = 0; i < 2; i++) {
            int ch = tid + i * 256;
            int row = ch >> 2, c16 = ch & 3;
            uint32_t so = sbase + row * 80 + c16 * 16;
            long ka = (long)(m0 + row) * K + k0 + c16 * 8;
            long kb = (long)(n0 + row) * K + k0 + c16 * 8;
            cpasync16(so,            Ah + ka);
            cpasync16(so + MATB,     Al + ka);
            cpasync16(so + 2 * MATB, Bh + kb);
            cpasync16(so + 3 * MATB, Bl + kb);
        }
        asm volatile("cp.async.commit_group;" ::: "memory");
    };

    auto compute = [&](int s) {
        uint32_t tb = su + s * STGB;
        #pragma unroll
        for (int kk = 0; kk < 2; kk++) {
            int kb = kk * 32;
            uint32_t ah[2][4], al[2][4];
            #pragma unroll
            for (int mt = 0; mt < 2; mt++) {
                uint32_t ad = tb + (wm * 32 + mt * 16 + (lane & 15)) * 80
                              + kb + ((lane >> 4) * 16);
                ldmx4(ah[mt], ad);
                ldmx4(al[mt], ad + MATB);
            }
            #pragma unroll
            for (int nt = 0; nt < 8; nt++) {
                uint32_t bd = tb + 2 * MATB
                              + (wn * 64 + nt * 8 + (lane & 7)) * 80
                              + kb + (((lane >> 3) & 1) * 16);
                uint32_t bh0, bh1, bl0, bl1;
                ldmx2(bh0, bh1, bd);
                ldmx2(bl0, bl1, bd + MATB);
                #pragma unroll
                for (int mt = 0; mt < 2; mt++) {
                    mma16816(acc[mt][nt], ah[mt], bh0, bh1);
                    mma16816(acc[mt][nt], ah[mt], bl0, bl1);
                    mma16816(acc[mt][nt], al[mt], bh0, bh1);
                }
            }
        }
    };

    loadst(0, 0);
    for (int c = 0; c < C; c++) {
        if (c + 1 < C) {
            loadst(c + 1, (c + 1) & 1);
            asm volatile("cp.async.wait_group 1;" ::: "memory");
        } else {
            asm volatile("cp.async.wait_group 0;" ::: "memory");
        }
        __syncthreads();
        compute(c & 1);
        __syncthreads();
    }

    float* Cs = (float*)smem_;   // [128][132]
    {
        int gr = lane >> 2, gc = (lane & 3) * 2;
        #pragma unroll
        for (int mt = 0; mt < 2; mt++)
            #pragma unroll
            for (int nt = 0; nt < 8; nt++) {
                int row = wm * 32 + mt * 16 + gr;
                int col = wn * 64 + nt * 8 + gc;
                Cs[row * 132 + col]           = acc[mt][nt][0];
                Cs[row * 132 + col + 1]       = acc[mt][nt][1];
                Cs[(row + 8) * 132 + col]     = acc[mt][nt][2];
                Cs[(row + 8) * 132 + col + 1] = acc[mt][nt][3];
            }
    }
    __syncthreads();

    if (mode == 0) {
        for (int idx = tid; idx < 128 * 32; idx += 256) {
            int rr = idx >> 5, c4 = (idx & 31) << 2;
            float4 vv = *(const float4*)(Cs + rr * 132 + c4);
            vv.x *= alpha; vv.y *= alpha; vv.z *= alpha; vv.w *= alpha;
            *(float4*)(outF + (long)z * sC + (long)(m0 + rr) * N + n0 + c4) = vv;
        }
    } else {
        // fused QKV
        int seg = n0 / DD;            // 0:Q 1:K 2:V
        int nl0 = n0 - seg * DD;
        if (seg < 2) {
            const float* bb = (seg == 0) ? bias : bias2;
            bf16* H = (seg == 0) ? o1H : o2H;
            bf16* L = (seg == 0) ? o1L : o2L;
            for (int idx = tid; idx < 128 * 32; idx += 256) {
                int rr = idx >> 5, c4 = (idx & 31) << 2;
                float4 vv = *(const float4*)(Cs + rr * 132 + c4);
                float4 bbv = *(const float4*)(bb + nl0 + c4);
                float v[4] = {vv.x + bbv.x, vv.y + bbv.y, vv.z + bbv.z, vv.w + bbv.w};
                int mg = m0 + rr, b = mg >> 9, sI = mg & 511;
                int ng = nl0 + c4, hh = ng >> 6, dk = ng & 63;
                long dst = (((long)(b * HH + hh) * SS + sI) << 6) + dk;
                store_hl4(H, L, dst, v);
            }
        } else {
            int b = m0 >> 9, s0v = m0 & 511;
            for (int idx = tid; idx < 128 * 32; idx += 256) {
                int n = idx >> 5, rg = (idx & 31) << 2;
                int ng = nl0 + n, hh = ng >> 6, dk = ng & 63;
                float badd = bias3[ng];
                float v[4];
                #pragma unroll
                for (int i = 0; i < 4; i++) v[i] = Cs[(rg + i) * 132 + n] + badd;
                long dst = (((long)(b * HH + hh) * DKK + dk) << 9) + s0v + rg;
                store_hl4(o3H, o3L, dst, v);
            }
        }
    }
}

// ------------------------- mm64_kernel (BN=64) -------------------------------
// Same math, BM=128 BN=64. 8 warps, each 16x64. Always 3-term, N%64==0.
// mode 0: fp32 row-major  mode 1: hi/lo row-major (+bias)  mode 4: hi/lo ctx
#define M64A 10240     // 128*80
#define M64B 5120      // 64*80
#define STG64 30720
#define MM64SMEM 61440

__global__ void __launch_bounds__(256, 2) mm64_kernel(
    const bf16* __restrict__ Ah, const bf16* __restrict__ Al, long sA,
    const bf16* __restrict__ Bh, const bf16* __restrict__ Bl, long sB,
    const float* __restrict__ bias, int M, int N, int K,
    float* __restrict__ outF, bf16* __restrict__ outH, bf16* __restrict__ outL,
    long sC, int mode)
{
    uint32_t su = smem_u32(smem_);
    int tid = threadIdx.x, w = tid >> 5, lane = tid & 31;
    int z = blockIdx.z;
    Ah += (long)z * sA;  Al += (long)z * sA;
    Bh += (long)z * sB;  Bl += (long)z * sB;
    int m0 = blockIdx.y * 128, n0 = blockIdx.x * 64;

    const int C = K >> 5;
    float acc[8][4];
    #pragma unroll
    for (int j = 0; j < 8; j++)
        #pragma unroll
        for (int q = 0; q < 4; q++) acc[j][q] = 0.f;

    auto loadst = [&](int c, int s) {
        int k0 = c << 5;
        uint32_t sbase = su + s * STG64;
        #pragma unroll
        for (int i = 0; i < 2; i++) {
            int ch = tid + i * 256;
            int row = ch >> 2, c16 = ch & 3;
            uint32_t so = sbase + row * 80 + c16 * 16;
            long ka = (long)(m0 + row) * K + k0 + c16 * 8;
            cpasync16(so,        Ah + ka);
            cpasync16(so + M64A, Al + ka);
        }
        {
            int row = tid >> 2, c16 = tid & 3;
            uint32_t so = sbase + 2 * M64A + row * 80 + c16 * 16;
            long kb = (long)(n0 + row) * K + k0 + c16 * 8;
            cpasync16(so,        Bh + kb);
            cpasync16(so + M64B, Bl + kb);
        }
        asm volatile("cp.async.commit_group;" ::: "memory");
    };

    auto compute = [&](int s) {
        uint32_t tb = su + s * STG64;
        #pragma unroll
        for (int kk = 0; kk < 2; kk++) {
            int kb = kk * 32;
            uint32_t ah[4], al[4];
            uint32_t ad = tb + (w * 16 + (lane & 15)) * 80 + kb + ((lane >> 4) * 16);
            ldmx4(ah, ad);
            ldmx4(al, ad + M64A);
            #pragma unroll
            for (int nt = 0; nt < 8; nt++) {
                uint32_t bd = tb + 2 * M64A
                              + (nt * 8 + (lane & 7)) * 80
                              + kb + (((lane >> 3) & 1) * 16);
                uint32_t bh0, bh1, bl0, bl1;
                ldmx2(bh0, bh1, bd);
                ldmx2(bl0, bl1, bd + M64B);
                mma16816(acc[nt], ah, bh0, bh1);
                mma16816(acc[nt], ah, bl0, bl1);
                mma16816(acc[nt], al, bh0, bh1);
            }
        }
    };

    loadst(0, 0);
    for (int c = 0; c < C; c++) {
        if (c + 1 < C) {
            loadst(c + 1, (c + 1) & 1);
            asm volatile("cp.async.wait_group 1;" ::: "memory");
        } else {
            asm volatile("cp.async.wait_group 0;" ::: "memory");
        }
        __syncthreads();
        compute(c & 1);
        __syncthreads();
    }

    float* Cs = (float*)smem_;   // [128][68]
    {
        int gr = lane >> 2, gc = (lane & 3) * 2;
        #pragma unroll
        for (int nt = 0; nt < 8; nt++) {
            int row = w * 16 + gr;
            int col = nt * 8 + gc;
            Cs[row * 68 + col]           = acc[nt][0];
            Cs[row * 68 + col + 1]       = acc[nt][1];
            Cs[(row + 8) * 68 + col]     = acc[nt][2];
            Cs[(row + 8) * 68 + col + 1] = acc[nt][3];
        }
    }
    __syncthreads();

    for (int idx = tid; idx < 128 * 16; idx += 256) {
        int rr = idx >> 4, c4 = (idx & 15) << 2;
        float4 vv = *(const float4*)(Cs + rr * 68 + c4);
        float v[4] = {vv.x, vv.y, vv.z, vv.w};
        if (mode == 0) {
            *(float4*)(outF + (long)z * sC + (long)(m0 + rr) * N + n0 + c4) = vv;
        } else if (mode == 1) {
            float4 bb = *(const float4*)(bias + n0 + c4);
            v[0] += bb.x; v[1] += bb.y; v[2] += bb.z; v[3] += bb.w;
            store_hl4(outH, outL, (long)(m0 + rr) * N + n0 + c4, v);
        } else { // ctx: z = b*HH+h
            int b = z / HH, hh = z - b * HH;
            long dst = ((long)(b * SS + m0 + rr)) * DD + hh * DKK + n0 + c4;
            store_hl4(outH, outL, dst, v);
        }
    }
}

// --------------------------- elementwise kernels -----------------------------
__device__ __forceinline__ float bsum(float v, float* sh) {
    int lane = threadIdx.x & 31, w = threadIdx.x >> 5;
    #pragma unroll
    for (int o = 16; o > 0; o >>= 1) v += __shfl_xor_sync(0xffffffffu, v, o);
    if (lane == 0) sh[w] = v;
    __syncthreads();
    float r = 0.f;
    #pragma unroll
    for (int i = 0; i < 8; i++) r += sh[i];
    __syncthreads();
    return r;
}
__device__ __forceinline__ float bmax(float v, float* sh) {
    int lane = threadIdx.x & 31, w = threadIdx.x >> 5;
    #pragma unroll
    for (int o = 16; o > 0; o >>= 1) v = fmaxf(v, __shfl_xor_sync(0xffffffffu, v, o));
    if (lane == 0) sh[w] = v;
    __syncthreads();
    float r = -1e30f;
    #pragma unroll
    for (int i = 0; i < 8; i++) r = fmaxf(r, sh[i]);
    __syncthreads();
    return r;
}
__device__ __forceinline__ void wsplit(bf16* H, bf16* L, long i, float v) {
    bf16 h = __float2bfloat16_rn(v);
    H[i] = h;
    L[i] = __float2bfloat16_rn(v - __bfloat162float(h));
}

// one kernel converting/splitting ALL weights; QKV remapped into fused layout
#define S1 ((long)LL*DD*DD)
#define S2 ((long)LL*FF*DD)
__global__ void cvt_all_kernel(const float* __restrict__ Wq, const float* __restrict__ Wk,
                               const float* __restrict__ Wv, const float* __restrict__ Wo,
                               const float* __restrict__ W1, const float* __restrict__ W2,
                               bf16* __restrict__ qkvh, bf16* __restrict__ qkvl,
                               bf16* __restrict__ woh, bf16* __restrict__ wol,
                               bf16* __restrict__ w1h, bf16* __restrict__ w1l,
                               bf16* __restrict__ w2h, bf16* __restrict__ w2l) {
    const long total = 4 * S1 + 2 * S2;
    long i = (long)blockIdx.x * 256 + threadIdx.x;
    long stride = (long)gridDim.x * 256;
    for (; i < total; i += stride) {
        long j = i;
        if (j < 3 * S1) {
            int seg = (int)(j / S1);        // 0=Wq 1=Wk 2=Wv
            long r = j - (long)seg * S1;
            const float* src = (seg == 0) ? Wq : (seg == 1) ? Wk : Wv;
            long l = r / (DD * DD);
            long rem = r - l * (DD * DD);
            long n = rem / DD, k = rem - n * DD;
            long dst = (l * NQKV + seg * DD + n) * DD + k;
            wsplit(qkvh, qkvl, dst, src[r]);
        } else if (j < 4 * S1) {
            long r = j - 3 * S1;
            wsplit(woh, wol, r, Wo[r]);
        } else if (j < 4 * S1 + S2) {
            long r = j - 4 * S1;
            wsplit(w1h, w1l, r, W1[r]);
        } else {
            long r = j - 4 * S1 - S2;
            wsplit(w2h, w2l, r, W2[r]);
        }
    }
}

__global__ void embed_ln_kernel(const int* __restrict__ ids, const int* __restrict__ tt,
                                const float* __restrict__ we, const float* __restrict__ pe,
                                const float* __restrict__ te, const float* __restrict__ gamma,
                                const float* __restrict__ beta, float* __restrict__ outF,
                                bf16* __restrict__ outH, bf16* __restrict__ outL) {
    __shared__ float sh[8];
    int m = blockIdx.x, s = m & (SS - 1);
    int id = ids[m], ty = tt[m], t = threadIdx.x;
    float v[3];
    #pragma unroll
    for (int i = 0; i < 3; i++) {
        int d = t + i * 256;
        v[i] = we[(long)id * DD + d] + te[(long)ty * DD + d] + pe[(long)s * DD + d];
    }
    float mu = bsum(v[0] + v[1] + v[2], sh) * (1.f / DD);
    float qs = 0.f;
    #pragma unroll
    for (int i = 0; i < 3; i++) { float d0 = v[i] - mu; qs += d0 * d0; }
    float rstd = rsqrtf(bsum(qs, sh) * (1.f / DD) + 1e-12f);
    #pragma unroll
    for (int i = 0; i < 3; i++) {
        int d = t + i * 256;
        float y = (v[i] - mu) * rstd * gamma[d] + beta[d];
        outF[(long)m * DD + d] = y;
        wsplit(outH, outL, (long)m * DD + d, y);
    }
}

__global__ void ln768_kernel(const float* __restrict__ in, const float* __restrict__ resid,
                             const float* __restrict__ bias, const float* __restrict__ gamma,
                             const float* __restrict__ beta, float* __restrict__ outF,
                             bf16* __restrict__ outH, bf16* __restrict__ outL, float eps) {
    __shared__ float sh[8];
    long m = blockIdx.x;
    int t = threadIdx.x;
    float v[3];
    #pragma unroll
    for (int i = 0; i < 3; i++) {
        int d = t + i * 256;
        float x = in[m * DD + d];
        if (bias) x += bias[d];
        if (resid) x += resid[m * DD + d];
        v[i] = x;
    }
    float mu = bsum(v[0] + v[1] + v[2], sh) * (1.f / DD);
    float qs = 0.f;
    #pragma unroll
    for (int i = 0; i < 3; i++) { float d0 = v[i] - mu; qs += d0 * d0; }
    float rstd = rsqrtf(bsum(qs, sh) * (1.f / DD) + eps);
    #pragma unroll
    for (int i = 0; i < 3; i++) {
        int d = t + i * 256;
        float y = (v[i] - mu) * rstd * gamma[d] + beta[d];
        if (outF) outF[m * DD + d] = y;
        wsplit(outH, outL, m * DD + d, y);
    }
}

__global__ void softmax_kernel(const float* __restrict__ scores,
                               const float* __restrict__ amask,
                               bf16* __restrict__ pH, bf16* __restrict__ pL) {
    __shared__ float sh[8];
    int z = blockIdx.y, qr = blockIdx.x, b = z / HH;
    const float* row = scores + ((long)z * SS + qr) * SS;
    long ro = ((long)z * SS + qr) * SS;
    int t = threadIdx.x;
    float v[2];
    #pragma unroll
    for (int i = 0; i < 2; i++) {
        int k = t + i * 256;
        float s = row[k];
        if (amask[b * SS + k] == 0.f) s = -1e9f;
        v[i] = s;
    }
    float mx = bmax(fmaxf(v[0], v[1]), sh);
    float e0 = __expf(v[0] - mx), e1 = __expf(v[1] - mx);
    float inv = 1.f / bsum(e0 + e1, sh);
    wsplit(pH, pL, ro + t, e0 * inv);
    wsplit(pH, pL, ro + t + 256, e1 * inv);
}

// ------------------------------- launch --------------------------------------
extern "C" void kernel_launch(void* const* d_in, const int* in_sizes, int n_in,
                              void* d_out, int out_size) {
    const int*   input_ids = (const int*)  d_in[0];
    const int*   type_ids  = (const int*)  d_in[1];
    const float* amask     = (const float*)d_in[2];
    const float* word_emb  = (const float*)d_in[3];
    const float* pos_emb   = (const float*)d_in[4];
    const float* type_emb  = (const float*)d_in[5];
    const float* emb_g     = (const float*)d_in[6];
    const float* emb_b     = (const float*)d_in[7];
    const float* Wq = (const float*)d_in[8];  const float* bq = (const float*)d_in[9];
    const float* Wk = (const float*)d_in[10]; const float* bk = (const float*)d_in[11];
    const float* Wv = (const float*)d_in[12]; const float* bv = (const float*)d_in[13];
    const float* Wo = (const float*)d_in[14]; const float* bo = (const float*)d_in[15];
    const float* ag = (const float*)d_in[16]; const float* ab = (const float*)d_in[17];
    const float* W1 = (const float*)d_in[18]; const float* b1 = (const float*)d_in[19];
    const float* W2 = (const float*)d_in[20]; const float* b2 = (const float*)d_in[21];
    const float* fg = (const float*)d_in[22]; const float* fb = (const float*)d_in[23];

    static int smem_set = 0;
    if (!smem_set) {
        cudaFuncSetAttribute(mm_kernel, cudaFuncAttributeMaxDynamicSharedMemorySize, MMSMEM);
        cudaFuncSetAttribute(mm64_kernel, cudaFuncAttributeMaxDynamicSharedMemorySize, MM64SMEM);
        smem_set = 1;
    }

    float *x, *t, *sc;
    bf16 *xh, *xl, *ah, *al, *qh, *ql, *kh, *kl, *vth, *vtl, *phb, *plb, *ch, *cl, *hh, *hl;
    bf16 *qkvh, *qkvl, *woh, *wol, *w1h, *w1l, *w2h, *w2l;
    cudaGetSymbolAddress((void**)&x, g_x);     cudaGetSymbolAddress((void**)&t, g_t);
    cudaGetSymbolAddress((void**)&sc, g_sc);
    cudaGetSymbolAddress((void**)&xh, g_xh);   cudaGetSymbolAddress((void**)&xl, g_xl);
    cudaGetSymbolAddress((void**)&ah, g_ah);   cudaGetSymbolAddress((void**)&al, g_al);
    cudaGetSymbolAddress((void**)&qh, g_qh);   cudaGetSymbolAddress((void**)&ql, g_ql);
    cudaGetSymbolAddress((void**)&kh, g_kh);   cudaGetSymbolAddress((void**)&kl, g_kl);
    cudaGetSymbolAddress((void**)&vth, g_vth); cudaGetSymbolAddress((void**)&vtl, g_vtl);
    cudaGetSymbolAddress((void**)&phb, g_ph);  cudaGetSymbolAddress((void**)&plb, g_pl);
    cudaGetSymbolAddress((void**)&ch, g_ch);   cudaGetSymbolAddress((void**)&cl, g_cl);
    cudaGetSymbolAddress((void**)&hh, g_hh);   cudaGetSymbolAddress((void**)&hl, g_hl);
    cudaGetSymbolAddress((void**)&qkvh, g_wqkvh); cudaGetSymbolAddress((void**)&qkvl, g_wqkvl);
    cudaGetSymbolAddress((void**)&woh, g_woh); cudaGetSymbolAddress((void**)&wol, g_wol);
    cudaGetSymbolAddress((void**)&w1h, g_w1h); cudaGetSymbolAddress((void**)&w1l, g_w1l);
    cudaGetSymbolAddress((void**)&w2h, g_w2h); cudaGetSymbolAddress((void**)&w2l, g_w2l);

    cvt_all_kernel<<<8192, 256>>>(Wq, Wk, Wv, Wo, W1, W2,
                                  qkvh, qkvl, woh, wol, w1h, w1l, w2h, w2l);

    embed_ln_kernel<<<MTOK, 256>>>(input_ids, type_ids, word_emb, pos_emb,
                                   type_emb, emb_g, emb_b, x, xh, xl);

    for (int l = 0; l < LL; l++) {
        const bf16* qkh = qkvh + (long)l * NQKV * DD;
        const bf16* qkl = qkvl + (long)l * NQKV * DD;
        // fused QKV: N=2304, 576 CTAs
        mm_kernel<<<dim3(18, 32), 256, MMSMEM>>>(xh, xl, 0, qkh, qkl, 0,
            bq + l * DD, bk + l * DD, bv + l * DD, 1.f, MTOK, NQKV, DD,
            nullptr, qh, ql, kh, kl, vth, vtl, 0, 5);
        // scores = 0.125 * Q K^T
        mm_kernel<<<dim3(4, 4, NHB), 256, MMSMEM>>>(qh, ql, (long)SS * DKK,
            kh, kl, (long)SS * DKK, nullptr, nullptr, nullptr, SCALE,
            SS, SS, DKK, sc, nullptr, nullptr, nullptr, nullptr, nullptr, nullptr,
            (long)SS * SS, 0);
        softmax_kernel<<<dim3(SS, NHB), 256>>>(sc, amask, phb, plb);
        // ctx = P V : A=P [512x512], B=V^T [64x512]
        mm64_kernel<<<dim3(1, 4, NHB), 256, MM64SMEM>>>(phb, plb, (long)SS * SS,
            vth, vtl, (long)DKK * SS, nullptr, SS, DKK, SS,
            nullptr, ch, cl, 0, 4);
        // O projection -> fp32 t
        mm64_kernel<<<dim3(12, 32), 256, MM64SMEM>>>(ch, cl, 0,
            woh + (long)l * DD * DD, wol + (long)l * DD * DD, 0, nullptr,
            MTOK, DD, DD, t, nullptr, nullptr, 0, 0);
        ln768_kernel<<<MTOK, 256>>>(t, x, bo + l * DD, ag + l * DD, ab + l * DD,
                                    nullptr, ah, al, 1e-5f);
        // FFN1 -> hi/lo h
        mm64_kernel<<<dim3(48, 32), 256, MM64SMEM>>>(ah, al, 0,
            w1h + (long)l * FF * DD, w1l + (long)l * FF * DD, 0, b1 + l * FF,
            MTOK, FF, DD, nullptr, hh, hl, 0, 1);
        // FFN2 -> fp32 t
        mm64_kernel<<<dim3(12, 32), 256, MM64SMEM>>>(hh, hl, 0,
            w2h + (long)l * DD * FF, w2l + (long)l * DD * FF, 0, nullptr,
            MTOK, DD, FF, t, nullptr, nullptr, 0, 0);
        ln768_kernel<<<MTOK, 256>>>(t, nullptr, b2 + l * DD, fg + l * DD,
                                    fb + l * DD, x, xh, xl, 1e-5f);
    }

    cudaMemcpyAsync(d_out, x, (size_t)MTOK * DD * sizeof(float),
                    cudaMemcpyDeviceToDevice);
}

// round 9
// speedup vs baseline: 2.6704x; 1.0483x over previous
#include <cuda_runtime.h>
#include <cuda_bf16.h>
#include <stdint.h>
#include <math.h>

#define BB 8
#define SS 512
#define DD 768
#define HH 12
#define DKK 64
#define FF 3072
#define LL 12
#define MTOK (BB*SS)
#define NHB (BB*HH)
#define SCALE 0.125f
#define NQKV 2304

typedef __nv_bfloat16 bf16;

// ------------------------------- scratch -----------------------------------
__device__ __align__(256) float g_x[MTOK*DD];
__device__ __align__(256) float g_t[MTOK*DD];
__device__ __align__(256) float g_sc[(long)NHB*SS*SS];
__device__ __align__(256) bf16 g_xh[MTOK*DD], g_xl[MTOK*DD];
__device__ __align__(256) bf16 g_ah[MTOK*DD], g_al[MTOK*DD];
__device__ __align__(256) bf16 g_qh[MTOK*DD], g_ql[MTOK*DD];
__device__ __align__(256) bf16 g_kh[MTOK*DD], g_kl[MTOK*DD];
__device__ __align__(256) bf16 g_vth[MTOK*DD], g_vtl[MTOK*DD];   // V^T [b,h,dk,s]
__device__ __align__(256) bf16 g_ph[(long)NHB*SS*SS], g_pl[(long)NHB*SS*SS];
__device__ __align__(256) bf16 g_ch[MTOK*DD], g_cl[MTOK*DD];
__device__ __align__(256) bf16 g_hh[MTOK*FF], g_hl[MTOK*FF];
__device__ __align__(256) bf16 g_wqkvh[(long)LL*NQKV*DD], g_wqkvl[(long)LL*NQKV*DD];
__device__ __align__(256) bf16 g_woh[LL*DD*DD], g_wol[LL*DD*DD];
__device__ __align__(256) bf16 g_w1h[(long)LL*FF*DD], g_w1l[(long)LL*FF*DD];
__device__ __align__(256) bf16 g_w2h[(long)LL*DD*FF], g_w2l[(long)LL*DD*FF];

// ----------------------------- helpers --------------------------------------
__device__ __forceinline__ uint32_t smem_u32(const void* p) {
    uint32_t a;
    asm("{ .reg .u64 t; cvta.to.shared.u64 t, %1; cvt.u32.u64 %0, t; }"
        : "=r"(a) : "l"(p));
    return a;
}
__device__ __forceinline__ void cpasync16(uint32_t saddr, const void* gaddr) {
    asm volatile("cp.async.ca.shared.global [%0], [%1], 16;"
                 :: "r"(saddr), "l"(gaddr) : "memory");
}
__device__ __forceinline__ void ldmx4(uint32_t* r, uint32_t addr) {
    asm volatile("ldmatrix.sync.aligned.m8n8.x4.shared.b16 {%0,%1,%2,%3}, [%4];"
                 : "=r"(r[0]), "=r"(r[1]), "=r"(r[2]), "=r"(r[3]) : "r"(addr));
}
__device__ __forceinline__ void mma16816(float* c, const uint32_t* a,
                                         uint32_t b0, uint32_t b1) {
    asm volatile(
        "mma.sync.aligned.m16n8k16.row.col.f32.bf16.bf16.f32 "
        "{%0,%1,%2,%3}, {%4,%5,%6,%7}, {%8,%9}, {%0,%1,%2,%3};"
        : "+f"(c[0]), "+f"(c[1]), "+f"(c[2]), "+f"(c[3])
        : "r"(a[0]), "r"(a[1]), "r"(a[2]), "r"(a[3]), "r"(b0), "r"(b1));
}
__device__ __forceinline__ void store_hl4(bf16* __restrict__ H, bf16* __restrict__ L,
                                          long dst, const float* v) {
    union { bf16 b[4]; uint2 u; } uh, ul;
    #pragma unroll
    for (int i = 0; i < 4; i++) {
        bf16 h = __float2bfloat16_rn(v[i]);
        uh.b[i] = h;
        ul.b[i] = __float2bfloat16_rn(v[i] - __bfloat162float(h));
    }
    *(uint2*)(H + dst) = uh.u;
    *(uint2*)(L + dst) = ul.u;
}

// ------------------------- mm_kernel (BN=128) --------------------------------
// C = alpha*A B^T (+bias). 3-term: AhBh + AhBl + AlBh, fp32 accum.
// BM=128 BN=128 BK=32, cp.async 2-stage, B-fragments via paired ldmatrix.x4
// with double-buffered prefetch.
// mode 0: fp32 row-major * alpha (z-batched)
// mode 5: fused QKV epilogue (seg0 Q-perm, seg1 K-perm, seg2 V^T)
#define MATB 10240
#define STGB (4*MATB)
#define MMSMEM 81920

extern __shared__ __align__(16) char smem_[];

__global__ void __launch_bounds__(256, 2) mm_kernel(
    const bf16* __restrict__ Ah, const bf16* __restrict__ Al, long sA,
    const bf16* __restrict__ Bh, const bf16* __restrict__ Bl, long sB,
    const float* __restrict__ bias, const float* __restrict__ bias2,
    const float* __restrict__ bias3, float alpha, int M, int N, int K,
    float* __restrict__ outF, bf16* __restrict__ o1H, bf16* __restrict__ o1L,
    bf16* __restrict__ o2H, bf16* __restrict__ o2L,
    bf16* __restrict__ o3H, bf16* __restrict__ o3L, long sC, int mode)
{
    uint32_t su = smem_u32(smem_);
    int tid = threadIdx.x, wid = tid >> 5, lane = tid & 31;
    int wm = wid & 3, wn = wid >> 2;
    int z = blockIdx.z;
    Ah += (long)z * sA;  Al += (long)z * sA;
    Bh += (long)z * sB;  Bl += (long)z * sB;
    int m0 = blockIdx.y * 128, n0 = blockIdx.x * 128;

    const int C = K >> 5;
    float acc[2][8][4];
    #pragma unroll
    for (int i = 0; i < 2; i++)
        #pragma unroll
        for (int j = 0; j < 8; j++)
            #pragma unroll
            for (int q = 0; q < 4; q++) acc[i][j][q] = 0.f;

    auto loadst = [&](int c, int s) {
        int k0 = c << 5;
        uint32_t sbase = su + s * STGB;
        #pragma unroll
        for (int i = 0; i < 2; i++) {
            int ch = tid + i * 256;
            int row = ch >> 2, c16 = ch & 3;
            uint32_t so = sbase + row * 80 + c16 * 16;
            long ka = (long)(m0 + row) * K + k0 + c16 * 8;
            long kb = (long)(n0 + row) * K + k0 + c16 * 8;
            cpasync16(so,            Ah + ka);
            cpasync16(so + MATB,     Al + ka);
            cpasync16(so + 2 * MATB, Bh + kb);
            cpasync16(so + 3 * MATB, Bl + kb);
        }
        asm volatile("cp.async.commit_group;" ::: "memory");
    };

    auto compute = [&](int s) {
        uint32_t tb = su + s * STGB;
        #pragma unroll
        for (int kk = 0; kk < 2; kk++) {
            int kb = kk * 32;
            uint32_t ah[2][4], al[2][4];
            #pragma unroll
            for (int mt = 0; mt < 2; mt++) {
                uint32_t ad = tb + (wm * 32 + mt * 16 + (lane & 15)) * 80
                              + kb + ((lane >> 4) * 16);
                ldmx4(ah[mt], ad);
                ldmx4(al[mt], ad + MATB);
            }
            // B pair fragments (2 n-tiles per ldmatrix.x4), double buffered
            uint32_t bh[2][4], bl[2][4];
            uint32_t bbase = tb + 2 * MATB
                           + (wn * 64 + (lane >> 4) * 8 + (lane & 7)) * 80
                           + kb + (((lane >> 3) & 1) * 16);
            ldmx4(bh[0], bbase);
            ldmx4(bl[0], bbase + MATB);
            #pragma unroll
            for (int p = 0; p < 4; p++) {
                int cur = p & 1;
                if (p < 3) {
                    uint32_t bd = bbase + (p + 1) * 16 * 80;
                    ldmx4(bh[cur ^ 1], bd);
                    ldmx4(bl[cur ^ 1], bd + MATB);
                }
                #pragma unroll
                for (int half = 0; half < 2; half++) {
                    int nt = p * 2 + half;
                    uint32_t b0h = bh[cur][half * 2], b1h = bh[cur][half * 2 + 1];
                    uint32_t b0l = bl[cur][half * 2], b1l = bl[cur][half * 2 + 1];
                    #pragma unroll
                    for (int mt = 0; mt < 2; mt++) {
                        mma16816(acc[mt][nt], ah[mt], b0h, b1h);
                        mma16816(acc[mt][nt], ah[mt], b0l, b1l);
                        mma16816(acc[mt][nt], al[mt], b0h, b1h);
                    }
                }
            }
        }
    };

    loadst(0, 0);
    for (int c = 0; c < C; c++) {
        if (c + 1 < C) {
            loadst(c + 1, (c + 1) & 1);
            asm volatile("cp.async.wait_group 1;" ::: "memory");
        } else {
            asm volatile("cp.async.wait_group 0;" ::: "memory");
        }
        __syncthreads();
        compute(c & 1);
        __syncthreads();
    }

    float* Cs = (float*)smem_;   // [128][132]
    {
        int gr = lane >> 2, gc = (lane & 3) * 2;
        #pragma unroll
        for (int mt = 0; mt < 2; mt++)
            #pragma unroll
            for (int nt = 0; nt < 8; nt++) {
                int row = wm * 32 + mt * 16 + gr;
                int col = wn * 64 + nt * 8 + gc;
                Cs[row * 132 + col]           = acc[mt][nt][0];
                Cs[row * 132 + col + 1]       = acc[mt][nt][1];
                Cs[(row + 8) * 132 + col]     = acc[mt][nt][2];
                Cs[(row + 8) * 132 + col + 1] = acc[mt][nt][3];
            }
    }
    __syncthreads();

    if (mode == 0) {
        for (int idx = tid; idx < 128 * 32; idx += 256) {
            int rr = idx >> 5, c4 = (idx & 31) << 2;
            float4 vv = *(const float4*)(Cs + rr * 132 + c4);
            vv.x *= alpha; vv.y *= alpha; vv.z *= alpha; vv.w *= alpha;
            *(float4*)(outF + (long)z * sC + (long)(m0 + rr) * N + n0 + c4) = vv;
        }
    } else {
        int seg = n0 / DD;            // 0:Q 1:K 2:V
        int nl0 = n0 - seg * DD;
        if (seg < 2) {
            const float* bb = (seg == 0) ? bias : bias2;
            bf16* H = (seg == 0) ? o1H : o2H;
            bf16* L = (seg == 0) ? o1L : o2L;
            for (int idx = tid; idx < 128 * 32; idx += 256) {
                int rr = idx >> 5, c4 = (idx & 31) << 2;
                float4 vv = *(const float4*)(Cs + rr * 132 + c4);
                float4 bbv = *(const float4*)(bb + nl0 + c4);
                float v[4] = {vv.x + bbv.x, vv.y + bbv.y, vv.z + bbv.z, vv.w + bbv.w};
                int mg = m0 + rr, b = mg >> 9, sI = mg & 511;
                int ng = nl0 + c4, hh = ng >> 6, dk = ng & 63;
                long dst = (((long)(b * HH + hh) * SS + sI) << 6) + dk;
                store_hl4(H, L, dst, v);
            }
        } else {
            int b = m0 >> 9, s0v = m0 & 511;
            for (int idx = tid; idx < 128 * 32; idx += 256) {
                int n = idx >> 5, rg = (idx & 31) << 2;
                int ng = nl0 + n, hh = ng >> 6, dk = ng & 63;
                float badd = bias3[ng];
                float v[4];
                #pragma unroll
                for (int i = 0; i < 4; i++) v[i] = Cs[(rg + i) * 132 + n] + badd;
                long dst = (((long)(b * HH + hh) * DKK + dk) << 9) + s0v + rg;
                store_hl4(o3H, o3L, dst, v);
            }
        }
    }
}

// ------------------------- mm64_kernel (BN=64) -------------------------------
// BM=128 BN=64, 8 warps each 16x64, paired-x4 B fragments + prefetch.
// mode 0: fp32 row-major  mode 1: hi/lo row-major (+bias)  mode 4: hi/lo ctx
#define M64A 10240
#define M64B 5120
#define STG64 30720
#define MM64SMEM 61440

__global__ void __launch_bounds__(256, 2) mm64_kernel(
    const bf16* __restrict__ Ah, const bf16* __restrict__ Al, long sA,
    const bf16* __restrict__ Bh, const bf16* __restrict__ Bl, long sB,
    const float* __restrict__ bias, int M, int N, int K,
    float* __restrict__ outF, bf16* __restrict__ outH, bf16* __restrict__ outL,
    long sC, int mode)
{
    uint32_t su = smem_u32(smem_);
    int tid = threadIdx.x, w = tid >> 5, lane = tid & 31;
    int z = blockIdx.z;
    Ah += (long)z * sA;  Al += (long)z * sA;
    Bh += (long)z * sB;  Bl += (long)z * sB;
    int m0 = blockIdx.y * 128, n0 = blockIdx.x * 64;

    const int C = K >> 5;
    float acc[8][4];
    #pragma unroll
    for (int j = 0; j < 8; j++)
        #pragma unroll
        for (int q = 0; q < 4; q++) acc[j][q] = 0.f;

    auto loadst = [&](int c, int s) {
        int k0 = c << 5;
        uint32_t sbase = su + s * STG64;
        #pragma unroll
        for (int i = 0; i < 2; i++) {
            int ch = tid + i * 256;
            int row = ch >> 2, c16 = ch & 3;
            uint32_t so = sbase + row * 80 + c16 * 16;
            long ka = (long)(m0 + row) * K + k0 + c16 * 8;
            cpasync16(so,        Ah + ka);
            cpasync16(so + M64A, Al + ka);
        }
        {
            int row = tid >> 2, c16 = tid & 3;
            uint32_t so = sbase + 2 * M64A + row * 80 + c16 * 16;
            long kb = (long)(n0 + row) * K + k0 + c16 * 8;
            cpasync16(so,        Bh + kb);
            cpasync16(so + M64B, Bl + kb);
        }
        asm volatile("cp.async.commit_group;" ::: "memory");
    };

    auto compute = [&](int s) {
        uint32_t tb = su + s * STG64;
        #pragma unroll
        for (int kk = 0; kk < 2; kk++) {
            int kb = kk * 32;
            uint32_t ah[4], al[4];
            uint32_t ad = tb + (w * 16 + (lane & 15)) * 80 + kb + ((lane >> 4) * 16);
            ldmx4(ah, ad);
            ldmx4(al, ad + M64A);
            uint32_t bh[2][4], bl[2][4];
            uint32_t bbase = tb + 2 * M64A
                           + ((lane >> 4) * 8 + (lane & 7)) * 80
                           + kb + (((lane >> 3) & 1) * 16);
            ldmx4(bh[0], bbase);
            ldmx4(bl[0], bbase + M64B);
            #pragma unroll
            for (int p = 0; p < 4; p++) {
                int cur = p & 1;
                if (p < 3) {
                    uint32_t bd = bbase + (p + 1) * 16 * 80;
                    ldmx4(bh[cur ^ 1], bd);
                    ldmx4(bl[cur ^ 1], bd + M64B);
                }
                #pragma unroll
                for (int half = 0; half < 2; half++) {
                    int nt = p * 2 + half;
                    uint32_t b0h = bh[cur][half * 2], b1h = bh[cur][half * 2 + 1];
                    uint32_t b0l = bl[cur][half * 2], b1l = bl[cur][half * 2 + 1];
                    mma16816(acc[nt], ah, b0h, b1h);
                    mma16816(acc[nt], ah, b0l, b1l);
                    mma16816(acc[nt], al, b0h, b1h);
                }
            }
        }
    };

    loadst(0, 0);
    for (int c = 0; c < C; c++) {
        if (c + 1 < C) {
            loadst(c + 1, (c + 1) & 1);
            asm volatile("cp.async.wait_group 1;" ::: "memory");
        } else {
            asm volatile("cp.async.wait_group 0;" ::: "memory");
        }
        __syncthreads();
        compute(c & 1);
        __syncthreads();
    }

    float* Cs = (float*)smem_;   // [128][68]
    {
        int gr = lane >> 2, gc = (lane & 3) * 2;
        #pragma unroll
        for (int nt = 0; nt < 8; nt++) {
            int row = w * 16 + gr;
            int col = nt * 8 + gc;
            Cs[row * 68 + col]           = acc[nt][0];
            Cs[row * 68 + col + 1]       = acc[nt][1];
            Cs[(row + 8) * 68 + col]     = acc[nt][2];
            Cs[(row + 8) * 68 + col + 1] = acc[nt][3];
        }
    }
    __syncthreads();

    for (int idx = tid; idx < 128 * 16; idx += 256) {
        int rr = idx >> 4, c4 = (idx & 15) << 2;
        float4 vv = *(const float4*)(Cs + rr * 68 + c4);
        float v[4] = {vv.x, vv.y, vv.z, vv.w};
        if (mode == 0) {
            *(float4*)(outF + (long)z * sC + (long)(m0 + rr) * N + n0 + c4) = vv;
        } else if (mode == 1) {
            float4 bb = *(const float4*)(bias + n0 + c4);
            v[0] += bb.x; v[1] += bb.y; v[2] += bb.z; v[3] += bb.w;
            store_hl4(outH, outL, (long)(m0 + rr) * N + n0 + c4, v);
        } else {
            int b = z / HH, hh = z - b * HH;
            long dst = ((long)(b * SS + m0 + rr)) * DD + hh * DKK + n0 + c4;
            store_hl4(outH, outL, dst, v);
        }
    }
}

// --------------------------- elementwise kernels -----------------------------
__device__ __forceinline__ float bsum(float v, float* sh) {
    int lane = threadIdx.x & 31, w = threadIdx.x >> 5;
    #pragma unroll
    for (int o = 16; o > 0; o >>= 1) v += __shfl_xor_sync(0xffffffffu, v, o);
    if (lane == 0) sh[w] = v;
    __syncthreads();
    float r = 0.f;
    #pragma unroll
    for (int i = 0; i < 8; i++) r += sh[i];
    __syncthreads();
    return r;
}
__device__ __forceinline__ float bmax(float v, float* sh) {
    int lane = threadIdx.x & 31, w = threadIdx.x >> 5;
    #pragma unroll
    for (int o = 16; o > 0; o >>= 1) v = fmaxf(v, __shfl_xor_sync(0xffffffffu, v, o));
    if (lane == 0) sh[w] = v;
    __syncthreads();
    float r = -1e30f;
    #pragma unroll
    for (int i = 0; i < 8; i++) r = fmaxf(r, sh[i]);
    __syncthreads();
    return r;
}
__device__ __forceinline__ void wsplit(bf16* H, bf16* L, long i, float v) {
    bf16 h = __float2bfloat16_rn(v);
    H[i] = h;
    L[i] = __float2bfloat16_rn(v - __bfloat162float(h));
}

#define S1 ((long)LL*DD*DD)
#define S2 ((long)LL*FF*DD)
__global__ void cvt_all_kernel(const float* __restrict__ Wq, const float* __restrict__ Wk,
                               const float* __restrict__ Wv, const float* __restrict__ Wo,
                               const float* __restrict__ W1, const float* __restrict__ W2,
                               bf16* __restrict__ qkvh, bf16* __restrict__ qkvl,
                               bf16* __restrict__ woh, bf16* __restrict__ wol,
                               bf16* __restrict__ w1h, bf16* __restrict__ w1l,
                               bf16* __restrict__ w2h, bf16* __restrict__ w2l) {
    const long total = 4 * S1 + 2 * S2;
    long i = (long)blockIdx.x * 256 + threadIdx.x;
    long stride = (long)gridDim.x * 256;
    for (; i < total; i += stride) {
        long j = i;
        if (j < 3 * S1) {
            int seg = (int)(j / S1);
            long r = j - (long)seg * S1;
            const float* src = (seg == 0) ? Wq : (seg == 1) ? Wk : Wv;
            long l = r / (DD * DD);
            long rem = r - l * (DD * DD);
            long n = rem / DD, k = rem - n * DD;
            long dst = (l * NQKV + seg * DD + n) * DD + k;
            wsplit(qkvh, qkvl, dst, src[r]);
        } else if (j < 4 * S1) {
            long r = j - 3 * S1;
            wsplit(woh, wol, r, Wo[r]);
        } else if (j < 4 * S1 + S2) {
            long r = j - 4 * S1;
            wsplit(w1h, w1l, r, W1[r]);
        } else {
            long r = j - 4 * S1 - S2;
            wsplit(w2h, w2l, r, W2[r]);
        }
    }
}

__global__ void embed_ln_kernel(const int* __restrict__ ids, const int* __restrict__ tt,
                                const float* __restrict__ we, const float* __restrict__ pe,
                                const float* __restrict__ te, const float* __restrict__ gamma,
                                const float* __restrict__ beta, float* __restrict__ outF,
                                bf16* __restrict__ outH, bf16* __restrict__ outL) {
    __shared__ float sh[8];
    int m = blockIdx.x, s = m & (SS - 1);
    int id = ids[m], ty = tt[m], t = threadIdx.x;
    float v[3];
    #pragma unroll
    for (int i = 0; i < 3; i++) {
        int d = t + i * 256;
        v[i] = we[(long)id * DD + d] + te[(long)ty * DD + d] + pe[(long)s * DD + d];
    }
    float mu = bsum(v[0] + v[1] + v[2], sh) * (1.f / DD);
    float qs = 0.f;
    #pragma unroll
    for (int i = 0; i < 3; i++) { float d0 = v[i] - mu; qs += d0 * d0; }
    float rstd = rsqrtf(bsum(qs, sh) * (1.f / DD) + 1e-12f);
    #pragma unroll
    for (int i = 0; i < 3; i++) {
        int d = t + i * 256;
        float y = (v[i] - mu) * rstd * gamma[d] + beta[d];
        outF[(long)m * DD + d] = y;
        wsplit(outH, outL, (long)m * DD + d, y);
    }
}

__global__ void ln768_kernel(const float* __restrict__ in, const float* __restrict__ resid,
                             const float* __restrict__ bias, const float* __restrict__ gamma,
                             const float* __restrict__ beta, float* __restrict__ outF,
                             bf16* __restrict__ outH, bf16* __restrict__ outL, float eps) {
    __shared__ float sh[8];
    long m = blockIdx.x;
    int t = threadIdx.x;
    float v[3];
    #pragma unroll
    for (int i = 0; i < 3; i++) {
        int d = t + i * 256;
        float x = in[m * DD + d];
        if (bias) x += bias[d];
        if (resid) x += resid[m * DD + d];
        v[i] = x;
    }
    float mu = bsum(v[0] + v[1] + v[2], sh) * (1.f / DD);
    float qs = 0.f;
    #pragma unroll
    for (int i = 0; i < 3; i++) { float d0 = v[i] - mu; qs += d0 * d0; }
    float rstd = rsqrtf(bsum(qs, sh) * (1.f / DD) + eps);
    #pragma unroll
    for (int i = 0; i < 3; i++) {
        int d = t + i * 256;
        float y = (v[i] - mu) * rstd * gamma[d] + beta[d];
        if (outF) outF[m * DD + d] = y;
        wsplit(outH, outL, m * DD + d, y);
    }
}

__global__ void softmax_kernel(const float* __restrict__ scores,
                               const float* __restrict__ amask,
                               bf16* __restrict__ pH, bf16* __restrict__ pL) {
    __shared__ float sh[8];
    int z = blockIdx.y, qr = blockIdx.x, b = z / HH;
    const float* row = scores + ((long)z * SS + qr) * SS;
    long ro = ((long)z * SS + qr) * SS;
    int t = threadIdx.x;
    float v[2];
    #pragma unroll
    for (int i = 0; i < 2; i++) {
        int k = t + i * 256;
        float s = row[k];
        if (amask[b * SS + k] == 0.f) s = -1e9f;
        v[i] = s;
    }
    float mx = bmax(fmaxf(v[0], v[1]), sh);
    float e0 = __expf(v[0] - mx), e1 = __expf(v[1] - mx);
    float inv = 1.f / bsum(e0 + e1, sh);
    wsplit(pH, pL, ro + t, e0 * inv);
    wsplit(pH, pL, ro + t + 256, e1 * inv);
}

// ------------------------------- launch --------------------------------------
extern "C" void kernel_launch(void* const* d_in, const int* in_sizes, int n_in,
                              void* d_out, int out_size) {
    const int*   input_ids = (const int*)  d_in[0];
    const int*   type_ids  = (const int*)  d_in[1];
    const float* amask     = (const float*)d_in[2];
    const float* word_emb  = (const float*)d_in[3];
    const float* pos_emb   = (const float*)d_in[4];
    const float* type_emb  = (const float*)d_in[5];
    const float* emb_g     = (const float*)d_in[6];
    const float* emb_b     = (const float*)d_in[7];
    const float* Wq = (const float*)d_in[8];  const float* bq = (const float*)d_in[9];
    const float* Wk = (const float*)d_in[10]; const float* bk = (const float*)d_in[11];
    const float* Wv = (const float*)d_in[12]; const float* bv = (const float*)d_in[13];
    const float* Wo = (const float*)d_in[14]; const float* bo = (const float*)d_in[15];
    const float* ag = (const float*)d_in[16]; const float* ab = (const float*)d_in[17];
    const float* W1 = (const float*)d_in[18]; const float* b1 = (const float*)d_in[19];
    const float* W2 = (const float*)d_in[20]; const float* b2 = (const float*)d_in[21];
    const float* fg = (const float*)d_in[22]; const float* fb = (const float*)d_in[23];

    static int smem_set = 0;
    if (!smem_set) {
        cudaFuncSetAttribute(mm_kernel, cudaFuncAttributeMaxDynamicSharedMemorySize, MMSMEM);
        cudaFuncSetAttribute(mm64_kernel, cudaFuncAttributeMaxDynamicSharedMemorySize, MM64SMEM);
        smem_set = 1;
    }

    float *x, *t, *sc;
    bf16 *xh, *xl, *ah, *al, *qh, *ql, *kh, *kl, *vth, *vtl, *phb, *plb, *ch, *cl, *hh, *hl;
    bf16 *qkvh, *qkvl, *woh, *wol, *w1h, *w1l, *w2h, *w2l;
    cudaGetSymbolAddress((void**)&x, g_x);     cudaGetSymbolAddress((void**)&t, g_t);
    cudaGetSymbolAddress((void**)&sc, g_sc);
    cudaGetSymbolAddress((void**)&xh, g_xh);   cudaGetSymbolAddress((void**)&xl, g_xl);
    cudaGetSymbolAddress((void**)&ah, g_ah);   cudaGetSymbolAddress((void**)&al, g_al);
    cudaGetSymbolAddress((void**)&qh, g_qh);   cudaGetSymbolAddress((void**)&ql, g_ql);
    cudaGetSymbolAddress((void**)&kh, g_kh);   cudaGetSymbolAddress((void**)&kl, g_kl);
    cudaGetSymbolAddress((void**)&vth, g_vth); cudaGetSymbolAddress((void**)&vtl, g_vtl);
    cudaGetSymbolAddress((void**)&phb, g_ph);  cudaGetSymbolAddress((void**)&plb, g_pl);
    cudaGetSymbolAddress((void**)&ch, g_ch);   cudaGetSymbolAddress((void**)&cl, g_cl);
    cudaGetSymbolAddress((void**)&hh, g_hh);   cudaGetSymbolAddress((void**)&hl, g_hl);
    cudaGetSymbolAddress((void**)&qkvh, g_wqkvh); cudaGetSymbolAddress((void**)&qkvl, g_wqkvl);
    cudaGetSymbolAddress((void**)&woh, g_woh); cudaGetSymbolAddress((void**)&wol, g_wol);
    cudaGetSymbolAddress((void**)&w1h, g_w1h); cudaGetSymbolAddress((void**)&w1l, g_w1l);
    cudaGetSymbolAddress((void**)&w2h, g_w2h); cudaGetSymbolAddress((void**)&w2l, g_w2l);

    cvt_all_kernel<<<8192, 256>>>(Wq, Wk, Wv, Wo, W1, W2,
                                  qkvh, qkvl, woh, wol, w1h, w1l, w2h, w2l);

    embed_ln_kernel<<<MTOK, 256>>>(input_ids, type_ids, word_emb, pos_emb,
                                   type_emb, emb_g, emb_b, x, xh, xl);

    for (int l = 0; l < LL; l++) {
        const bf16* qkh = qkvh + (long)l * NQKV * DD;
        const bf16* qkl = qkvl + (long)l * NQKV * DD;
        mm_kernel<<<dim3(18, 32), 256, MMSMEM>>>(xh, xl, 0, qkh, qkl, 0,
            bq + l * DD, bk + l * DD, bv + l * DD, 1.f, MTOK, NQKV, DD,
            nullptr, qh, ql, kh, kl, vth, vtl, 0, 5);
        mm_kernel<<<dim3(4, 4, NHB), 256, MMSMEM>>>(qh, ql, (long)SS * DKK,
            kh, kl, (long)SS * DKK, nullptr, nullptr, nullptr, SCALE,
            SS, SS, DKK, sc, nullptr, nullptr, nullptr, nullptr, nullptr, nullptr,
            (long)SS * SS, 0);
        softmax_kernel<<<dim3(SS, NHB), 256>>>(sc, amask, phb, plb);
        mm64_kernel<<<dim3(1, 4, NHB), 256, MM64SMEM>>>(phb, plb, (long)SS * SS,
            vth, vtl, (long)DKK * SS, nullptr, SS, DKK, SS,
            nullptr, ch, cl, 0, 4);
        mm64_kernel<<<dim3(12, 32), 256, MM64SMEM>>>(ch, cl, 0,
            woh + (long)l * DD * DD, wol + (long)l * DD * DD, 0, nullptr,
            MTOK, DD, DD, t, nullptr, nullptr, 0, 0);
        ln768_kernel<<<MTOK, 256>>>(t, x, bo + l * DD, ag + l * DD, ab + l * DD,
                                    nullptr, ah, al, 1e-5f);
        mm64_kernel<<<dim3(48, 32), 256, MM64SMEM>>>(ah, al, 0,
            w1h + (long)l * FF * DD, w1l + (long)l * FF * DD, 0, b1 + l * FF,
            MTOK, FF, DD, nullptr, hh, hl, 0, 1);
        mm64_kernel<<<dim3(12, 32), 256, MM64SMEM>>>(hh, hl, 0,
            w2h + (long)l * DD * FF, w2l + (long)l * DD * FF, 0, nullptr,
            MTOK, DD, FF, t, nullptr, nullptr, 0, 0);
        ln768_kernel<<<MTOK, 256>>>(t, nullptr, b2 + l * DD, fg + l * DD,
                                    fb + l * DD, x, xh, xl, 1e-5f);
    }

    cudaMemcpyAsync(d_out, x, (size_t)MTOK * DD * sizeof(float),
                    cudaMemcpyDeviceToDevice);
}

// round 10
// speedup vs baseline: 2.7809x; 1.0414x over previous
#include <cuda_runtime.h>
#include <cuda_bf16.h>
#include <stdint.h>
#include <math.h>

#define BB 8
#define SS 512
#define DD 768
#define HH 12
#define DKK 64
#define FF 3072
#define LL 12
#define MTOK (BB*SS)
#define NHB (BB*HH)
#define SCALE 0.125f
#define NQKV 2304

typedef __nv_bfloat16 bf16;

// ------------------------------- scratch -----------------------------------
__device__ __align__(256) float g_x[MTOK*DD];
__device__ __align__(256) float g_t[MTOK*DD];
__device__ __align__(256) float g_sc[(long)NHB*SS*SS];
__device__ __align__(256) bf16 g_xh[MTOK*DD], g_xl[MTOK*DD];
__device__ __align__(256) bf16 g_ah[MTOK*DD], g_al[MTOK*DD];
__device__ __align__(256) bf16 g_qh[MTOK*DD], g_ql[MTOK*DD];
__device__ __align__(256) bf16 g_kh[MTOK*DD], g_kl[MTOK*DD];
__device__ __align__(256) bf16 g_vth[MTOK*DD], g_vtl[MTOK*DD];   // V^T [b,h,dk,s]
__device__ __align__(256) bf16 g_ph[(long)NHB*SS*SS], g_pl[(long)NHB*SS*SS];
__device__ __align__(256) bf16 g_ch[MTOK*DD], g_cl[MTOK*DD];
__device__ __align__(256) bf16 g_hh[MTOK*FF], g_hl[MTOK*FF];
__device__ __align__(256) bf16 g_wqkvh[(long)LL*NQKV*DD], g_wqkvl[(long)LL*NQKV*DD];
__device__ __align__(256) bf16 g_woh[LL*DD*DD], g_wol[LL*DD*DD];
__device__ __align__(256) bf16 g_w1h[(long)LL*FF*DD], g_w1l[(long)LL*FF*DD];
__device__ __align__(256) bf16 g_w2h[(long)LL*DD*FF], g_w2l[(long)LL*DD*FF];

// ----------------------------- helpers --------------------------------------
__device__ __forceinline__ uint32_t smem_u32(const void* p) {
    uint32_t a;
    asm("{ .reg .u64 t; cvta.to.shared.u64 t, %1; cvt.u32.u64 %0, t; }"
        : "=r"(a) : "l"(p));
    return a;
}
__device__ __forceinline__ void cpasync16(uint32_t saddr, const void* gaddr) {
    asm volatile("cp.async.ca.shared.global [%0], [%1], 16;"
                 :: "r"(saddr), "l"(gaddr) : "memory");
}
__device__ __forceinline__ void ldmx4(uint32_t* r, uint32_t addr) {
    asm volatile("ldmatrix.sync.aligned.m8n8.x4.shared.b16 {%0,%1,%2,%3}, [%4];"
                 : "=r"(r[0]), "=r"(r[1]), "=r"(r[2]), "=r"(r[3]) : "r"(addr));
}
__device__ __forceinline__ void mma16816(float* c, const uint32_t* a,
                                         uint32_t b0, uint32_t b1) {
    asm volatile(
        "mma.sync.aligned.m16n8k16.row.col.f32.bf16.bf16.f32 "
        "{%0,%1,%2,%3}, {%4,%5,%6,%7}, {%8,%9}, {%0,%1,%2,%3};"
        : "+f"(c[0]), "+f"(c[1]), "+f"(c[2]), "+f"(c[3])
        : "r"(a[0]), "r"(a[1]), "r"(a[2]), "r"(a[3]), "r"(b0), "r"(b1));
}
__device__ __forceinline__ void store_hl4(bf16* __restrict__ H, bf16* __restrict__ L,
                                          long dst, const float* v) {
    union { bf16 b[4]; uint2 u; } uh, ul;
    #pragma unroll
    for (int i = 0; i < 4; i++) {
        bf16 h = __float2bfloat16_rn(v[i]);
        uh.b[i] = h;
        ul.b[i] = __float2bfloat16_rn(v[i] - __bfloat162float(h));
    }
    *(uint2*)(H + dst) = uh.u;
    *(uint2*)(L + dst) = ul.u;
}

// ------------------------- mm_kernel (128x128, 4 warps) ----------------------
// C = alpha*A B^T (+bias). 3-term: AhBh + AhBl + AlBh, fp32 accum.
// 4 warps, warp tile 64x64 -> 1.5x FLOP per smem byte vs 32x64.
// BK=32, cp.async 2-stage. __launch_bounds__(128,2): <=256 regs, 2 CTA/SM.
// mode 0: fp32 row-major*alpha (z-batched)  mode 1: hi/lo row-major (+bias)
// mode 5: fused QKV (seg0 Q-perm, seg1 K-perm, seg2 V^T)
#define MATB 10240
#define STGB (4*MATB)
#define MMSMEM 81920

extern __shared__ __align__(16) char smem_[];

__global__ void __launch_bounds__(128, 2) mm_kernel(
    const bf16* __restrict__ Ah, const bf16* __restrict__ Al, long sA,
    const bf16* __restrict__ Bh, const bf16* __restrict__ Bl, long sB,
    const float* __restrict__ bias, const float* __restrict__ bias2,
    const float* __restrict__ bias3, float alpha, int M, int N, int K,
    float* __restrict__ outF, bf16* __restrict__ o1H, bf16* __restrict__ o1L,
    bf16* __restrict__ o2H, bf16* __restrict__ o2L,
    bf16* __restrict__ o3H, bf16* __restrict__ o3L, long sC, int mode)
{
    uint32_t su = smem_u32(smem_);
    int tid = threadIdx.x, wid = tid >> 5, lane = tid & 31;
    int wm = wid & 1, wn = wid >> 1;          // 2x2 warps of 64x64
    int z = blockIdx.z;
    Ah += (long)z * sA;  Al += (long)z * sA;
    Bh += (long)z * sB;  Bl += (long)z * sB;
    int m0 = blockIdx.y * 128, n0 = blockIdx.x * 128;

    const int C = K >> 5;
    float acc[4][8][4];
    #pragma unroll
    for (int i = 0; i < 4; i++)
        #pragma unroll
        for (int j = 0; j < 8; j++)
            #pragma unroll
            for (int q = 0; q < 4; q++) acc[i][j][q] = 0.f;

    auto loadst = [&](int c, int s) {
        int k0 = c << 5;
        uint32_t sbase = su + s * STGB;
        #pragma unroll
        for (int i = 0; i < 4; i++) {
            int ch = tid + i * 128;          // 0..511
            int row = ch >> 2, c16 = ch & 3;
            uint32_t so = sbase + row * 80 + c16 * 16;
            long ka = (long)(m0 + row) * K + k0 + c16 * 8;
            long kb = (long)(n0 + row) * K + k0 + c16 * 8;
            cpasync16(so,            Ah + ka);
            cpasync16(so + MATB,     Al + ka);
            cpasync16(so + 2 * MATB, Bh + kb);
            cpasync16(so + 3 * MATB, Bl + kb);
        }
        asm volatile("cp.async.commit_group;" ::: "memory");
    };

    auto compute = [&](int s) {
        uint32_t tb = su + s * STGB;
        #pragma unroll
        for (int kk = 0; kk < 2; kk++) {
            int kb = kk * 32;
            uint32_t ah[4][4], al[4][4];
            #pragma unroll
            for (int mt = 0; mt < 4; mt++) {
                uint32_t ad = tb + (wm * 64 + mt * 16 + (lane & 15)) * 80
                              + kb + ((lane >> 4) * 16);
                ldmx4(ah[mt], ad);
                ldmx4(al[mt], ad + MATB);
            }
            uint32_t bh[2][4], bl[2][4];
            uint32_t bbase = tb + 2 * MATB
                           + (wn * 64 + (lane >> 4) * 8 + (lane & 7)) * 80
                           + kb + (((lane >> 3) & 1) * 16);
            ldmx4(bh[0], bbase);
            ldmx4(bl[0], bbase + MATB);
            #pragma unroll
            for (int p = 0; p < 4; p++) {
                int cur = p & 1;
                if (p < 3) {
                    uint32_t bd = bbase + (p + 1) * 16 * 80;
                    ldmx4(bh[cur ^ 1], bd);
                    ldmx4(bl[cur ^ 1], bd + MATB);
                }
                #pragma unroll
                for (int half = 0; half < 2; half++) {
                    int nt = p * 2 + half;
                    uint32_t b0h = bh[cur][half * 2], b1h = bh[cur][half * 2 + 1];
                    uint32_t b0l = bl[cur][half * 2], b1l = bl[cur][half * 2 + 1];
                    #pragma unroll
                    for (int mt = 0; mt < 4; mt++) {
                        mma16816(acc[mt][nt], ah[mt], b0h, b1h);
                        mma16816(acc[mt][nt], ah[mt], b0l, b1l);
                        mma16816(acc[mt][nt], al[mt], b0h, b1h);
                    }
                }
            }
        }
    };

    loadst(0, 0);
    for (int c = 0; c < C; c++) {
        if (c + 1 < C) {
            loadst(c + 1, (c + 1) & 1);
            asm volatile("cp.async.wait_group 1;" ::: "memory");
        } else {
            asm volatile("cp.async.wait_group 0;" ::: "memory");
        }
        __syncthreads();
        compute(c & 1);
        __syncthreads();
    }

    float* Cs = (float*)smem_;   // [128][132]
    {
        int gr = lane >> 2, gc = (lane & 3) * 2;
        #pragma unroll
        for (int mt = 0; mt < 4; mt++)
            #pragma unroll
            for (int nt = 0; nt < 8; nt++) {
                int row = wm * 64 + mt * 16 + gr;
                int col = wn * 64 + nt * 8 + gc;
                Cs[row * 132 + col]           = acc[mt][nt][0];
                Cs[row * 132 + col + 1]       = acc[mt][nt][1];
                Cs[(row + 8) * 132 + col]     = acc[mt][nt][2];
                Cs[(row + 8) * 132 + col + 1] = acc[mt][nt][3];
            }
    }
    __syncthreads();

    if (mode == 0) {
        for (int idx = tid; idx < 128 * 32; idx += 128) {
            int rr = idx >> 5, c4 = (idx & 31) << 2;
            float4 vv = *(const float4*)(Cs + rr * 132 + c4);
            vv.x *= alpha; vv.y *= alpha; vv.z *= alpha; vv.w *= alpha;
            *(float4*)(outF + (long)z * sC + (long)(m0 + rr) * N + n0 + c4) = vv;
        }
    } else if (mode == 1) {
        for (int idx = tid; idx < 128 * 32; idx += 128) {
            int rr = idx >> 5, c4 = (idx & 31) << 2;
            float4 vv = *(const float4*)(Cs + rr * 132 + c4);
            float v[4] = {vv.x, vv.y, vv.z, vv.w};
            if (bias) {
                float4 bb = *(const float4*)(bias + n0 + c4);
                v[0] += bb.x; v[1] += bb.y; v[2] += bb.z; v[3] += bb.w;
            }
            store_hl4(o1H, o1L, (long)(m0 + rr) * N + n0 + c4, v);
        }
    } else {
        int seg = n0 / DD;            // 0:Q 1:K 2:V
        int nl0 = n0 - seg * DD;
        if (seg < 2) {
            const float* bb = (seg == 0) ? bias : bias2;
            bf16* H = (seg == 0) ? o1H : o2H;
            bf16* L = (seg == 0) ? o1L : o2L;
            for (int idx = tid; idx < 128 * 32; idx += 128) {
                int rr = idx >> 5, c4 = (idx & 31) << 2;
                float4 vv = *(const float4*)(Cs + rr * 132 + c4);
                float4 bbv = *(const float4*)(bb + nl0 + c4);
                float v[4] = {vv.x + bbv.x, vv.y + bbv.y, vv.z + bbv.z, vv.w + bbv.w};
                int mg = m0 + rr, b = mg >> 9, sI = mg & 511;
                int ng = nl0 + c4, hh = ng >> 6, dk = ng & 63;
                long dst = (((long)(b * HH + hh) * SS + sI) << 6) + dk;
                store_hl4(H, L, dst, v);
            }
        } else {
            int b = m0 >> 9, s0v = m0 & 511;
            for (int idx = tid; idx < 128 * 32; idx += 128) {
                int n = idx >> 5, rg = (idx & 31) << 2;
                int ng = nl0 + n, hh = ng >> 6, dk = ng & 63;
                float badd = bias3[ng];
                float v[4];
                #pragma unroll
                for (int i = 0; i < 4; i++) v[i] = Cs[(rg + i) * 132 + n] + badd;
                long dst = (((long)(b * HH + hh) * DKK + dk) << 9) + s0v + rg;
                store_hl4(o3H, o3L, dst, v);
            }
        }
    }
}

// ------------------------- mm64_kernel (PV only) -----------------------------
#define M64A 10240
#define M64B 5120
#define STG64 30720
#define MM64SMEM 61440

__global__ void __launch_bounds__(256, 2) mm64_kernel(
    const bf16* __restrict__ Ah, const bf16* __restrict__ Al, long sA,
    const bf16* __restrict__ Bh, const bf16* __restrict__ Bl, long sB,
    int M, int N, int K,
    bf16* __restrict__ outH, bf16* __restrict__ outL)
{
    uint32_t su = smem_u32(smem_);
    int tid = threadIdx.x, w = tid >> 5, lane = tid & 31;
    int z = blockIdx.z;
    Ah += (long)z * sA;  Al += (long)z * sA;
    Bh += (long)z * sB;  Bl += (long)z * sB;
    int m0 = blockIdx.y * 128, n0 = blockIdx.x * 64;

    const int C = K >> 5;
    float acc[8][4];
    #pragma unroll
    for (int j = 0; j < 8; j++)
        #pragma unroll
        for (int q = 0; q < 4; q++) acc[j][q] = 0.f;

    auto loadst = [&](int c, int s) {
        int k0 = c << 5;
        uint32_t sbase = su + s * STG64;
        #pragma unroll
        for (int i = 0; i < 2; i++) {
            int ch = tid + i * 256;
            int row = ch >> 2, c16 = ch & 3;
            uint32_t so = sbase + row * 80 + c16 * 16;
            long ka = (long)(m0 + row) * K + k0 + c16 * 8;
            cpasync16(so,        Ah + ka);
            cpasync16(so + M64A, Al + ka);
        }
        {
            int row = tid >> 2, c16 = tid & 3;
            uint32_t so = sbase + 2 * M64A + row * 80 + c16 * 16;
            long kb = (long)(n0 + row) * K + k0 + c16 * 8;
            cpasync16(so,        Bh + kb);
            cpasync16(so + M64B, Bl + kb);
        }
        asm volatile("cp.async.commit_group;" ::: "memory");
    };

    auto compute = [&](int s) {
        uint32_t tb = su + s * STG64;
        #pragma unroll
        for (int kk = 0; kk < 2; kk++) {
            int kb = kk * 32;
            uint32_t ah[4], al[4];
            uint32_t ad = tb + (w * 16 + (lane & 15)) * 80 + kb + ((lane >> 4) * 16);
            ldmx4(ah, ad);
            ldmx4(al, ad + M64A);
            uint32_t bh[2][4], bl[2][4];
            uint32_t bbase = tb + 2 * M64A
                           + ((lane >> 4) * 8 + (lane & 7)) * 80
                           + kb + (((lane >> 3) & 1) * 16);
            ldmx4(bh[0], bbase);
            ldmx4(bl[0], bbase + M64B);
            #pragma unroll
            for (int p = 0; p < 4; p++) {
                int cur = p & 1;
                if (p < 3) {
                    uint32_t bd = bbase + (p + 1) * 16 * 80;
                    ldmx4(bh[cur ^ 1], bd);
                    ldmx4(bl[cur ^ 1], bd + M64B);
                }
                #pragma unroll
                for (int half = 0; half < 2; half++) {
                    int nt = p * 2 + half;
                    uint32_t b0h = bh[cur][half * 2], b1h = bh[cur][half * 2 + 1];
                    uint32_t b0l = bl[cur][half * 2], b1l = bl[cur][half * 2 + 1];
                    mma16816(acc[nt], ah, b0h, b1h);
                    mma16816(acc[nt], ah, b0l, b1l);
                    mma16816(acc[nt], al, b0h, b1h);
                }
            }
        }
    };

    loadst(0, 0);
    for (int c = 0; c < C; c++) {
        if (c + 1 < C) {
            loadst(c + 1, (c + 1) & 1);
            asm volatile("cp.async.wait_group 1;" ::: "memory");
        } else {
            asm volatile("cp.async.wait_group 0;" ::: "memory");
        }
        __syncthreads();
        compute(c & 1);
        __syncthreads();
    }

    float* Cs = (float*)smem_;   // [128][68]
    {
        int gr = lane >> 2, gc = (lane & 3) * 2;
        #pragma unroll
        for (int nt = 0; nt < 8; nt++) {
            int row = w * 16 + gr;
            int col = nt * 8 + gc;
            Cs[row * 68 + col]           = acc[nt][0];
            Cs[row * 68 + col + 1]       = acc[nt][1];
            Cs[(row + 8) * 68 + col]     = acc[nt][2];
            Cs[(row + 8) * 68 + col + 1] = acc[nt][3];
        }
    }
    __syncthreads();

    for (int idx = tid; idx < 128 * 16; idx += 256) {
        int rr = idx >> 4, c4 = (idx & 15) << 2;
        float4 vv = *(const float4*)(Cs + rr * 68 + c4);
        float v[4] = {vv.x, vv.y, vv.z, vv.w};
        int b = z / HH, hh = z - b * HH;
        long dst = ((long)(b * SS + m0 + rr)) * DD + hh * DKK + n0 + c4;
        store_hl4(outH, outL, dst, v);
    }
}

// --------------------------- elementwise kernels -----------------------------
__device__ __forceinline__ float bsum(float v, float* sh) {
    int lane = threadIdx.x & 31, w = threadIdx.x >> 5;
    #pragma unroll
    for (int o = 16; o > 0; o >>= 1) v += __shfl_xor_sync(0xffffffffu, v, o);
    if (lane == 0) sh[w] = v;
    __syncthreads();
    float r = 0.f;
    #pragma unroll
    for (int i = 0; i < 8; i++) r += sh[i];
    __syncthreads();
    return r;
}
__device__ __forceinline__ float bmax(float v, float* sh) {
    int lane = threadIdx.x & 31, w = threadIdx.x >> 5;
    #pragma unroll
    for (int o = 16; o > 0; o >>= 1) v = fmaxf(v, __shfl_xor_sync(0xffffffffu, v, o));
    if (lane == 0) sh[w] = v;
    __syncthreads();
    float r = -1e30f;
    #pragma unroll
    for (int i = 0; i < 8; i++) r = fmaxf(r, sh[i]);
    __syncthreads();
    return r;
}
__device__ __forceinline__ void wsplit(bf16* H, bf16* L, long i, float v) {
    bf16 h = __float2bfloat16_rn(v);
    H[i] = h;
    L[i] = __float2bfloat16_rn(v - __bfloat162float(h));
}

#define S1 ((long)LL*DD*DD)
#define S2 ((long)LL*FF*DD)
__global__ void cvt_all_kernel(const float* __restrict__ Wq, const float* __restrict__ Wk,
                               const float* __restrict__ Wv, const float* __restrict__ Wo,
                               const float* __restrict__ W1, const float* __restrict__ W2,
                               bf16* __restrict__ qkvh, bf16* __restrict__ qkvl,
                               bf16* __restrict__ woh, bf16* __restrict__ wol,
                               bf16* __restrict__ w1h, bf16* __restrict__ w1l,
                               bf16* __restrict__ w2h, bf16* __restrict__ w2l) {
    const long total = 4 * S1 + 2 * S2;
    long i = (long)blockIdx.x * 256 + threadIdx.x;
    long stride = (long)gridDim.x * 256;
    for (; i < total; i += stride) {
        long j = i;
        if (j < 3 * S1) {
            int seg = (int)(j / S1);
            long r = j - (long)seg * S1;
            const float* src = (seg == 0) ? Wq : (seg == 1) ? Wk : Wv;
            long l = r / (DD * DD);
            long rem = r - l * (DD * DD);
            long n = rem / DD, k = rem - n * DD;
            long dst = (l * NQKV + seg * DD + n) * DD + k;
            wsplit(qkvh, qkvl, dst, src[r]);
        } else if (j < 4 * S1) {
            long r = j - 3 * S1;
            wsplit(woh, wol, r, Wo[r]);
        } else if (j < 4 * S1 + S2) {
            long r = j - 4 * S1;
            wsplit(w1h, w1l, r, W1[r]);
        } else {
            long r = j - 4 * S1 - S2;
            wsplit(w2h, w2l, r, W2[r]);
        }
    }
}

__global__ void embed_ln_kernel(const int* __restrict__ ids, const int* __restrict__ tt,
                                const float* __restrict__ we, const float* __restrict__ pe,
                                const float* __restrict__ te, const float* __restrict__ gamma,
                                const float* __restrict__ beta, float* __restrict__ outF,
                                bf16* __restrict__ outH, bf16* __restrict__ outL) {
    __shared__ float sh[8];
    int m = blockIdx.x, s = m & (SS - 1);
    int id = ids[m], ty = tt[m], t = threadIdx.x;
    float v[3];
    #pragma unroll
    for (int i = 0; i < 3; i++) {
        int d = t + i * 256;
        v[i] = we[(long)id * DD + d] + te[(long)ty * DD + d] + pe[(long)s * DD + d];
    }
    float mu = bsum(v[0] + v[1] + v[2], sh) * (1.f / DD);
    float qs = 0.f;
    #pragma unroll
    for (int i = 0; i < 3; i++) { float d0 = v[i] - mu; qs += d0 * d0; }
    float rstd = rsqrtf(bsum(qs, sh) * (1.f / DD) + 1e-12f);
    #pragma unroll
    for (int i = 0; i < 3; i++) {
        int d = t + i * 256;
        float y = (v[i] - mu) * rstd * gamma[d] + beta[d];
        outF[(long)m * DD + d] = y;
        wsplit(outH, outL, (long)m * DD + d, y);
    }
}

__global__ void ln768_kernel(const float* __restrict__ in, const float* __restrict__ resid,
                             const float* __restrict__ bias, const float* __restrict__ gamma,
                             const float* __restrict__ beta, float* __restrict__ outF,
                             bf16* __restrict__ outH, bf16* __restrict__ outL, float eps) {
    __shared__ float sh[8];
    long m = blockIdx.x;
    int t = threadIdx.x;
    float v[3];
    #pragma unroll
    for (int i = 0; i < 3; i++) {
        int d = t + i * 256;
        float x = in[m * DD + d];
        if (bias) x += bias[d];
        if (resid) x += resid[m * DD + d];
        v[i] = x;
    }
    float mu = bsum(v[0] + v[1] + v[2], sh) * (1.f / DD);
    float qs = 0.f;
    #pragma unroll
    for (int i = 0; i < 3; i++) { float d0 = v[i] - mu; qs += d0 * d0; }
    float rstd = rsqrtf(bsum(qs, sh) * (1.f / DD) + eps);
    #pragma unroll
    for (int i = 0; i < 3; i++) {
        int d = t + i * 256;
        float y = (v[i] - mu) * rstd * gamma[d] + beta[d];
        if (outF) outF[m * DD + d] = y;
        wsplit(outH, outL, m * DD + d, y);
    }
}

__global__ void softmax_kernel(const float* __restrict__ scores,
                               const float* __restrict__ amask,
                               bf16* __restrict__ pH, bf16* __restrict__ pL) {
    __shared__ float sh[8];
    int z = blockIdx.y, qr = blockIdx.x, b = z / HH;
    const float* row = scores + ((long)z * SS + qr) * SS;
    long ro = ((long)z * SS + qr) * SS;
    int t = threadIdx.x;
    float v[2];
    #pragma unroll
    for (int i = 0; i < 2; i++) {
        int k = t + i * 256;
        float s = row[k];
        if (amask[b * SS + k] == 0.f) s = -1e9f;
        v[i] = s;
    }
    float mx = bmax(fmaxf(v[0], v[1]), sh);
    float e0 = __expf(v[0] - mx), e1 = __expf(v[1] - mx);
    float inv = 1.f / bsum(e0 + e1, sh);
    wsplit(pH, pL, ro + t, e0 * inv);
    wsplit(pH, pL, ro + t + 256, e1 * inv);
}

// ------------------------------- launch --------------------------------------
extern "C" void kernel_launch(void* const* d_in, const int* in_sizes, int n_in,
                              void* d_out, int out_size) {
    const int*   input_ids = (const int*)  d_in[0];
    const int*   type_ids  = (const int*)  d_in[1];
    const float* amask     = (const float*)d_in[2];
    const float* word_emb  = (const float*)d_in[3];
    const float* pos_emb   = (const float*)d_in[4];
    const float* type_emb  = (const float*)d_in[5];
    const float* emb_g     = (const float*)d_in[6];
    const float* emb_b     = (const float*)d_in[7];
    const float* Wq = (const float*)d_in[8];  const float* bq = (const float*)d_in[9];
    const float* Wk = (const float*)d_in[10]; const float* bk = (const float*)d_in[11];
    const float* Wv = (const float*)d_in[12]; const float* bv = (const float*)d_in[13];
    const float* Wo = (const float*)d_in[14]; const float* bo = (const float*)d_in[15];
    const float* ag = (const float*)d_in[16]; const float* ab = (const float*)d_in[17];
    const float* W1 = (const float*)d_in[18]; const float* b1 = (const float*)d_in[19];
    const float* W2 = (const float*)d_in[20]; const float* b2 = (const float*)d_in[21];
    const float* fg = (const float*)d_in[22]; const float* fb = (const float*)d_in[23];

    static int smem_set = 0;
    if (!smem_set) {
        cudaFuncSetAttribute(mm_kernel, cudaFuncAttributeMaxDynamicSharedMemorySize, MMSMEM);
        cudaFuncSetAttribute(mm64_kernel, cudaFuncAttributeMaxDynamicSharedMemorySize, MM64SMEM);
        smem_set = 1;
    }

    float *x, *t, *sc;
    bf16 *xh, *xl, *ah, *al, *qh, *ql, *kh, *kl, *vth, *vtl, *phb, *plb, *ch, *cl, *hh, *hl;
    bf16 *qkvh, *qkvl, *woh, *wol, *w1h, *w1l, *w2h, *w2l;
    cudaGetSymbolAddress((void**)&x, g_x);     cudaGetSymbolAddress((void**)&t, g_t);
    cudaGetSymbolAddress((void**)&sc, g_sc);
    cudaGetSymbolAddress((void**)&xh, g_xh);   cudaGetSymbolAddress((void**)&xl, g_xl);
    cudaGetSymbolAddress((void**)&ah, g_ah);   cudaGetSymbolAddress((void**)&al, g_al);
    cudaGetSymbolAddress((void**)&qh, g_qh);   cudaGetSymbolAddress((void**)&ql, g_ql);
    cudaGetSymbolAddress((void**)&kh, g_kh);   cudaGetSymbolAddress((void**)&kl, g_kl);
    cudaGetSymbolAddress((void**)&vth, g_vth); cudaGetSymbolAddress((void**)&vtl, g_vtl);
    cudaGetSymbolAddress((void**)&phb, g_ph);  cudaGetSymbolAddress((void**)&plb, g_pl);
    cudaGetSymbolAddress((void**)&ch, g_ch);   cudaGetSymbolAddress((void**)&cl, g_cl);
    cudaGetSymbolAddress((void**)&hh, g_hh);   cudaGetSymbolAddress((void**)&hl, g_hl);
    cudaGetSymbolAddress((void**)&qkvh, g_wqkvh); cudaGetSymbolAddress((void**)&qkvl, g_wqkvl);
    cudaGetSymbolAddress((void**)&woh, g_woh); cudaGetSymbolAddress((void**)&wol, g_wol);
    cudaGetSymbolAddress((void**)&w1h, g_w1h); cudaGetSymbolAddress((void**)&w1l, g_w1l);
    cudaGetSymbolAddress((void**)&w2h, g_w2h); cudaGetSymbolAddress((void**)&w2l, g_w2l);

    cvt_all_kernel<<<8192, 256>>>(Wq, Wk, Wv, Wo, W1, W2,
                                  qkvh, qkvl, woh, wol, w1h, w1l, w2h, w2l);

    embed_ln_kernel<<<MTOK, 256>>>(input_ids, type_ids, word_emb, pos_emb,
                                   type_emb, emb_g, emb_b, x, xh, xl);

    for (int l = 0; l < LL; l++) {
        const bf16* qkh = qkvh + (long)l * NQKV * DD;
        const bf16* qkl = qkvl + (long)l * NQKV * DD;
        // fused QKV
        mm_kernel<<<dim3(18, 32), 128, MMSMEM>>>(xh, xl, 0, qkh, qkl, 0,
            bq + l * DD, bk + l * DD, bv + l * DD, 1.f, MTOK, NQKV, DD,
            nullptr, qh, ql, kh, kl, vth, vtl, 0, 5);
        // scores = 0.125 * Q K^T
        mm_kernel<<<dim3(4, 4, NHB), 128, MMSMEM>>>(qh, ql, (long)SS * DKK,
            kh, kl, (long)SS * DKK, nullptr, nullptr, nullptr, SCALE,
            SS, SS, DKK, sc, nullptr, nullptr, nullptr, nullptr, nullptr, nullptr,
            (long)SS * SS, 0);
        softmax_kernel<<<dim3(SS, NHB), 256>>>(sc, amask, phb, plb);
        // ctx = P V
        mm64_kernel<<<dim3(1, 4, NHB), 256, MM64SMEM>>>(phb, plb, (long)SS * SS,
            vth, vtl, (long)DKK * SS, SS, DKK, SS, ch, cl);
        // O projection -> fp32 t
        mm_kernel<<<dim3(6, 32), 128, MMSMEM>>>(ch, cl, 0,
            woh + (long)l * DD * DD, wol + (long)l * DD * DD, 0,
            nullptr, nullptr, nullptr, 1.f, MTOK, DD, DD,
            t, nullptr, nullptr, nullptr, nullptr, nullptr, nullptr, 0, 0);
        ln768_kernel<<<MTOK, 256>>>(t, x, bo + l * DD, ag + l * DD, ab + l * DD,
                                    nullptr, ah, al, 1e-5f);
        // FFN1 -> hi/lo h (+bias)
        mm_kernel<<<dim3(24, 32), 128, MMSMEM>>>(ah, al, 0,
            w1h + (long)l * FF * DD, w1l + (long)l * FF * DD, 0,
            b1 + l * FF, nullptr, nullptr, 1.f, MTOK, FF, DD,
            nullptr, hh, hl, nullptr, nullptr, nullptr, nullptr, 0, 1);
        // FFN2 -> fp32 t
        mm_kernel<<<dim3(6, 32), 128, MMSMEM>>>(hh, hl, 0,
            w2h + (long)l * DD * FF, w2l + (long)l * DD * FF, 0,
            nullptr, nullptr, nullptr, 1.f, MTOK, DD, FF,
            t, nullptr, nullptr, nullptr, nullptr, nullptr, nullptr, 0, 0);
        ln768_kernel<<<MTOK, 256>>>(t, nullptr, b2 + l * DD, fg + l * DD,
                                    fb + l * DD, x, xh, xl, 1e-5f);
    }

    cudaMemcpyAsync(d_out, x, (size_t)MTOK * DD * sizeof(float),
                    cudaMemcpyDeviceToDevice);
}

// round 12
// speedup vs baseline: 3.0919x; 1.1118x over previous
#include <cuda_runtime.h>
#include <cuda_bf16.h>
#include <stdint.h>
#include <math.h>

#define BB 8
#define SS 512
#define DD 768
#define HH 12
#define DKK 64
#define FF 3072
#define LL 12
#define MTOK (BB*SS)
#define NHB (BB*HH)
#define SCALE 0.125f
#define NQKV 2304

typedef __nv_bfloat16 bf16;

// ------------------------------- scratch -----------------------------------
__device__ __align__(256) float g_x[MTOK*DD];
__device__ __align__(256) float g_t[MTOK*DD];
__device__ __align__(256) bf16 g_xh[MTOK*DD], g_xl[MTOK*DD];
__device__ __align__(256) bf16 g_ah[MTOK*DD], g_al[MTOK*DD];
__device__ __align__(256) bf16 g_qh[MTOK*DD], g_ql[MTOK*DD];
__device__ __align__(256) bf16 g_kh[MTOK*DD], g_kl[MTOK*DD];
__device__ __align__(256) bf16 g_vth[MTOK*DD], g_vtl[MTOK*DD];   // V^T [b,h,dk,s]
__device__ __align__(256) bf16 g_ch[MTOK*DD], g_cl[MTOK*DD];
__device__ __align__(256) bf16 g_hh[MTOK*FF], g_hl[MTOK*FF];
__device__ __align__(256) bf16 g_wqkvh[(long)LL*NQKV*DD], g_wqkvl[(long)LL*NQKV*DD];
__device__ __align__(256) bf16 g_woh[LL*DD*DD], g_wol[LL*DD*DD];
__device__ __align__(256) bf16 g_w1h[(long)LL*FF*DD], g_w1l[(long)LL*FF*DD];
__device__ __align__(256) bf16 g_w2h[(long)LL*DD*FF], g_w2l[(long)LL*DD*FF];

// ----------------------------- helpers --------------------------------------
__device__ __forceinline__ uint32_t smem_u32(const void* p) {
    uint32_t a;
    asm("{ .reg .u64 t; cvta.to.shared.u64 t, %1; cvt.u32.u64 %0, t; }"
        : "=r"(a) : "l"(p));
    return a;
}
__device__ __forceinline__ void cpasync16(uint32_t saddr, const void* gaddr) {
    asm volatile("cp.async.ca.shared.global [%0], [%1], 16;"
                 :: "r"(saddr), "l"(gaddr) : "memory");
}
__device__ __forceinline__ void ldmx4(uint32_t* r, uint32_t addr) {
    asm volatile("ldmatrix.sync.aligned.m8n8.x4.shared.b16 {%0,%1,%2,%3}, [%4];"
                 : "=r"(r[0]), "=r"(r[1]), "=r"(r[2]), "=r"(r[3]) : "r"(addr));
}
__device__ __forceinline__ void mma16816(float* c, const uint32_t* a,
                                         uint32_t b0, uint32_t b1) {
    asm volatile(
        "mma.sync.aligned.m16n8k16.row.col.f32.bf16.bf16.f32 "
        "{%0,%1,%2,%3}, {%4,%5,%6,%7}, {%8,%9}, {%0,%1,%2,%3};"
        : "+f"(c[0]), "+f"(c[1]), "+f"(c[2]), "+f"(c[3])
        : "r"(a[0]), "r"(a[1]), "r"(a[2]), "r"(a[3]), "r"(b0), "r"(b1));
}
__device__ __forceinline__ void store_hl4(bf16* __restrict__ H, bf16* __restrict__ L,
                                          long dst, const float* v) {
    union { bf16 b[4]; uint2 u; } uh, ul;
    #pragma unroll
    for (int i = 0; i < 4; i++) {
        bf16 h = __float2bfloat16_rn(v[i]);
        uh.b[i] = h;
        ul.b[i] = __float2bfloat16_rn(v[i] - __bfloat162float(h));
    }
    *(uint2*)(H + dst) = uh.u;
    *(uint2*)(L + dst) = ul.u;
}
__device__ __forceinline__ uint32_t packbf2(float a, float b) {
    __nv_bfloat162 t = __floats2bfloat162_rn(a, b);   // .x=a (low), .y=b (high)
    return *(uint32_t*)&t;
}

// ------------------------- mm_kernel (128x128, 4 warps) ----------------------
#define MATB 10240
#define STGB (4*MATB)
#define MMSMEM 81920

extern __shared__ __align__(16) char smem_[];

__global__ void __launch_bounds__(128, 2) mm_kernel(
    const bf16* __restrict__ Ah, const bf16* __restrict__ Al, long sA,
    const bf16* __restrict__ Bh, const bf16* __restrict__ Bl, long sB,
    const float* __restrict__ bias, const float* __restrict__ bias2,
    const float* __restrict__ bias3, float alpha, int M, int N, int K,
    float* __restrict__ outF, bf16* __restrict__ o1H, bf16* __restrict__ o1L,
    bf16* __restrict__ o2H, bf16* __restrict__ o2L,
    bf16* __restrict__ o3H, bf16* __restrict__ o3L, long sC, int mode)
{
    uint32_t su = smem_u32(smem_);
    int tid = threadIdx.x, wid = tid >> 5, lane = tid & 31;
    int wm = wid & 1, wn = wid >> 1;
    int z = blockIdx.z;
    Ah += (long)z * sA;  Al += (long)z * sA;
    Bh += (long)z * sB;  Bl += (long)z * sB;
    int m0 = blockIdx.y * 128, n0 = blockIdx.x * 128;

    const int C = K >> 5;
    float acc[4][8][4];
    #pragma unroll
    for (int i = 0; i < 4; i++)
        #pragma unroll
        for (int j = 0; j < 8; j++)
            #pragma unroll
            for (int q = 0; q < 4; q++) acc[i][j][q] = 0.f;

    auto loadst = [&](int c, int s) {
        int k0 = c << 5;
        uint32_t sbase = su + s * STGB;
        #pragma unroll
        for (int i = 0; i < 4; i++) {
            int ch = tid + i * 128;
            int row = ch >> 2, c16 = ch & 3;
            uint32_t so = sbase + row * 80 + c16 * 16;
            long ka = (long)(m0 + row) * K + k0 + c16 * 8;
            long kb = (long)(n0 + row) * K + k0 + c16 * 8;
            cpasync16(so,            Ah + ka);
            cpasync16(so + MATB,     Al + ka);
            cpasync16(so + 2 * MATB, Bh + kb);
            cpasync16(so + 3 * MATB, Bl + kb);
        }
        asm volatile("cp.async.commit_group;" ::: "memory");
    };

    auto compute = [&](int s) {
        uint32_t tb = su + s * STGB;
        #pragma unroll
        for (int kk = 0; kk < 2; kk++) {
            int kb = kk * 32;
            uint32_t ah[4][4], al[4][4];
            #pragma unroll
            for (int mt = 0; mt < 4; mt++) {
                uint32_t ad = tb + (wm * 64 + mt * 16 + (lane & 15)) * 80
                              + kb + ((lane >> 4) * 16);
                ldmx4(ah[mt], ad);
                ldmx4(al[mt], ad + MATB);
            }
            uint32_t bh[2][4], bl[2][4];
            uint32_t bbase = tb + 2 * MATB
                           + (wn * 64 + (lane >> 4) * 8 + (lane & 7)) * 80
                           + kb + (((lane >> 3) & 1) * 16);
            ldmx4(bh[0], bbase);
            ldmx4(bl[0], bbase + MATB);
            #pragma unroll
            for (int p = 0; p < 4; p++) {
                int cur = p & 1;
                if (p < 3) {
                    uint32_t bd = bbase + (p + 1) * 16 * 80;
                    ldmx4(bh[cur ^ 1], bd);
                    ldmx4(bl[cur ^ 1], bd + MATB);
                }
                #pragma unroll
                for (int half = 0; half < 2; half++) {
                    int nt = p * 2 + half;
                    uint32_t b0h = bh[cur][half * 2], b1h = bh[cur][half * 2 + 1];
                    uint32_t b0l = bl[cur][half * 2], b1l = bl[cur][half * 2 + 1];
                    #pragma unroll
                    for (int mt = 0; mt < 4; mt++) {
                        mma16816(acc[mt][nt], ah[mt], b0h, b1h);
                        mma16816(acc[mt][nt], ah[mt], b0l, b1l);
                        mma16816(acc[mt][nt], al[mt], b0h, b1h);
                    }
                }
            }
        }
    };

    loadst(0, 0);
    for (int c = 0; c < C; c++) {
        if (c + 1 < C) {
            loadst(c + 1, (c + 1) & 1);
            asm volatile("cp.async.wait_group 1;" ::: "memory");
        } else {
            asm volatile("cp.async.wait_group 0;" ::: "memory");
        }
        __syncthreads();
        compute(c & 1);
        __syncthreads();
    }

    float* Cs = (float*)smem_;   // [128][132]
    {
        int gr = lane >> 2, gc = (lane & 3) * 2;
        #pragma unroll
        for (int mt = 0; mt < 4; mt++)
            #pragma unroll
            for (int nt = 0; nt < 8; nt++) {
                int row = wm * 64 + mt * 16 + gr;
                int col = wn * 64 + nt * 8 + gc;
                Cs[row * 132 + col]           = acc[mt][nt][0];
                Cs[row * 132 + col + 1]       = acc[mt][nt][1];
                Cs[(row + 8) * 132 + col]     = acc[mt][nt][2];
                Cs[(row + 8) * 132 + col + 1] = acc[mt][nt][3];
            }
    }
    __syncthreads();

    if (mode == 0) {
        for (int idx = tid; idx < 128 * 32; idx += 128) {
            int rr = idx >> 5, c4 = (idx & 31) << 2;
            float4 vv = *(const float4*)(Cs + rr * 132 + c4);
            vv.x *= alpha; vv.y *= alpha; vv.z *= alpha; vv.w *= alpha;
            *(float4*)(outF + (long)z * sC + (long)(m0 + rr) * N + n0 + c4) = vv;
        }
    } else if (mode == 1) {
        for (int idx = tid; idx < 128 * 32; idx += 128) {
            int rr = idx >> 5, c4 = (idx & 31) << 2;
            float4 vv = *(const float4*)(Cs + rr * 132 + c4);
            float v[4] = {vv.x, vv.y, vv.z, vv.w};
            if (bias) {
                float4 bb = *(const float4*)(bias + n0 + c4);
                v[0] += bb.x; v[1] += bb.y; v[2] += bb.z; v[3] += bb.w;
            }
            store_hl4(o1H, o1L, (long)(m0 + rr) * N + n0 + c4, v);
        }
    } else {
        int seg = n0 / DD;            // 0:Q 1:K 2:V
        int nl0 = n0 - seg * DD;
        if (seg < 2) {
            const float* bb = (seg == 0) ? bias : bias2;
            bf16* H = (seg == 0) ? o1H : o2H;
            bf16* L = (seg == 0) ? o1L : o2L;
            for (int idx = tid; idx < 128 * 32; idx += 128) {
                int rr = idx >> 5, c4 = (idx & 31) << 2;
                float4 vv = *(const float4*)(Cs + rr * 132 + c4);
                float4 bbv = *(const float4*)(bb + nl0 + c4);
                float v[4] = {vv.x + bbv.x, vv.y + bbv.y, vv.z + bbv.z, vv.w + bbv.w};
                int mg = m0 + rr, b = mg >> 9, sI = mg & 511;
                int ng = nl0 + c4, hh = ng >> 6, dk = ng & 63;
                long dst = (((long)(b * HH + hh) * SS + sI) << 6) + dk;
                store_hl4(H, L, dst, v);
            }
        } else {
            int b = m0 >> 9, s0v = m0 & 511;
            for (int idx = tid; idx < 128 * 32; idx += 128) {
                int n = idx >> 5, rg = (idx & 31) << 2;
                int ng = nl0 + n, hh = ng >> 6, dk = ng & 63;
                float badd = bias3[ng];
                float v[4];
                #pragma unroll
                for (int i = 0; i < 4; i++) v[i] = Cs[(rg + i) * 132 + n] + badd;
                long dst = (((long)(b * HH + hh) * DKK + dk) << 9) + s0v + rg;
                store_hl4(o3H, o3L, dst, v);
            }
        }
    }
}

// --------------------------- flash attention ---------------------------------
// One CTA: 128 q-rows of one (b,h). 8 warps x 16 rows. 4 k-tiles of 128 keys:
// S=QK^T (3-term), online softmax in regs, P re-packed from S accumulators,
// PV (3-term) into O accum. K/V double-buffered cp.async.
#define QPITCH 144
#define VPITCH 272
#define QS_OFF 0
#define QSB 18432
#define KS_OFF (2*QSB)
#define KSTG (2*QSB)
#define VS_OFF (KS_OFF + 2*KSTG)
#define VSB 17408
#define VSTG (2*VSB)
#define FSMEM (VS_OFF + 2*VSTG)    // 180224

__global__ void __launch_bounds__(256, 1) flash_kernel(
    const bf16* __restrict__ qh, const bf16* __restrict__ ql,
    const bf16* __restrict__ kh, const bf16* __restrict__ kl,
    const bf16* __restrict__ vth, const bf16* __restrict__ vtl,
    const float* __restrict__ amask,
    bf16* __restrict__ ch, bf16* __restrict__ cl)
{
    uint32_t su = smem_u32(smem_);
    int tid = threadIdx.x, w = tid >> 5, lane = tid & 31;
    int z = blockIdx.y;
    int b = z / HH, h = z - b * HH;
    int q0 = blockIdx.x * 128;
    const bf16* Qh = qh + (long)z * SS * DKK;
    const bf16* Ql = ql + (long)z * SS * DKK;
    const bf16* Kh = kh + (long)z * SS * DKK;
    const bf16* Kl = kl + (long)z * SS * DKK;
    const bf16* Vh = vth + (long)z * DKK * SS;
    const bf16* Vl = vtl + (long)z * DKK * SS;

    for (int i = tid; i < 1024; i += 256) {
        int r = i >> 3, c = i & 7;
        uint32_t so = su + QS_OFF + r * QPITCH + c * 16;
        long go = (long)(q0 + r) * DKK + c * 8;
        cpasync16(so,        Qh + go);
        cpasync16(so + QSB,  Ql + go);
    }
    auto loadKV = [&](int kt, int s) {
        for (int i = tid; i < 1024; i += 256) {
            int r = i >> 3, c = i & 7;
            uint32_t so = su + KS_OFF + s * KSTG + r * QPITCH + c * 16;
            long go = (long)(kt * 128 + r) * DKK + c * 8;
            cpasync16(so,        Kh + go);
            cpasync16(so + QSB,  Kl + go);
        }
        for (int i = tid; i < 1024; i += 256) {
            int r = i >> 4, c = i & 15;
            uint32_t so = su + VS_OFF + s * VSTG + r * VPITCH + c * 16;
            long go = (long)r * SS + kt * 128 + c * 8;
            cpasync16(so,        Vh + go);
            cpasync16(so + VSB,  Vl + go);
        }
        asm volatile("cp.async.commit_group;" ::: "memory");
    };
    loadKV(0, 0);

    float acc_o[8][4];
    #pragma unroll
    for (int j = 0; j < 8; j++)
        #pragma unroll
        for (int q = 0; q < 4; q++) acc_o[j][q] = 0.f;
    float rm[2] = {-INFINITY, -INFINITY};
    float rl[2] = {0.f, 0.f};
    int gr = lane >> 2, gc2 = (lane & 3) * 2;

    for (int kt = 0; kt < 4; kt++) {
        int s = kt & 1;
        asm volatile("cp.async.wait_group 0;" ::: "memory");
        __syncthreads();
        if (kt + 1 < 4) loadKV(kt + 1, s ^ 1);

        // S = Q K^T (3-term), 16 x 128 per warp
        float accs[16][4];
        #pragma unroll
        for (int j = 0; j < 16; j++)
            #pragma unroll
            for (int q = 0; q < 4; q++) accs[j][q] = 0.f;
        uint32_t kbase = su + KS_OFF + s * KSTG;
        #pragma unroll
        for (int kb = 0; kb < 4; kb++) {
            uint32_t aqh[4], aql[4];
            uint32_t ad = su + QS_OFF + (w * 16 + (lane & 15)) * QPITCH
                          + kb * 32 + ((lane >> 4) * 16);
            ldmx4(aqh, ad);
            ldmx4(aql, ad + QSB);
            #pragma unroll
            for (int pr = 0; pr < 8; pr++) {
                uint32_t bd = kbase + (pr * 16 + (lane >> 4) * 8 + (lane & 7)) * QPITCH
                              + kb * 32 + (((lane >> 3) & 1) * 16);
                uint32_t bhf[4], blf[4];
                ldmx4(bhf, bd);
                ldmx4(blf, bd + QSB);
                #pragma unroll
                for (int hf = 0; hf < 2; hf++) {
                    int nt = pr * 2 + hf;
                    mma16816(accs[nt], aqh, bhf[hf * 2], bhf[hf * 2 + 1]);
                    mma16816(accs[nt], aqh, blf[hf * 2], blf[hf * 2 + 1]);
                    mma16816(accs[nt], aql, bhf[hf * 2], bhf[hf * 2 + 1]);
                }
            }
        }

        // mask + scale + tile row max
        const float* mrow = amask + b * SS + kt * 128;
        float tmax0 = -INFINITY, tmax1 = -INFINITY;
        #pragma unroll
        for (int nt = 0; nt < 16; nt++) {
            int c0 = nt * 8 + gc2;
            float m0 = mrow[c0], m1 = mrow[c0 + 1];
            float v0 = accs[nt][0] * SCALE, v1 = accs[nt][1] * SCALE;
            float v2 = accs[nt][2] * SCALE, v3 = accs[nt][3] * SCALE;
            if (m0 == 0.f) { v0 = -1e9f; v2 = -1e9f; }
            if (m1 == 0.f) { v1 = -1e9f; v3 = -1e9f; }
            accs[nt][0] = v0; accs[nt][1] = v1; accs[nt][2] = v2; accs[nt][3] = v3;
            tmax0 = fmaxf(tmax0, fmaxf(v0, v1));
            tmax1 = fmaxf(tmax1, fmaxf(v2, v3));
        }
        tmax0 = fmaxf(tmax0, __shfl_xor_sync(0xffffffffu, tmax0, 1));
        tmax0 = fmaxf(tmax0, __shfl_xor_sync(0xffffffffu, tmax0, 2));
        tmax1 = fmaxf(tmax1, __shfl_xor_sync(0xffffffffu, tmax1, 1));
        tmax1 = fmaxf(tmax1, __shfl_xor_sync(0xffffffffu, tmax1, 2));
        float nm0 = fmaxf(rm[0], tmax0), nm1 = fmaxf(rm[1], tmax1);
        float al0 = __expf(rm[0] - nm0), al1 = __expf(rm[1] - nm1);
        rm[0] = nm0; rm[1] = nm1;
        #pragma unroll
        for (int j = 0; j < 8; j++) {
            acc_o[j][0] *= al0; acc_o[j][1] *= al0;
            acc_o[j][2] *= al1; acc_o[j][3] *= al1;
        }
        rl[0] *= al0; rl[1] *= al1;

        // exp, pack P frags, PV (3-term)
        uint32_t vbase = su + VS_OFF + s * VSTG;
        float rs0 = 0.f, rs1 = 0.f;
        #pragma unroll
        for (int kc = 0; kc < 8; kc++) {
            float p[2][4];
            #pragma unroll
            for (int hf = 0; hf < 2; hf++) {
                int nt = kc * 2 + hf;
                p[hf][0] = __expf(accs[nt][0] - nm0);
                p[hf][1] = __expf(accs[nt][1] - nm0);
                p[hf][2] = __expf(accs[nt][2] - nm1);
                p[hf][3] = __expf(accs[nt][3] - nm1);
                rs0 += p[hf][0] + p[hf][1];
                rs1 += p[hf][2] + p[hf][3];
            }
            uint32_t pah[4], pal[4];
            #pragma unroll
            for (int hf = 0; hf < 2; hf++) {
                float h0 = __bfloat162float(__float2bfloat16_rn(p[hf][0]));
                float h1 = __bfloat162float(__float2bfloat16_rn(p[hf][1]));
                float h2 = __bfloat162float(__float2bfloat16_rn(p[hf][2]));
                float h3 = __bfloat162float(__float2bfloat16_rn(p[hf][3]));
                pah[hf * 2]     = packbf2(h0, h1);
                pah[hf * 2 + 1] = packbf2(h2, h3);
                pal[hf * 2]     = packbf2(p[hf][0] - h0, p[hf][1] - h1);
                pal[hf * 2 + 1] = packbf2(p[hf][2] - h2, p[hf][3] - h3);
            }
            #pragma unroll
            for (int vp = 0; vp < 4; vp++) {
                uint32_t bd = vbase + (vp * 16 + (lane >> 4) * 8 + (lane & 7)) * VPITCH
                              + kc * 32 + (((lane >> 3) & 1) * 16);
                uint32_t vhf[4], vlf[4];
                ldmx4(vhf, bd);
                ldmx4(vlf, bd + VSB);
                #pragma unroll
                for (int hf = 0; hf < 2; hf++) {
                    int no = vp * 2 + hf;
                    mma16816(acc_o[no], pah, vhf[hf * 2], vhf[hf * 2 + 1]);
                    mma16816(acc_o[no], pah, vlf[hf * 2], vlf[hf * 2 + 1]);
                    mma16816(acc_o[no], pal, vhf[hf * 2], vhf[hf * 2 + 1]);
                }
            }
        }
        rl[0] += rs0;
        rl[1] += rs1;
    }
    // FIX (R11): reduce row sums across the 4-thread quad — each thread only
    // accumulated exp-sums for its own 2-column slices of each n-tile.
    rl[0] += __shfl_xor_sync(0xffffffffu, rl[0], 1);
    rl[0] += __shfl_xor_sync(0xffffffffu, rl[0], 2);
    rl[1] += __shfl_xor_sync(0xffffffffu, rl[1], 1);
    rl[1] += __shfl_xor_sync(0xffffffffu, rl[1], 2);
    __syncthreads();

    // stage O (divide by row sum) + write hi/lo
    float* Cs = (float*)(smem_ + KS_OFF);     // [128][68]
    {
        float inv0 = 1.f / rl[0], inv1 = 1.f / rl[1];
        int r0 = w * 16 + gr;
        #pragma unroll
        for (int no = 0; no < 8; no++) {
            int col = no * 8 + gc2;
            Cs[r0 * 68 + col]           = acc_o[no][0] * inv0;
            Cs[r0 * 68 + col + 1]       = acc_o[no][1] * inv0;
            Cs[(r0 + 8) * 68 + col]     = acc_o[no][2] * inv1;
            Cs[(r0 + 8) * 68 + col + 1] = acc_o[no][3] * inv1;
        }
    }
    __syncthreads();
    for (int idx = tid; idx < 128 * 16; idx += 256) {
        int r = idx >> 4, c4 = (idx & 15) << 2;
        float4 vv = *(const float4*)(Cs + r * 68 + c4);
        float v[4] = {vv.x, vv.y, vv.z, vv.w};
        long dst = ((long)(b * SS + q0 + r)) * DD + h * DKK + c4;
        store_hl4(ch, cl, dst, v);
    }
}

// --------------------------- elementwise kernels -----------------------------
__device__ __forceinline__ float bsum(float v, float* sh) {
    int lane = threadIdx.x & 31, w = threadIdx.x >> 5;
    #pragma unroll
    for (int o = 16; o > 0; o >>= 1) v += __shfl_xor_sync(0xffffffffu, v, o);
    if (lane == 0) sh[w] = v;
    __syncthreads();
    float r = 0.f;
    #pragma unroll
    for (int i = 0; i < 8; i++) r += sh[i];
    __syncthreads();
    return r;
}
__device__ __forceinline__ void wsplit(bf16* H, bf16* L, long i, float v) {
    bf16 h = __float2bfloat16_rn(v);
    H[i] = h;
    L[i] = __float2bfloat16_rn(v - __bfloat162float(h));
}

#define S1 ((long)LL*DD*DD)
#define S2 ((long)LL*FF*DD)
__global__ void cvt_all_kernel(const float* __restrict__ Wq, const float* __restrict__ Wk,
                               const float* __restrict__ Wv, const float* __restrict__ Wo,
                               const float* __restrict__ W1, const float* __restrict__ W2,
                               bf16* __restrict__ qkvh, bf16* __restrict__ qkvl,
                               bf16* __restrict__ woh, bf16* __restrict__ wol,
                               bf16* __restrict__ w1h, bf16* __restrict__ w1l,
                               bf16* __restrict__ w2h, bf16* __restrict__ w2l) {
    const long total = 4 * S1 + 2 * S2;
    long i = (long)blockIdx.x * 256 + threadIdx.x;
    long stride = (long)gridDim.x * 256;
    for (; i < total; i += stride) {
        long j = i;
        if (j < 3 * S1) {
            int seg = (int)(j / S1);
            long r = j - (long)seg * S1;
            const float* src = (seg == 0) ? Wq : (seg == 1) ? Wk : Wv;
            long l = r / (DD * DD);
            long rem = r - l * (DD * DD);
            long n = rem / DD, k = rem - n * DD;
            long dst = (l * NQKV + seg * DD + n) * DD + k;
            wsplit(qkvh, qkvl, dst, src[r]);
        } else if (j < 4 * S1) {
            long r = j - 3 * S1;
            wsplit(woh, wol, r, Wo[r]);
        } else if (j < 4 * S1 + S2) {
            long r = j - 4 * S1;
            wsplit(w1h, w1l, r, W1[r]);
        } else {
            long r = j - 4 * S1 - S2;
            wsplit(w2h, w2l, r, W2[r]);
        }
    }
}

__global__ void embed_ln_kernel(const int* __restrict__ ids, const int* __restrict__ tt,
                                const float* __restrict__ we, const float* __restrict__ pe,
                                const float* __restrict__ te, const float* __restrict__ gamma,
                                const float* __restrict__ beta, float* __restrict__ outF,
                                bf16* __restrict__ outH, bf16* __restrict__ outL) {
    __shared__ float sh[8];
    int m = blockIdx.x, s = m & (SS - 1);
    int id = ids[m], ty = tt[m], t = threadIdx.x;
    float v[3];
    #pragma unroll
    for (int i = 0; i < 3; i++) {
        int d = t + i * 256;
        v[i] = we[(long)id * DD + d] + te[(long)ty * DD + d] + pe[(long)s * DD + d];
    }
    float mu = bsum(v[0] + v[1] + v[2], sh) * (1.f / DD);
    float qs = 0.f;
    #pragma unroll
    for (int i = 0; i < 3; i++) { float d0 = v[i] - mu; qs += d0 * d0; }
    float rstd = rsqrtf(bsum(qs, sh) * (1.f / DD) + 1e-12f);
    #pragma unroll
    for (int i = 0; i < 3; i++) {
        int d = t + i * 256;
        float y = (v[i] - mu) * rstd * gamma[d] + beta[d];
        outF[(long)m * DD + d] = y;
        wsplit(outH, outL, (long)m * DD + d, y);
    }
}

__global__ void ln768_kernel(const float* __restrict__ in, const float* __restrict__ resid,
                             const float* __restrict__ bias, const float* __restrict__ gamma,
                             const float* __restrict__ beta, float* __restrict__ outF,
                             bf16* __restrict__ outH, bf16* __restrict__ outL, float eps) {
    __shared__ float sh[8];
    long m = blockIdx.x;
    int t = threadIdx.x;
    float v[3];
    #pragma unroll
    for (int i = 0; i < 3; i++) {
        int d = t + i * 256;
        float x = in[m * DD + d];
        if (bias) x += bias[d];
        if (resid) x += resid[m * DD + d];
        v[i] = x;
    }
    float mu = bsum(v[0] + v[1] + v[2], sh) * (1.f / DD);
    float qs = 0.f;
    #pragma unroll
    for (int i = 0; i < 3; i++) { float d0 = v[i] - mu; qs += d0 * d0; }
    float rstd = rsqrtf(bsum(qs, sh) * (1.f / DD) + eps);
    #pragma unroll
    for (int i = 0; i < 3; i++) {
        int d = t + i * 256;
        float y = (v[i] - mu) * rstd * gamma[d] + beta[d];
        if (outF) outF[m * DD + d] = y;
        wsplit(outH, outL, m * DD + d, y);
    }
}

// ------------------------------- launch --------------------------------------
extern "C" void kernel_launch(void* const* d_in, const int* in_sizes, int n_in,
                              void* d_out, int out_size) {
    const int*   input_ids = (const int*)  d_in[0];
    const int*   type_ids  = (const int*)  d_in[1];
    const float* amask     = (const float*)d_in[2];
    const float* word_emb  = (const float*)d_in[3];
    const float* pos_emb   = (const float*)d_in[4];
    const float* type_emb  = (const float*)d_in[5];
    const float* emb_g     = (const float*)d_in[6];
    const float* emb_b     = (const float*)d_in[7];
    const float* Wq = (const float*)d_in[8];  const float* bq = (const float*)d_in[9];
    const float* Wk = (const float*)d_in[10]; const float* bk = (const float*)d_in[11];
    const float* Wv = (const float*)d_in[12]; const float* bv = (const float*)d_in[13];
    const float* Wo = (const float*)d_in[14]; const float* bo = (const float*)d_in[15];
    const float* ag = (const float*)d_in[16]; const float* ab = (const float*)d_in[17];
    const float* W1 = (const float*)d_in[18]; const float* b1 = (const float*)d_in[19];
    const float* W2 = (const float*)d_in[20]; const float* b2 = (const float*)d_in[21];
    const float* fg = (const float*)d_in[22]; const float* fb = (const float*)d_in[23];

    static int smem_set = 0;
    if (!smem_set) {
        cudaFuncSetAttribute(mm_kernel, cudaFuncAttributeMaxDynamicSharedMemorySize, MMSMEM);
        cudaFuncSetAttribute(flash_kernel, cudaFuncAttributeMaxDynamicSharedMemorySize, FSMEM);
        smem_set = 1;
    }

    float *x, *t;
    bf16 *xh, *xl, *ah, *al, *qh, *ql, *kh, *kl, *vth, *vtl, *ch, *cl, *hh, *hl;
    bf16 *qkvh, *qkvl, *woh, *wol, *w1h, *w1l, *w2h, *w2l;
    cudaGetSymbolAddress((void**)&x, g_x);     cudaGetSymbolAddress((void**)&t, g_t);
    cudaGetSymbolAddress((void**)&xh, g_xh);   cudaGetSymbolAddress((void**)&xl, g_xl);
    cudaGetSymbolAddress((void**)&ah, g_ah);   cudaGetSymbolAddress((void**)&al, g_al);
    cudaGetSymbolAddress((void**)&qh, g_qh);   cudaGetSymbolAddress((void**)&ql, g_ql);
    cudaGetSymbolAddress((void**)&kh, g_kh);   cudaGetSymbolAddress((void**)&kl, g_kl);
    cudaGetSymbolAddress((void**)&vth, g_vth); cudaGetSymbolAddress((void**)&vtl, g_vtl);
    cudaGetSymbolAddress((void**)&ch, g_ch);   cudaGetSymbolAddress((void**)&cl, g_cl);
    cudaGetSymbolAddress((void**)&hh, g_hh);   cudaGetSymbolAddress((void**)&hl, g_hl);
    cudaGetSymbolAddress((void**)&qkvh, g_wqkvh); cudaGetSymbolAddress((void**)&qkvl, g_wqkvl);
    cudaGetSymbolAddress((void**)&woh, g_woh); cudaGetSymbolAddress((void**)&wol, g_wol);
    cudaGetSymbolAddress((void**)&w1h, g_w1h); cudaGetSymbolAddress((void**)&w1l, g_w1l);
    cudaGetSymbolAddress((void**)&w2h, g_w2h); cudaGetSymbolAddress((void**)&w2l, g_w2l);

    cvt_all_kernel<<<8192, 256>>>(Wq, Wk, Wv, Wo, W1, W2,
                                  qkvh, qkvl, woh, wol, w1h, w1l, w2h, w2l);

    embed_ln_kernel<<<MTOK, 256>>>(input_ids, type_ids, word_emb, pos_emb,
                                   type_emb, emb_g, emb_b, x, xh, xl);

    for (int l = 0; l < LL; l++) {
        const bf16* qkh = qkvh + (long)l * NQKV * DD;
        const bf16* qkl = qkvl + (long)l * NQKV * DD;
        // fused QKV
        mm_kernel<<<dim3(18, 32), 128, MMSMEM>>>(xh, xl, 0, qkh, qkl, 0,
            bq + l * DD, bk + l * DD, bv + l * DD, 1.f, MTOK, NQKV, DD,
            nullptr, qh, ql, kh, kl, vth, vtl, 0, 5);
        // fused attention (QK^T + softmax + PV)
        flash_kernel<<<dim3(4, NHB), 256, FSMEM>>>(qh, ql, kh, kl, vth, vtl,
                                                   amask, ch, cl);
        // O projection -> fp32 t
        mm_kernel<<<dim3(6, 32), 128, MMSMEM>>>(ch, cl, 0,
            woh + (long)l * DD * DD, wol + (long)l * DD * DD, 0,
            nullptr, nullptr, nullptr, 1.f, MTOK, DD, DD,
            t, nullptr, nullptr, nullptr, nullptr, nullptr, nullptr, 0, 0);
        ln768_kernel<<<MTOK, 256>>>(t, x, bo + l * DD, ag + l * DD, ab + l * DD,
                                    nullptr, ah, al, 1e-5f);
        // FFN1 -> hi/lo h (+bias)
        mm_kernel<<<dim3(24, 32), 128, MMSMEM>>>(ah, al, 0,
            w1h + (long)l * FF * DD, w1l + (long)l * FF * DD, 0,
            b1 + l * FF, nullptr, nullptr, 1.f, MTOK, FF, DD,
            nullptr, hh, hl, nullptr, nullptr, nullptr, nullptr, 0, 1);
        // FFN2 -> fp32 t
        mm_kernel<<<dim3(6, 32), 128, MMSMEM>>>(hh, hl, 0,
            w2h + (long)l * DD * FF, w2l + (long)l * DD * FF, 0,
            nullptr, nullptr, nullptr, 1.f, MTOK, DD, FF,
            t, nullptr, nullptr, nullptr, nullptr, nullptr, nullptr, 0, 0);
        ln768_kernel<<<MTOK, 256>>>(t, nullptr, b2 + l * DD, fg + l * DD,
                                    fb + l * DD, x, xh, xl, 1e-5f);
    }

    cudaMemcpyAsync(d_out, x, (size_t)MTOK * DD * sizeof(float),
                    cudaMemcpyDeviceToDevice);
}

// round 13
// speedup vs baseline: 3.1023x; 1.0033x over previous
#include <cuda_runtime.h>
#include <cuda_bf16.h>
#include <stdint.h>
#include <math.h>

#define BB 8
#define SS 512
#define DD 768
#define HH 12
#define DKK 64
#define FF 3072
#define LL 12
#define MTOK (BB*SS)
#define NHB (BB*HH)
#define SCALE 0.125f
#define NQKV 2304

typedef __nv_bfloat16 bf16;

// ------------------------------- scratch -----------------------------------
__device__ __align__(256) float g_x[MTOK*DD];
__device__ __align__(256) float g_t[MTOK*DD];
__device__ __align__(256) bf16 g_xh[MTOK*DD], g_xl[MTOK*DD];
__device__ __align__(256) bf16 g_ah[MTOK*DD], g_al[MTOK*DD];
__device__ __align__(256) bf16 g_qh[MTOK*DD], g_ql[MTOK*DD];
__device__ __align__(256) bf16 g_kh[MTOK*DD], g_kl[MTOK*DD];
__device__ __align__(256) bf16 g_vth[MTOK*DD], g_vtl[MTOK*DD];   // V^T [b,h,dk,s]
__device__ __align__(256) bf16 g_ch[MTOK*DD], g_cl[MTOK*DD];
__device__ __align__(256) bf16 g_hh[MTOK*FF], g_hl[MTOK*FF];
__device__ __align__(256) bf16 g_wqkvh[(long)LL*NQKV*DD], g_wqkvl[(long)LL*NQKV*DD];
__device__ __align__(256) bf16 g_woh[LL*DD*DD], g_wol[LL*DD*DD];
__device__ __align__(256) bf16 g_w1h[(long)LL*FF*DD], g_w1l[(long)LL*FF*DD];
__device__ __align__(256) bf16 g_w2h[(long)LL*DD*FF], g_w2l[(long)LL*DD*FF];

// ----------------------------- helpers --------------------------------------
__device__ __forceinline__ uint32_t smem_u32(const void* p) {
    uint32_t a;
    asm("{ .reg .u64 t; cvta.to.shared.u64 t, %1; cvt.u32.u64 %0, t; }"
        : "=r"(a) : "l"(p));
    return a;
}
__device__ __forceinline__ void cpasync16(uint32_t saddr, const void* gaddr) {
    asm volatile("cp.async.ca.shared.global [%0], [%1], 16;"
                 :: "r"(saddr), "l"(gaddr) : "memory");
}
__device__ __forceinline__ void ldmx4(uint32_t* r, uint32_t addr) {
    asm volatile("ldmatrix.sync.aligned.m8n8.x4.shared.b16 {%0,%1,%2,%3}, [%4];"
                 : "=r"(r[0]), "=r"(r[1]), "=r"(r[2]), "=r"(r[3]) : "r"(addr));
}
__device__ __forceinline__ void mma16816(float* c, const uint32_t* a,
                                         uint32_t b0, uint32_t b1) {
    asm volatile(
        "mma.sync.aligned.m16n8k16.row.col.f32.bf16.bf16.f32 "
        "{%0,%1,%2,%3}, {%4,%5,%6,%7}, {%8,%9}, {%0,%1,%2,%3};"
        : "+f"(c[0]), "+f"(c[1]), "+f"(c[2]), "+f"(c[3])
        : "r"(a[0]), "r"(a[1]), "r"(a[2]), "r"(a[3]), "r"(b0), "r"(b1));
}
__device__ __forceinline__ void store_hl4(bf16* __restrict__ H, bf16* __restrict__ L,
                                          long dst, const float* v) {
    union { bf16 b[4]; uint2 u; } uh, ul;
    #pragma unroll
    for (int i = 0; i < 4; i++) {
        bf16 h = __float2bfloat16_rn(v[i]);
        uh.b[i] = h;
        ul.b[i] = __float2bfloat16_rn(v[i] - __bfloat162float(h));
    }
    *(uint2*)(H + dst) = uh.u;
    *(uint2*)(L + dst) = ul.u;
}
__device__ __forceinline__ uint32_t packbf2(float a, float b) {
    __nv_bfloat162 t = __floats2bfloat162_rn(a, b);
    return *(uint32_t*)&t;
}

// ------------------------- mm_kernel (128x128, 4 warps) ----------------------
#define MATB 10240
#define STGB (4*MATB)
#define MMSMEM 81920

extern __shared__ __align__(16) char smem_[];

__global__ void __launch_bounds__(128, 2) mm_kernel(
    const bf16* __restrict__ Ah, const bf16* __restrict__ Al, long sA,
    const bf16* __restrict__ Bh, const bf16* __restrict__ Bl, long sB,
    const float* __restrict__ bias, const float* __restrict__ bias2,
    const float* __restrict__ bias3, float alpha, int M, int N, int K,
    float* __restrict__ outF, bf16* __restrict__ o1H, bf16* __restrict__ o1L,
    bf16* __restrict__ o2H, bf16* __restrict__ o2L,
    bf16* __restrict__ o3H, bf16* __restrict__ o3L, long sC, int mode)
{
    uint32_t su = smem_u32(smem_);
    int tid = threadIdx.x, wid = tid >> 5, lane = tid & 31;
    int wm = wid & 1, wn = wid >> 1;
    int z = blockIdx.z;
    Ah += (long)z * sA;  Al += (long)z * sA;
    Bh += (long)z * sB;  Bl += (long)z * sB;
    int m0 = blockIdx.y * 128, n0 = blockIdx.x * 128;

    const int C = K >> 5;
    float acc[4][8][4];
    #pragma unroll
    for (int i = 0; i < 4; i++)
        #pragma unroll
        for (int j = 0; j < 8; j++)
            #pragma unroll
            for (int q = 0; q < 4; q++) acc[i][j][q] = 0.f;

    auto loadst = [&](int c, int s) {
        int k0 = c << 5;
        uint32_t sbase = su + s * STGB;
        #pragma unroll
        for (int i = 0; i < 4; i++) {
            int ch = tid + i * 128;
            int row = ch >> 2, c16 = ch & 3;
            uint32_t so = sbase + row * 80 + c16 * 16;
            long ka = (long)(m0 + row) * K + k0 + c16 * 8;
            long kb = (long)(n0 + row) * K + k0 + c16 * 8;
            cpasync16(so,            Ah + ka);
            cpasync16(so + MATB,     Al + ka);
            cpasync16(so + 2 * MATB, Bh + kb);
            cpasync16(so + 3 * MATB, Bl + kb);
        }
        asm volatile("cp.async.commit_group;" ::: "memory");
    };

    auto compute = [&](int s) {
        uint32_t tb = su + s * STGB;
        #pragma unroll
        for (int kk = 0; kk < 2; kk++) {
            int kb = kk * 32;
            uint32_t ah[4][4], al[4][4];
            #pragma unroll
            for (int mt = 0; mt < 4; mt++) {
                uint32_t ad = tb + (wm * 64 + mt * 16 + (lane & 15)) * 80
                              + kb + ((lane >> 4) * 16);
                ldmx4(ah[mt], ad);
                ldmx4(al[mt], ad + MATB);
            }
            uint32_t bh[2][4], bl[2][4];
            uint32_t bbase = tb + 2 * MATB
                           + (wn * 64 + (lane >> 4) * 8 + (lane & 7)) * 80
                           + kb + (((lane >> 3) & 1) * 16);
            ldmx4(bh[0], bbase);
            ldmx4(bl[0], bbase + MATB);
            #pragma unroll
            for (int p = 0; p < 4; p++) {
                int cur = p & 1;
                if (p < 3) {
                    uint32_t bd = bbase + (p + 1) * 16 * 80;
                    ldmx4(bh[cur ^ 1], bd);
                    ldmx4(bl[cur ^ 1], bd + MATB);
                }
                // term-major issue: same-accumulator MMAs are 8 apart
                #pragma unroll
                for (int half = 0; half < 2; half++)
                    #pragma unroll
                    for (int mt = 0; mt < 4; mt++)
                        mma16816(acc[mt][p * 2 + half], ah[mt],
                                 bh[cur][half * 2], bh[cur][half * 2 + 1]);
                #pragma unroll
                for (int half = 0; half < 2; half++)
                    #pragma unroll
                    for (int mt = 0; mt < 4; mt++)
                        mma16816(acc[mt][p * 2 + half], ah[mt],
                                 bl[cur][half * 2], bl[cur][half * 2 + 1]);
                #pragma unroll
                for (int half = 0; half < 2; half++)
                    #pragma unroll
                    for (int mt = 0; mt < 4; mt++)
                        mma16816(acc[mt][p * 2 + half], al[mt],
                                 bh[cur][half * 2], bh[cur][half * 2 + 1]);
            }
        }
    };

    loadst(0, 0);
    for (int c = 0; c < C; c++) {
        if (c + 1 < C) {
            loadst(c + 1, (c + 1) & 1);
            asm volatile("cp.async.wait_group 1;" ::: "memory");
        } else {
            asm volatile("cp.async.wait_group 0;" ::: "memory");
        }
        __syncthreads();
        compute(c & 1);
        __syncthreads();
    }

    float* Cs = (float*)smem_;   // [128][132]
    {
        int gr = lane >> 2, gc = (lane & 3) * 2;
        #pragma unroll
        for (int mt = 0; mt < 4; mt++)
            #pragma unroll
            for (int nt = 0; nt < 8; nt++) {
                int row = wm * 64 + mt * 16 + gr;
                int col = wn * 64 + nt * 8 + gc;
                Cs[row * 132 + col]           = acc[mt][nt][0];
                Cs[row * 132 + col + 1]       = acc[mt][nt][1];
                Cs[(row + 8) * 132 + col]     = acc[mt][nt][2];
                Cs[(row + 8) * 132 + col + 1] = acc[mt][nt][3];
            }
    }
    __syncthreads();

    if (mode == 0) {
        for (int idx = tid; idx < 128 * 32; idx += 128) {
            int rr = idx >> 5, c4 = (idx & 31) << 2;
            float4 vv = *(const float4*)(Cs + rr * 132 + c4);
            vv.x *= alpha; vv.y *= alpha; vv.z *= alpha; vv.w *= alpha;
            *(float4*)(outF + (long)z * sC + (long)(m0 + rr) * N + n0 + c4) = vv;
        }
    } else if (mode == 1) {
        for (int idx = tid; idx < 128 * 32; idx += 128) {
            int rr = idx >> 5, c4 = (idx & 31) << 2;
            float4 vv = *(const float4*)(Cs + rr * 132 + c4);
            float v[4] = {vv.x, vv.y, vv.z, vv.w};
            if (bias) {
                float4 bb = *(const float4*)(bias + n0 + c4);
                v[0] += bb.x; v[1] += bb.y; v[2] += bb.z; v[3] += bb.w;
            }
            store_hl4(o1H, o1L, (long)(m0 + rr) * N + n0 + c4, v);
        }
    } else {
        int seg = n0 / DD;            // 0:Q 1:K 2:V
        int nl0 = n0 - seg * DD;
        if (seg < 2) {
            const float* bb = (seg == 0) ? bias : bias2;
            bf16* H = (seg == 0) ? o1H : o2H;
            bf16* L = (seg == 0) ? o1L : o2L;
            for (int idx = tid; idx < 128 * 32; idx += 128) {
                int rr = idx >> 5, c4 = (idx & 31) << 2;
                float4 vv = *(const float4*)(Cs + rr * 132 + c4);
                float4 bbv = *(const float4*)(bb + nl0 + c4);
                float v[4] = {vv.x + bbv.x, vv.y + bbv.y, vv.z + bbv.z, vv.w + bbv.w};
                int mg = m0 + rr, b = mg >> 9, sI = mg & 511;
                int ng = nl0 + c4, hh = ng >> 6, dk = ng & 63;
                long dst = (((long)(b * HH + hh) * SS + sI) << 6) + dk;
                store_hl4(H, L, dst, v);
            }
        } else {
            int b = m0 >> 9, s0v = m0 & 511;
            for (int idx = tid; idx < 128 * 32; idx += 128) {
                int n = idx >> 5, rg = (idx & 31) << 2;
                int ng = nl0 + n, hh = ng >> 6, dk = ng & 63;
                float badd = bias3[ng];
                float v[4];
                #pragma unroll
                for (int i = 0; i < 4; i++) v[i] = Cs[(rg + i) * 132 + n] + badd;
                long dst = (((long)(b * HH + hh) * DKK + dk) << 9) + s0v + rg;
                store_hl4(o3H, o3L, dst, v);
            }
        }
    }
}

// --------------------------- flash attention ---------------------------------
#define QPITCH 144
#define VPITCH 272
#define QS_OFF 0
#define QSB 18432
#define KS_OFF (2*QSB)
#define KSTG (2*QSB)
#define VS_OFF (KS_OFF + 2*KSTG)
#define VSB 17408
#define VSTG (2*VSB)
#define FSMEM (VS_OFF + 2*VSTG)    // 180224

__global__ void __launch_bounds__(256, 1) flash_kernel(
    const bf16* __restrict__ qh, const bf16* __restrict__ ql,
    const bf16* __restrict__ kh, const bf16* __restrict__ kl,
    const bf16* __restrict__ vth, const bf16* __restrict__ vtl,
    const float* __restrict__ amask,
    bf16* __restrict__ ch, bf16* __restrict__ cl)
{
    uint32_t su = smem_u32(smem_);
    int tid = threadIdx.x, w = tid >> 5, lane = tid & 31;
    int z = blockIdx.y;
    int b = z / HH, h = z - b * HH;
    int q0 = blockIdx.x * 128;
    const bf16* Qh = qh + (long)z * SS * DKK;
    const bf16* Ql = ql + (long)z * SS * DKK;
    const bf16* Kh = kh + (long)z * SS * DKK;
    const bf16* Kl = kl + (long)z * SS * DKK;
    const bf16* Vh = vth + (long)z * DKK * SS;
    const bf16* Vl = vtl + (long)z * DKK * SS;

    for (int i = tid; i < 1024; i += 256) {
        int r = i >> 3, c = i & 7;
        uint32_t so = su + QS_OFF + r * QPITCH + c * 16;
        long go = (long)(q0 + r) * DKK + c * 8;
        cpasync16(so,        Qh + go);
        cpasync16(so + QSB,  Ql + go);
    }
    auto loadKV = [&](int kt, int s) {
        for (int i = tid; i < 1024; i += 256) {
            int r = i >> 3, c = i & 7;
            uint32_t so = su + KS_OFF + s * KSTG + r * QPITCH + c * 16;
            long go = (long)(kt * 128 + r) * DKK + c * 8;
            cpasync16(so,        Kh + go);
            cpasync16(so + QSB,  Kl + go);
        }
        for (int i = tid; i < 1024; i += 256) {
            int r = i >> 4, c = i & 15;
            uint32_t so = su + VS_OFF + s * VSTG + r * VPITCH + c * 16;
            long go = (long)r * SS + kt * 128 + c * 8;
            cpasync16(so,        Vh + go);
            cpasync16(so + VSB,  Vl + go);
        }
        asm volatile("cp.async.commit_group;" ::: "memory");
    };
    loadKV(0, 0);

    float acc_o[8][4];
    #pragma unroll
    for (int j = 0; j < 8; j++)
        #pragma unroll
        for (int q = 0; q < 4; q++) acc_o[j][q] = 0.f;
    float rm[2] = {-INFINITY, -INFINITY};
    float rl[2] = {0.f, 0.f};
    int gr = lane >> 2, gc2 = (lane & 3) * 2;

    for (int kt = 0; kt < 4; kt++) {
        int s = kt & 1;
        asm volatile("cp.async.wait_group 0;" ::: "memory");
        __syncthreads();
        if (kt + 1 < 4) loadKV(kt + 1, s ^ 1);

        // S = Q K^T (3-term, term-major, B double-buffered)
        float accs[16][4];
        #pragma unroll
        for (int j = 0; j < 16; j++)
            #pragma unroll
            for (int q = 0; q < 4; q++) accs[j][q] = 0.f;
        uint32_t kbase = su + KS_OFF + s * KSTG;
        #pragma unroll
        for (int kb = 0; kb < 4; kb++) {
            uint32_t aqh[4], aql[4];
            uint32_t ad = su + QS_OFF + (w * 16 + (lane & 15)) * QPITCH
                          + kb * 32 + ((lane >> 4) * 16);
            ldmx4(aqh, ad);
            ldmx4(aql, ad + QSB);
            uint32_t bhf[2][4], blf[2][4];
            uint32_t bd0 = kbase + ((lane >> 4) * 8 + (lane & 7)) * QPITCH
                           + kb * 32 + (((lane >> 3) & 1) * 16);
            ldmx4(bhf[0], bd0);
            ldmx4(blf[0], bd0 + QSB);
            #pragma unroll
            for (int pr = 0; pr < 8; pr++) {
                int cur = pr & 1;
                if (pr < 7) {
                    uint32_t bd = bd0 + (pr + 1) * 16 * QPITCH;
                    ldmx4(bhf[cur ^ 1], bd);
                    ldmx4(blf[cur ^ 1], bd + QSB);
                }
                #pragma unroll
                for (int hf = 0; hf < 2; hf++)
                    mma16816(accs[pr * 2 + hf], aqh, bhf[cur][hf * 2], bhf[cur][hf * 2 + 1]);
                #pragma unroll
                for (int hf = 0; hf < 2; hf++)
                    mma16816(accs[pr * 2 + hf], aqh, blf[cur][hf * 2], blf[cur][hf * 2 + 1]);
                #pragma unroll
                for (int hf = 0; hf < 2; hf++)
                    mma16816(accs[pr * 2 + hf], aql, bhf[cur][hf * 2], bhf[cur][hf * 2 + 1]);
            }
        }

        // mask + scale + tile row max
        const float* mrow = amask + b * SS + kt * 128;
        float tmax0 = -INFINITY, tmax1 = -INFINITY;
        #pragma unroll
        for (int nt = 0; nt < 16; nt++) {
            int c0 = nt * 8 + gc2;
            float m0 = mrow[c0], m1 = mrow[c0 + 1];
            float v0 = accs[nt][0] * SCALE, v1 = accs[nt][1] * SCALE;
            float v2 = accs[nt][2] * SCALE, v3 = accs[nt][3] * SCALE;
            if (m0 == 0.f) { v0 = -1e9f; v2 = -1e9f; }
            if (m1 == 0.f) { v1 = -1e9f; v3 = -1e9f; }
            accs[nt][0] = v0; accs[nt][1] = v1; accs[nt][2] = v2; accs[nt][3] = v3;
            tmax0 = fmaxf(tmax0, fmaxf(v0, v1));
            tmax1 = fmaxf(tmax1, fmaxf(v2, v3));
        }
        tmax0 = fmaxf(tmax0, __shfl_xor_sync(0xffffffffu, tmax0, 1));
        tmax0 = fmaxf(tmax0, __shfl_xor_sync(0xffffffffu, tmax0, 2));
        tmax1 = fmaxf(tmax1, __shfl_xor_sync(0xffffffffu, tmax1, 1));
        tmax1 = fmaxf(tmax1, __shfl_xor_sync(0xffffffffu, tmax1, 2));
        float nm0 = fmaxf(rm[0], tmax0), nm1 = fmaxf(rm[1], tmax1);
        float al0 = __expf(rm[0] - nm0), al1 = __expf(rm[1] - nm1);
        rm[0] = nm0; rm[1] = nm1;
        #pragma unroll
        for (int j = 0; j < 8; j++) {
            acc_o[j][0] *= al0; acc_o[j][1] *= al0;
            acc_o[j][2] *= al1; acc_o[j][3] *= al1;
        }
        rl[0] *= al0; rl[1] *= al1;

        // exp, pack P frags, PV (3-term, term-major, V double-buffered)
        uint32_t vbase = su + VS_OFF + s * VSTG;
        float rs0 = 0.f, rs1 = 0.f;
        #pragma unroll
        for (int kc = 0; kc < 8; kc++) {
            float p[2][4];
            #pragma unroll
            for (int hf = 0; hf < 2; hf++) {
                int nt = kc * 2 + hf;
                p[hf][0] = __expf(accs[nt][0] - nm0);
                p[hf][1] = __expf(accs[nt][1] - nm0);
                p[hf][2] = __expf(accs[nt][2] - nm1);
                p[hf][3] = __expf(accs[nt][3] - nm1);
                rs0 += p[hf][0] + p[hf][1];
                rs1 += p[hf][2] + p[hf][3];
            }
            uint32_t pah[4], pal[4];
            #pragma unroll
            for (int hf = 0; hf < 2; hf++) {
                float h0 = __bfloat162float(__float2bfloat16_rn(p[hf][0]));
                float h1 = __bfloat162float(__float2bfloat16_rn(p[hf][1]));
                float h2 = __bfloat162float(__float2bfloat16_rn(p[hf][2]));
                float h3 = __bfloat162float(__float2bfloat16_rn(p[hf][3]));
                pah[hf * 2]     = packbf2(h0, h1);
                pah[hf * 2 + 1] = packbf2(h2, h3);
                pal[hf * 2]     = packbf2(p[hf][0] - h0, p[hf][1] - h1);
                pal[hf * 2 + 1] = packbf2(p[hf][2] - h2, p[hf][3] - h3);
            }
            uint32_t vhf[2][4], vlf[2][4];
            uint32_t vd0 = vbase + ((lane >> 4) * 8 + (lane & 7)) * VPITCH
                           + kc * 32 + (((lane >> 3) & 1) * 16);
            ldmx4(vhf[0], vd0);
            ldmx4(vlf[0], vd0 + VSB);
            #pragma unroll
            for (int vp = 0; vp < 4; vp++) {
                int cur = vp & 1;
                if (vp < 3) {
                    uint32_t vd = vd0 + (vp + 1) * 16 * VPITCH;
                    ldmx4(vhf[cur ^ 1], vd);
                    ldmx4(vlf[cur ^ 1], vd + VSB);
                }
                #pragma unroll
                for (int hf = 0; hf < 2; hf++)
                    mma16816(acc_o[vp * 2 + hf], pah, vhf[cur][hf * 2], vhf[cur][hf * 2 + 1]);
                #pragma unroll
                for (int hf = 0; hf < 2; hf++)
                    mma16816(acc_o[vp * 2 + hf], pah, vlf[cur][hf * 2], vlf[cur][hf * 2 + 1]);
                #pragma unroll
                for (int hf = 0; hf < 2; hf++)
                    mma16816(acc_o[vp * 2 + hf], pal, vhf[cur][hf * 2], vhf[cur][hf * 2 + 1]);
            }
        }
        rl[0] += rs0;
        rl[1] += rs1;
    }
    // quad-reduce row sums
    rl[0] += __shfl_xor_sync(0xffffffffu, rl[0], 1);
    rl[0] += __shfl_xor_sync(0xffffffffu, rl[0], 2);
    rl[1] += __shfl_xor_sync(0xffffffffu, rl[1], 1);
    rl[1] += __shfl_xor_sync(0xffffffffu, rl[1], 2);
    __syncthreads();

    float* Cs = (float*)(smem_ + KS_OFF);     // [128][68]
    {
        float inv0 = 1.f / rl[0], inv1 = 1.f / rl[1];
        int r0 = w * 16 + gr;
        #pragma unroll
        for (int no = 0; no < 8; no++) {
            int col = no * 8 + gc2;
            Cs[r0 * 68 + col]           = acc_o[no][0] * inv0;
            Cs[r0 * 68 + col + 1]       = acc_o[no][1] * inv0;
            Cs[(r0 + 8) * 68 + col]     = acc_o[no][2] * inv1;
            Cs[(r0 + 8) * 68 + col + 1] = acc_o[no][3] * inv1;
        }
    }
    __syncthreads();
    for (int idx = tid; idx < 128 * 16; idx += 256) {
        int r = idx >> 4, c4 = (idx & 15) << 2;
        float4 vv = *(const float4*)(Cs + r * 68 + c4);
        float v[4] = {vv.x, vv.y, vv.z, vv.w};
        long dst = ((long)(b * SS + q0 + r)) * DD + h * DKK + c4;
        store_hl4(ch, cl, dst, v);
    }
}

// --------------------------- elementwise kernels -----------------------------
__device__ __forceinline__ float bsum(float v, float* sh) {
    int lane = threadIdx.x & 31, w = threadIdx.x >> 5;
    #pragma unroll
    for (int o = 16; o > 0; o >>= 1) v += __shfl_xor_sync(0xffffffffu, v, o);
    if (lane == 0) sh[w] = v;
    __syncthreads();
    float r = 0.f;
    #pragma unroll
    for (int i = 0; i < 8; i++) r += sh[i];
    __syncthreads();
    return r;
}
__device__ __forceinline__ void wsplit(bf16* H, bf16* L, long i, float v) {
    bf16 h = __float2bfloat16_rn(v);
    H[i] = h;
    L[i] = __float2bfloat16_rn(v - __bfloat162float(h));
}

#define S1 ((long)LL*DD*DD)
#define S2 ((long)LL*FF*DD)
__global__ void cvt_all_kernel(const float* __restrict__ Wq, const float* __restrict__ Wk,
                               const float* __restrict__ Wv, const float* __restrict__ Wo,
                               const float* __restrict__ W1, const float* __restrict__ W2,
                               bf16* __restrict__ qkvh, bf16* __restrict__ qkvl,
                               bf16* __restrict__ woh, bf16* __restrict__ wol,
                               bf16* __restrict__ w1h, bf16* __restrict__ w1l,
                               bf16* __restrict__ w2h, bf16* __restrict__ w2l) {
    const long total = 4 * S1 + 2 * S2;
    long i = (long)blockIdx.x * 256 + threadIdx.x;
    long stride = (long)gridDim.x * 256;
    for (; i < total; i += stride) {
        long j = i;
        if (j < 3 * S1) {
            int seg = (int)(j / S1);
            long r = j - (long)seg * S1;
            const float* src = (seg == 0) ? Wq : (seg == 1) ? Wk : Wv;
            long l = r / (DD * DD);
            long rem = r - l * (DD * DD);
            long n = rem / DD, k = rem - n * DD;
            long dst = (l * NQKV + seg * DD + n) * DD + k;
            wsplit(qkvh, qkvl, dst, src[r]);
        } else if (j < 4 * S1) {
            long r = j - 3 * S1;
            wsplit(woh, wol, r, Wo[r]);
        } else if (j < 4 * S1 + S2) {
            long r = j - 4 * S1;
            wsplit(w1h, w1l, r, W1[r]);
        } else {
            long r = j - 4 * S1 - S2;
            wsplit(w2h, w2l, r, W2[r]);
        }
    }
}

__global__ void embed_ln_kernel(const int* __restrict__ ids, const int* __restrict__ tt,
                                const float* __restrict__ we, const float* __restrict__ pe,
                                const float* __restrict__ te, const float* __restrict__ gamma,
                                const float* __restrict__ beta, float* __restrict__ outF,
                                bf16* __restrict__ outH, bf16* __restrict__ outL) {
    __shared__ float sh[8];
    int m = blockIdx.x, s = m & (SS - 1);
    int id = ids[m], ty = tt[m], t = threadIdx.x;
    float v[3];
    #pragma unroll
    for (int i = 0; i < 3; i++) {
        int d = t + i * 256;
        v[i] = we[(long)id * DD + d] + te[(long)ty * DD + d] + pe[(long)s * DD + d];
    }
    float mu = bsum(v[0] + v[1] + v[2], sh) * (1.f / DD);
    float qs = 0.f;
    #pragma unroll
    for (int i = 0; i < 3; i++) { float d0 = v[i] - mu; qs += d0 * d0; }
    float rstd = rsqrtf(bsum(qs, sh) * (1.f / DD) + 1e-12f);
    #pragma unroll
    for (int i = 0; i < 3; i++) {
        int d = t + i * 256;
        float y = (v[i] - mu) * rstd * gamma[d] + beta[d];
        outF[(long)m * DD + d] = y;
        wsplit(outH, outL, (long)m * DD + d, y);
    }
}

__global__ void ln768_kernel(const float* __restrict__ in, const float* __restrict__ resid,
                             const float* __restrict__ bias, const float* __restrict__ gamma,
                             const float* __restrict__ beta, float* __restrict__ outF,
                             bf16* __restrict__ outH, bf16* __restrict__ outL, float eps) {
    __shared__ float sh[8];
    long m = blockIdx.x;
    int t = threadIdx.x;
    float v[3];
    #pragma unroll
    for (int i = 0; i < 3; i++) {
        int d = t + i * 256;
        float x = in[m * DD + d];
        if (bias) x += bias[d];
        if (resid) x += resid[m * DD + d];
        v[i] = x;
    }
    float mu = bsum(v[0] + v[1] + v[2], sh) * (1.f / DD);
    float qs = 0.f;
    #pragma unroll
    for (int i = 0; i < 3; i++) { float d0 = v[i] - mu; qs += d0 * d0; }
    float rstd = rsqrtf(bsum(qs, sh) * (1.f / DD) + eps);
    #pragma unroll
    for (int i = 0; i < 3; i++) {
        int d = t + i * 256;
        float y = (v[i] - mu) * rstd * gamma[d] + beta[d];
        if (outF) outF[m * DD + d] = y;
        wsplit(outH, outL, m * DD + d, y);
    }
}

// ------------------------------- launch --------------------------------------
extern "C" void kernel_launch(void* const* d_in, const int* in_sizes, int n_in,
                              void* d_out, int out_size) {
    const int*   input_ids = (const int*)  d_in[0];
    const int*   type_ids  = (const int*)  d_in[1];
    const float* amask     = (const float*)d_in[2];
    const float* word_emb  = (const float*)d_in[3];
    const float* pos_emb   = (const float*)d_in[4];
    const float* type_emb  = (const float*)d_in[5];
    const float* emb_g     = (const float*)d_in[6];
    const float* emb_b     = (const float*)d_in[7];
    const float* Wq = (const float*)d_in[8];  const float* bq = (const float*)d_in[9];
    const float* Wk = (const float*)d_in[10]; const float* bk = (const float*)d_in[11];
    const float* Wv = (const float*)d_in[12]; const float* bv = (const float*)d_in[13];
    const float* Wo = (const float*)d_in[14]; const float* bo = (const float*)d_in[15];
    const float* ag = (const float*)d_in[16]; const float* ab = (const float*)d_in[17];
    const float* W1 = (const float*)d_in[18]; const float* b1 = (const float*)d_in[19];
    const float* W2 = (const float*)d_in[20]; const float* b2 = (const float*)d_in[21];
    const float* fg = (const float*)d_in[22]; const float* fb = (const float*)d_in[23];

    static int smem_set = 0;
    if (!smem_set) {
        cudaFuncSetAttribute(mm_kernel, cudaFuncAttributeMaxDynamicSharedMemorySize, MMSMEM);
        cudaFuncSetAttribute(flash_kernel, cudaFuncAttributeMaxDynamicSharedMemorySize, FSMEM);
        smem_set = 1;
    }

    float *x, *t;
    bf16 *xh, *xl, *ah, *al, *qh, *ql, *kh, *kl, *vth, *vtl, *ch, *cl, *hh, *hl;
    bf16 *qkvh, *qkvl, *woh, *wol, *w1h, *w1l, *w2h, *w2l;
    cudaGetSymbolAddress((void**)&x, g_x);     cudaGetSymbolAddress((void**)&t, g_t);
    cudaGetSymbolAddress((void**)&xh, g_xh);   cudaGetSymbolAddress((void**)&xl, g_xl);
    cudaGetSymbolAddress((void**)&ah, g_ah);   cudaGetSymbolAddress((void**)&al, g_al);
    cudaGetSymbolAddress((void**)&qh, g_qh);   cudaGetSymbolAddress((void**)&ql, g_ql);
    cudaGetSymbolAddress((void**)&kh, g_kh);   cudaGetSymbolAddress((void**)&kl, g_kl);
    cudaGetSymbolAddress((void**)&vth, g_vth); cudaGetSymbolAddress((void**)&vtl, g_vtl);
    cudaGetSymbolAddress((void**)&ch, g_ch);   cudaGetSymbolAddress((void**)&cl, g_cl);
    cudaGetSymbolAddress((void**)&hh, g_hh);   cudaGetSymbolAddress((void**)&hl, g_hl);
    cudaGetSymbolAddress((void**)&qkvh, g_wqkvh); cudaGetSymbolAddress((void**)&qkvl, g_wqkvl);
    cudaGetSymbolAddress((void**)&woh, g_woh); cudaGetSymbolAddress((void**)&wol, g_wol);
    cudaGetSymbolAddress((void**)&w1h, g_w1h); cudaGetSymbolAddress((void**)&w1l, g_w1l);
    cudaGetSymbolAddress((void**)&w2h, g_w2h); cudaGetSymbolAddress((void**)&w2l, g_w2l);

    cvt_all_kernel<<<8192, 256>>>(Wq, Wk, Wv, Wo, W1, W2,
                                  qkvh, qkvl, woh, wol, w1h, w1l, w2h, w2l);

    embed_ln_kernel<<<MTOK, 256>>>(input_ids, type_ids, word_emb, pos_emb,
                                   type_emb, emb_g, emb_b, x, xh, xl);

    for (int l = 0; l < LL; l++) {
        const bf16* qkh = qkvh + (long)l * NQKV * DD;
        const bf16* qkl = qkvl + (long)l * NQKV * DD;
        mm_kernel<<<dim3(18, 32), 128, MMSMEM>>>(xh, xl, 0, qkh, qkl, 0,
            bq + l * DD, bk + l * DD, bv + l * DD, 1.f, MTOK, NQKV, DD,
            nullptr, qh, ql, kh, kl, vth, vtl, 0, 5);
        flash_kernel<<<dim3(4, NHB), 256, FSMEM>>>(qh, ql, kh, kl, vth, vtl,
                                                   amask, ch, cl);
        mm_kernel<<<dim3(6, 32), 128, MMSMEM>>>(ch, cl, 0,
            woh + (long)l * DD * DD, wol + (long)l * DD * DD, 0,
            nullptr, nullptr, nullptr, 1.f, MTOK, DD, DD,
            t, nullptr, nullptr, nullptr, nullptr, nullptr, nullptr, 0, 0);
        ln768_kernel<<<MTOK, 256>>>(t, x, bo + l * DD, ag + l * DD, ab + l * DD,
                                    nullptr, ah, al, 1e-5f);
        mm_kernel<<<dim3(24, 32), 128, MMSMEM>>>(ah, al, 0,
            w1h + (long)l * FF * DD, w1l + (long)l * FF * DD, 0,
            b1 + l * FF, nullptr, nullptr, 1.f, MTOK, FF, DD,
            nullptr, hh, hl, nullptr, nullptr, nullptr, nullptr, 0, 1);
        mm_kernel<<<dim3(6, 32), 128, MMSMEM>>>(hh, hl, 0,
            w2h + (long)l * DD * FF, w2l + (long)l * DD * FF, 0,
            nullptr, nullptr, nullptr, 1.f, MTOK, DD, FF,
            t, nullptr, nullptr, nullptr, nullptr, nullptr, nullptr, 0, 0);
        ln768_kernel<<<MTOK, 256>>>(t, nullptr, b2 + l * DD, fg + l * DD,
                                    fb + l * DD, x, xh, xl, 1e-5f);
    }

    cudaMemcpyAsync(d_out, x, (size_t)MTOK * DD * sizeof(float),
                    cudaMemcpyDeviceToDevice);
}

// round 14
// speedup vs baseline: 3.2850x; 1.0589x over previous
#include <cuda_runtime.h>
#include <cuda_bf16.h>
#include <stdint.h>
#include <math.h>

#define BB 8
#define SS 512
#define DD 768
#define HH 12
#define DKK 64
#define FF 3072
#define LL 12
#define MTOK (BB*SS)
#define NHB (BB*HH)
#define SCALE 0.125f
#define NQKV 2304

typedef __nv_bfloat16 bf16;

// ------------------------------- scratch -----------------------------------
__device__ __align__(256) float g_x[MTOK*DD];
__device__ __align__(256) float g_t[MTOK*DD];
__device__ __align__(256) bf16 g_xh[MTOK*DD], g_xl[MTOK*DD];
__device__ __align__(256) bf16 g_ah[MTOK*DD], g_al[MTOK*DD];
__device__ __align__(256) bf16 g_qh[MTOK*DD], g_ql[MTOK*DD];
__device__ __align__(256) bf16 g_kh[MTOK*DD], g_kl[MTOK*DD];
__device__ __align__(256) bf16 g_vth[MTOK*DD], g_vtl[MTOK*DD];   // V^T [b,h,dk,s]
__device__ __align__(256) bf16 g_ch[MTOK*DD], g_cl[MTOK*DD];
__device__ __align__(256) bf16 g_hh[MTOK*FF], g_hl[MTOK*FF];
__device__ __align__(256) bf16 g_wqkvh[(long)LL*NQKV*DD], g_wqkvl[(long)LL*NQKV*DD];
__device__ __align__(256) bf16 g_woh[LL*DD*DD], g_wol[LL*DD*DD];
__device__ __align__(256) bf16 g_w1h[(long)LL*FF*DD], g_w1l[(long)LL*FF*DD];
__device__ __align__(256) bf16 g_w2h[(long)LL*DD*FF], g_w2l[(long)LL*DD*FF];

// ----------------------------- helpers --------------------------------------
__device__ __forceinline__ uint32_t smem_u32(const void* p) {
    uint32_t a;
    asm("{ .reg .u64 t; cvta.to.shared.u64 t, %1; cvt.u32.u64 %0, t; }"
        : "=r"(a) : "l"(p));
    return a;
}
__device__ __forceinline__ void cpasync16(uint32_t saddr, const void* gaddr) {
    asm volatile("cp.async.ca.shared.global [%0], [%1], 16;"
                 :: "r"(saddr), "l"(gaddr) : "memory");
}
__device__ __forceinline__ void ldmx4(uint32_t* r, uint32_t addr) {
    asm volatile("ldmatrix.sync.aligned.m8n8.x4.shared.b16 {%0,%1,%2,%3}, [%4];"
                 : "=r"(r[0]), "=r"(r[1]), "=r"(r[2]), "=r"(r[3]) : "r"(addr));
}
__device__ __forceinline__ void mma16816(float* c, const uint32_t* a,
                                         uint32_t b0, uint32_t b1) {
    asm volatile(
        "mma.sync.aligned.m16n8k16.row.col.f32.bf16.bf16.f32 "
        "{%0,%1,%2,%3}, {%4,%5,%6,%7}, {%8,%9}, {%0,%1,%2,%3};"
        : "+f"(c[0]), "+f"(c[1]), "+f"(c[2]), "+f"(c[3])
        : "r"(a[0]), "r"(a[1]), "r"(a[2]), "r"(a[3]), "r"(b0), "r"(b1));
}
__device__ __forceinline__ void store_hl4(bf16* __restrict__ H, bf16* __restrict__ L,
                                          long dst, const float* v) {
    union { bf16 b[4]; uint2 u; } uh, ul;
    #pragma unroll
    for (int i = 0; i < 4; i++) {
        bf16 h = __float2bfloat16_rn(v[i]);
        uh.b[i] = h;
        ul.b[i] = __float2bfloat16_rn(v[i] - __bfloat162float(h));
    }
    *(uint2*)(H + dst) = uh.u;
    *(uint2*)(L + dst) = ul.u;
}
__device__ __forceinline__ uint32_t packbf2(float a, float b) {
    __nv_bfloat162 t = __floats2bfloat162_rn(a, b);
    return *(uint32_t*)&t;
}

// ------------------------- mm_kernel (128x128, 4 warps) ----------------------
#define MATB 10240
#define STGB (4*MATB)
#define MMSMEM 81920

extern __shared__ __align__(16) char smem_[];

__global__ void __launch_bounds__(128, 2) mm_kernel(
    const bf16* __restrict__ Ah, const bf16* __restrict__ Al, long sA,
    const bf16* __restrict__ Bh, const bf16* __restrict__ Bl, long sB,
    const float* __restrict__ bias, const float* __restrict__ bias2,
    const float* __restrict__ bias3, float alpha, int M, int N, int K,
    float* __restrict__ outF, bf16* __restrict__ o1H, bf16* __restrict__ o1L,
    bf16* __restrict__ o2H, bf16* __restrict__ o2L,
    bf16* __restrict__ o3H, bf16* __restrict__ o3L, long sC, int mode)
{
    uint32_t su = smem_u32(smem_);
    int tid = threadIdx.x, wid = tid >> 5, lane = tid & 31;
    int wm = wid & 1, wn = wid >> 1;
    int z = blockIdx.z;
    Ah += (long)z * sA;  Al += (long)z * sA;
    Bh += (long)z * sB;  Bl += (long)z * sB;
    int m0 = blockIdx.y * 128, n0 = blockIdx.x * 128;

    const int C = K >> 5;
    float acc[4][8][4];
    #pragma unroll
    for (int i = 0; i < 4; i++)
        #pragma unroll
        for (int j = 0; j < 8; j++)
            #pragma unroll
            for (int q = 0; q < 4; q++) acc[i][j][q] = 0.f;

    auto loadst = [&](int c, int s) {
        int k0 = c << 5;
        uint32_t sbase = su + s * STGB;
        #pragma unroll
        for (int i = 0; i < 4; i++) {
            int ch = tid + i * 128;
            int row = ch >> 2, c16 = ch & 3;
            uint32_t so = sbase + row * 80 + c16 * 16;
            long ka = (long)(m0 + row) * K + k0 + c16 * 8;
            long kb = (long)(n0 + row) * K + k0 + c16 * 8;
            cpasync16(so,            Ah + ka);
            cpasync16(so + MATB,     Al + ka);
            cpasync16(so + 2 * MATB, Bh + kb);
            cpasync16(so + 3 * MATB, Bl + kb);
        }
        asm volatile("cp.async.commit_group;" ::: "memory");
    };

    auto compute = [&](int s) {
        uint32_t tb = su + s * STGB;
        #pragma unroll
        for (int kk = 0; kk < 2; kk++) {
            int kb = kk * 32;
            uint32_t ah[4][4], al[4][4];
            #pragma unroll
            for (int mt = 0; mt < 4; mt++) {
                uint32_t ad = tb + (wm * 64 + mt * 16 + (lane & 15)) * 80
                              + kb + ((lane >> 4) * 16);
                ldmx4(ah[mt], ad);
                ldmx4(al[mt], ad + MATB);
            }
            uint32_t bh[2][4], bl[2][4];
            uint32_t bbase = tb + 2 * MATB
                           + (wn * 64 + (lane >> 4) * 8 + (lane & 7)) * 80
                           + kb + (((lane >> 3) & 1) * 16);
            ldmx4(bh[0], bbase);
            ldmx4(bl[0], bbase + MATB);
            #pragma unroll
            for (int p = 0; p < 4; p++) {
                int cur = p & 1;
                if (p < 3) {
                    uint32_t bd = bbase + (p + 1) * 16 * 80;
                    ldmx4(bh[cur ^ 1], bd);
                    ldmx4(bl[cur ^ 1], bd + MATB);
                }
                #pragma unroll
                for (int half = 0; half < 2; half++)
                    #pragma unroll
                    for (int mt = 0; mt < 4; mt++)
                        mma16816(acc[mt][p * 2 + half], ah[mt],
                                 bh[cur][half * 2], bh[cur][half * 2 + 1]);
                #pragma unroll
                for (int half = 0; half < 2; half++)
                    #pragma unroll
                    for (int mt = 0; mt < 4; mt++)
                        mma16816(acc[mt][p * 2 + half], ah[mt],
                                 bl[cur][half * 2], bl[cur][half * 2 + 1]);
                #pragma unroll
                for (int half = 0; half < 2; half++)
                    #pragma unroll
                    for (int mt = 0; mt < 4; mt++)
                        mma16816(acc[mt][p * 2 + half], al[mt],
                                 bh[cur][half * 2], bh[cur][half * 2 + 1]);
            }
        }
    };

    loadst(0, 0);
    for (int c = 0; c < C; c++) {
        if (c + 1 < C) {
            loadst(c + 1, (c + 1) & 1);
            asm volatile("cp.async.wait_group 1;" ::: "memory");
        } else {
            asm volatile("cp.async.wait_group 0;" ::: "memory");
        }
        __syncthreads();
        compute(c & 1);
        __syncthreads();
    }

    float* Cs = (float*)smem_;   // [128][132]
    {
        int gr = lane >> 2, gc = (lane & 3) * 2;
        #pragma unroll
        for (int mt = 0; mt < 4; mt++)
            #pragma unroll
            for (int nt = 0; nt < 8; nt++) {
                int row = wm * 64 + mt * 16 + gr;
                int col = wn * 64 + nt * 8 + gc;
                Cs[row * 132 + col]           = acc[mt][nt][0];
                Cs[row * 132 + col + 1]       = acc[mt][nt][1];
                Cs[(row + 8) * 132 + col]     = acc[mt][nt][2];
                Cs[(row + 8) * 132 + col + 1] = acc[mt][nt][3];
            }
    }
    __syncthreads();

    if (mode == 0) {
        for (int idx = tid; idx < 128 * 32; idx += 128) {
            int rr = idx >> 5, c4 = (idx & 31) << 2;
            float4 vv = *(const float4*)(Cs + rr * 132 + c4);
            vv.x *= alpha; vv.y *= alpha; vv.z *= alpha; vv.w *= alpha;
            *(float4*)(outF + (long)z * sC + (long)(m0 + rr) * N + n0 + c4) = vv;
        }
    } else if (mode == 1) {
        for (int idx = tid; idx < 128 * 32; idx += 128) {
            int rr = idx >> 5, c4 = (idx & 31) << 2;
            float4 vv = *(const float4*)(Cs + rr * 132 + c4);
            float v[4] = {vv.x, vv.y, vv.z, vv.w};
            if (bias) {
                float4 bb = *(const float4*)(bias + n0 + c4);
                v[0] += bb.x; v[1] += bb.y; v[2] += bb.z; v[3] += bb.w;
            }
            store_hl4(o1H, o1L, (long)(m0 + rr) * N + n0 + c4, v);
        }
    } else {
        int seg = n0 / DD;            // 0:Q 1:K 2:V
        int nl0 = n0 - seg * DD;
        if (seg < 2) {
            const float* bb = (seg == 0) ? bias : bias2;
            bf16* H = (seg == 0) ? o1H : o2H;
            bf16* L = (seg == 0) ? o1L : o2L;
            for (int idx = tid; idx < 128 * 32; idx += 128) {
                int rr = idx >> 5, c4 = (idx & 31) << 2;
                float4 vv = *(const float4*)(Cs + rr * 132 + c4);
                float4 bbv = *(const float4*)(bb + nl0 + c4);
                float v[4] = {vv.x + bbv.x, vv.y + bbv.y, vv.z + bbv.z, vv.w + bbv.w};
                int mg = m0 + rr, b = mg >> 9, sI = mg & 511;
                int ng = nl0 + c4, hh = ng >> 6, dk = ng & 63;
                long dst = (((long)(b * HH + hh) * SS + sI) << 6) + dk;
                store_hl4(H, L, dst, v);
            }
        } else {
            int b = m0 >> 9, s0v = m0 & 511;
            for (int idx = tid; idx < 128 * 32; idx += 128) {
                int n = idx >> 5, rg = (idx & 31) << 2;
                int ng = nl0 + n, hh = ng >> 6, dk = ng & 63;
                float badd = bias3[ng];
                float v[4];
                #pragma unroll
                for (int i = 0; i < 4; i++) v[i] = Cs[(rg + i) * 132 + n] + badd;
                long dst = (((long)(b * HH + hh) * DKK + dk) << 9) + s0v + rg;
                store_hl4(o3H, o3L, dst, v);
            }
        }
    }
}

// ---------------------- mm64m_kernel (64x128, 4 warps) -----------------------
// Half-height tiles for wave packing on small grids (O-proj, FFN2).
// 4 warps of 32x64 (wm in {0,1} m-halves, wn in {0,1} n-halves).
// mode 0: fp32 row-major  (only mode needed here, plus optional bias hi/lo)
#define M64A2 5120          // 64 rows * 80B
#define M64B2 10240         // 128 rows * 80B
#define STG64M (2*M64A2 + 2*M64B2)   // 30720
#define MM64MSMEM 61440

__global__ void __launch_bounds__(128, 2) mm64m_kernel(
    const bf16* __restrict__ Ah, const bf16* __restrict__ Al,
    const bf16* __restrict__ Bh, const bf16* __restrict__ Bl,
    int M, int N, int K, float* __restrict__ outF)
{
    uint32_t su = smem_u32(smem_);
    int tid = threadIdx.x, wid = tid >> 5, lane = tid & 31;
    int wm = wid & 1, wn = wid >> 1;
    int m0 = blockIdx.y * 64, n0 = blockIdx.x * 128;

    const int C = K >> 5;
    float acc[2][8][4];
    #pragma unroll
    for (int i = 0; i < 2; i++)
        #pragma unroll
        for (int j = 0; j < 8; j++)
            #pragma unroll
            for (int q = 0; q < 4; q++) acc[i][j][q] = 0.f;

    auto loadst = [&](int c, int s) {
        int k0 = c << 5;
        uint32_t sbase = su + s * STG64M;
        // A: 64 rows x 32 k (hi+lo): 256 chunks per matrix
        #pragma unroll
        for (int i = 0; i < 2; i++) {
            int ch = tid + i * 128;
            int row = ch >> 2, c16 = ch & 3;
            uint32_t so = sbase + row * 80 + c16 * 16;
            long ka = (long)(m0 + row) * K + k0 + c16 * 8;
            cpasync16(so,          Ah + ka);
            cpasync16(so + M64A2,  Al + ka);
        }
        // B: 128 rows (hi+lo)
        #pragma unroll
        for (int i = 0; i < 4; i++) {
            int ch = tid + i * 128;
            int row = ch >> 2, c16 = ch & 3;
            uint32_t so = sbase + 2 * M64A2 + row * 80 + c16 * 16;
            long kb = (long)(n0 + row) * K + k0 + c16 * 8;
            cpasync16(so,          Bh + kb);
            cpasync16(so + M64B2,  Bl + kb);
        }
        asm volatile("cp.async.commit_group;" ::: "memory");
    };

    auto compute = [&](int s) {
        uint32_t tb = su + s * STG64M;
        #pragma unroll
        for (int kk = 0; kk < 2; kk++) {
            int kb = kk * 32;
            uint32_t ah[2][4], al[2][4];
            #pragma unroll
            for (int mt = 0; mt < 2; mt++) {
                uint32_t ad = tb + (wm * 32 + mt * 16 + (lane & 15)) * 80
                              + kb + ((lane >> 4) * 16);
                ldmx4(ah[mt], ad);
                ldmx4(al[mt], ad + M64A2);
            }
            uint32_t bh[2][4], bl[2][4];
            uint32_t bbase = tb + 2 * M64A2
                           + (wn * 64 + (lane >> 4) * 8 + (lane & 7)) * 80
                           + kb + (((lane >> 3) & 1) * 16);
            ldmx4(bh[0], bbase);
            ldmx4(bl[0], bbase + M64B2);
            #pragma unroll
            for (int p = 0; p < 4; p++) {
                int cur = p & 1;
                if (p < 3) {
                    uint32_t bd = bbase + (p + 1) * 16 * 80;
                    ldmx4(bh[cur ^ 1], bd);
                    ldmx4(bl[cur ^ 1], bd + M64B2);
                }
                #pragma unroll
                for (int half = 0; half < 2; half++)
                    #pragma unroll
                    for (int mt = 0; mt < 2; mt++)
                        mma16816(acc[mt][p * 2 + half], ah[mt],
                                 bh[cur][half * 2], bh[cur][half * 2 + 1]);
                #pragma unroll
                for (int half = 0; half < 2; half++)
                    #pragma unroll
                    for (int mt = 0; mt < 2; mt++)
                        mma16816(acc[mt][p * 2 + half], ah[mt],
                                 bl[cur][half * 2], bl[cur][half * 2 + 1]);
                #pragma unroll
                for (int half = 0; half < 2; half++)
                    #pragma unroll
                    for (int mt = 0; mt < 2; mt++)
                        mma16816(acc[mt][p * 2 + half], al[mt],
                                 bh[cur][half * 2], bh[cur][half * 2 + 1]);
            }
        }
    };

    loadst(0, 0);
    for (int c = 0; c < C; c++) {
        if (c + 1 < C) {
            loadst(c + 1, (c + 1) & 1);
            asm volatile("cp.async.wait_group 1;" ::: "memory");
        } else {
            asm volatile("cp.async.wait_group 0;" ::: "memory");
        }
        __syncthreads();
        compute(c & 1);
        __syncthreads();
    }

    float* Cs = (float*)smem_;   // [64][132]
    {
        int gr = lane >> 2, gc = (lane & 3) * 2;
        #pragma unroll
        for (int mt = 0; mt < 2; mt++)
            #pragma unroll
            for (int nt = 0; nt < 8; nt++) {
                int row = wm * 32 + mt * 16 + gr;
                int col = wn * 64 + nt * 8 + gc;
                Cs[row * 132 + col]           = acc[mt][nt][0];
                Cs[row * 132 + col + 1]       = acc[mt][nt][1];
                Cs[(row + 8) * 132 + col]     = acc[mt][nt][2];
                Cs[(row + 8) * 132 + col + 1] = acc[mt][nt][3];
            }
    }
    __syncthreads();

    for (int idx = tid; idx < 64 * 32; idx += 128) {
        int rr = idx >> 5, c4 = (idx & 31) << 2;
        float4 vv = *(const float4*)(Cs + rr * 132 + c4);
        *(float4*)(outF + (long)(m0 + rr) * N + n0 + c4) = vv;
    }
}

// --------------------------- flash attention ---------------------------------
#define QPITCH 144
#define VPITCH 272
#define QS_OFF 0
#define QSB 18432
#define KS_OFF (2*QSB)
#define KSTG (2*QSB)
#define VS_OFF (KS_OFF + 2*KSTG)
#define VSB 17408
#define VSTG (2*VSB)
#define FSMEM (VS_OFF + 2*VSTG)    // 180224

__global__ void __launch_bounds__(256, 1) flash_kernel(
    const bf16* __restrict__ qh, const bf16* __restrict__ ql,
    const bf16* __restrict__ kh, const bf16* __restrict__ kl,
    const bf16* __restrict__ vth, const bf16* __restrict__ vtl,
    const float* __restrict__ amask,
    bf16* __restrict__ ch, bf16* __restrict__ cl)
{
    uint32_t su = smem_u32(smem_);
    int tid = threadIdx.x, w = tid >> 5, lane = tid & 31;
    int z = blockIdx.y;
    int b = z / HH, h = z - b * HH;
    int q0 = blockIdx.x * 128;
    const bf16* Qh = qh + (long)z * SS * DKK;
    const bf16* Ql = ql + (long)z * SS * DKK;
    const bf16* Kh = kh + (long)z * SS * DKK;
    const bf16* Kl = kl + (long)z * SS * DKK;
    const bf16* Vh = vth + (long)z * DKK * SS;
    const bf16* Vl = vtl + (long)z * DKK * SS;

    for (int i = tid; i < 1024; i += 256) {
        int r = i >> 3, c = i & 7;
        uint32_t so = su + QS_OFF + r * QPITCH + c * 16;
        long go = (long)(q0 + r) * DKK + c * 8;
        cpasync16(so,        Qh + go);
        cpasync16(so + QSB,  Ql + go);
    }
    auto loadKV = [&](int kt, int s) {
        for (int i = tid; i < 1024; i += 256) {
            int r = i >> 3, c = i & 7;
            uint32_t so = su + KS_OFF + s * KSTG + r * QPITCH + c * 16;
            long go = (long)(kt * 128 + r) * DKK + c * 8;
            cpasync16(so,        Kh + go);
            cpasync16(so + QSB,  Kl + go);
        }
        for (int i = tid; i < 1024; i += 256) {
            int r = i >> 4, c = i & 15;
            uint32_t so = su + VS_OFF + s * VSTG + r * VPITCH + c * 16;
            long go = (long)r * SS + kt * 128 + c * 8;
            cpasync16(so,        Vh + go);
            cpasync16(so + VSB,  Vl + go);
        }
        asm volatile("cp.async.commit_group;" ::: "memory");
    };
    loadKV(0, 0);

    float acc_o[8][4];
    #pragma unroll
    for (int j = 0; j < 8; j++)
        #pragma unroll
        for (int q = 0; q < 4; q++) acc_o[j][q] = 0.f;
    float rm[2] = {-INFINITY, -INFINITY};
    float rl[2] = {0.f, 0.f};
    int gr = lane >> 2, gc2 = (lane & 3) * 2;

    for (int kt = 0; kt < 4; kt++) {
        int s = kt & 1;
        asm volatile("cp.async.wait_group 0;" ::: "memory");
        __syncthreads();
        if (kt + 1 < 4) loadKV(kt + 1, s ^ 1);

        float accs[16][4];
        #pragma unroll
        for (int j = 0; j < 16; j++)
            #pragma unroll
            for (int q = 0; q < 4; q++) accs[j][q] = 0.f;
        uint32_t kbase = su + KS_OFF + s * KSTG;
        #pragma unroll
        for (int kb = 0; kb < 4; kb++) {
            uint32_t aqh[4], aql[4];
            uint32_t ad = su + QS_OFF + (w * 16 + (lane & 15)) * QPITCH
                          + kb * 32 + ((lane >> 4) * 16);
            ldmx4(aqh, ad);
            ldmx4(aql, ad + QSB);
            uint32_t bhf[2][4], blf[2][4];
            uint32_t bd0 = kbase + ((lane >> 4) * 8 + (lane & 7)) * QPITCH
                           + kb * 32 + (((lane >> 3) & 1) * 16);
            ldmx4(bhf[0], bd0);
            ldmx4(blf[0], bd0 + QSB);
            #pragma unroll
            for (int pr = 0; pr < 8; pr++) {
                int cur = pr & 1;
                if (pr < 7) {
                    uint32_t bd = bd0 + (pr + 1) * 16 * QPITCH;
                    ldmx4(bhf[cur ^ 1], bd);
                    ldmx4(blf[cur ^ 1], bd + QSB);
                }
                #pragma unroll
                for (int hf = 0; hf < 2; hf++)
                    mma16816(accs[pr * 2 + hf], aqh, bhf[cur][hf * 2], bhf[cur][hf * 2 + 1]);
                #pragma unroll
                for (int hf = 0; hf < 2; hf++)
                    mma16816(accs[pr * 2 + hf], aqh, blf[cur][hf * 2], blf[cur][hf * 2 + 1]);
                #pragma unroll
                for (int hf = 0; hf < 2; hf++)
                    mma16816(accs[pr * 2 + hf], aql, bhf[cur][hf * 2], bhf[cur][hf * 2 + 1]);
            }
        }

        const float* mrow = amask + b * SS + kt * 128;
        float tmax0 = -INFINITY, tmax1 = -INFINITY;
        #pragma unroll
        for (int nt = 0; nt < 16; nt++) {
            int c0 = nt * 8 + gc2;
            float m0 = mrow[c0], m1 = mrow[c0 + 1];
            float v0 = accs[nt][0] * SCALE, v1 = accs[nt][1] * SCALE;
            float v2 = accs[nt][2] * SCALE, v3 = accs[nt][3] * SCALE;
            if (m0 == 0.f) { v0 = -1e9f; v2 = -1e9f; }
            if (m1 == 0.f) { v1 = -1e9f; v3 = -1e9f; }
            accs[nt][0] = v0; accs[nt][1] = v1; accs[nt][2] = v2; accs[nt][3] = v3;
            tmax0 = fmaxf(tmax0, fmaxf(v0, v1));
            tmax1 = fmaxf(tmax1, fmaxf(v2, v3));
        }
        tmax0 = fmaxf(tmax0, __shfl_xor_sync(0xffffffffu, tmax0, 1));
        tmax0 = fmaxf(tmax0, __shfl_xor_sync(0xffffffffu, tmax0, 2));
        tmax1 = fmaxf(tmax1, __shfl_xor_sync(0xffffffffu, tmax1, 1));
        tmax1 = fmaxf(tmax1, __shfl_xor_sync(0xffffffffu, tmax1, 2));
        float nm0 = fmaxf(rm[0], tmax0), nm1 = fmaxf(rm[1], tmax1);
        float al0 = __expf(rm[0] - nm0), al1 = __expf(rm[1] - nm1);
        rm[0] = nm0; rm[1] = nm1;
        #pragma unroll
        for (int j = 0; j < 8; j++) {
            acc_o[j][0] *= al0; acc_o[j][1] *= al0;
            acc_o[j][2] *= al1; acc_o[j][3] *= al1;
        }
        rl[0] *= al0; rl[1] *= al1;

        uint32_t vbase = su + VS_OFF + s * VSTG;
        float rs0 = 0.f, rs1 = 0.f;
        #pragma unroll
        for (int kc = 0; kc < 8; kc++) {
            float p[2][4];
            #pragma unroll
            for (int hf = 0; hf < 2; hf++) {
                int nt = kc * 2 + hf;
                p[hf][0] = __expf(accs[nt][0] - nm0);
                p[hf][1] = __expf(accs[nt][1] - nm0);
                p[hf][2] = __expf(accs[nt][2] - nm1);
                p[hf][3] = __expf(accs[nt][3] - nm1);
                rs0 += p[hf][0] + p[hf][1];
                rs1 += p[hf][2] + p[hf][3];
            }
            uint32_t pah[4], pal[4];
            #pragma unroll
            for (int hf = 0; hf < 2; hf++) {
                float h0 = __bfloat162float(__float2bfloat16_rn(p[hf][0]));
                float h1 = __bfloat162float(__float2bfloat16_rn(p[hf][1]));
                float h2 = __bfloat162float(__float2bfloat16_rn(p[hf][2]));
                float h3 = __bfloat162float(__float2bfloat16_rn(p[hf][3]));
                pah[hf * 2]     = packbf2(h0, h1);
                pah[hf * 2 + 1] = packbf2(h2, h3);
                pal[hf * 2]     = packbf2(p[hf][0] - h0, p[hf][1] - h1);
                pal[hf * 2 + 1] = packbf2(p[hf][2] - h2, p[hf][3] - h3);
            }
            uint32_t vhf[2][4], vlf[2][4];
            uint32_t vd0 = vbase + ((lane >> 4) * 8 + (lane & 7)) * VPITCH
                           + kc * 32 + (((lane >> 3) & 1) * 16);
            ldmx4(vhf[0], vd0);
            ldmx4(vlf[0], vd0 + VSB);
            #pragma unroll
            for (int vp = 0; vp < 4; vp++) {
                int cur = vp & 1;
                if (vp < 3) {
                    uint32_t vd = vd0 + (vp + 1) * 16 * VPITCH;
                    ldmx4(vhf[cur ^ 1], vd);
                    ldmx4(vlf[cur ^ 1], vd + VSB);
                }
                #pragma unroll
                for (int hf = 0; hf < 2; hf++)
                    mma16816(acc_o[vp * 2 + hf], pah, vhf[cur][hf * 2], vhf[cur][hf * 2 + 1]);
                #pragma unroll
                for (int hf = 0; hf < 2; hf++)
                    mma16816(acc_o[vp * 2 + hf], pah, vlf[cur][hf * 2], vlf[cur][hf * 2 + 1]);
                #pragma unroll
                for (int hf = 0; hf < 2; hf++)
                    mma16816(acc_o[vp * 2 + hf], pal, vhf[cur][hf * 2], vhf[cur][hf * 2 + 1]);
            }
        }
        rl[0] += rs0;
        rl[1] += rs1;
    }
    rl[0] += __shfl_xor_sync(0xffffffffu, rl[0], 1);
    rl[0] += __shfl_xor_sync(0xffffffffu, rl[0], 2);
    rl[1] += __shfl_xor_sync(0xffffffffu, rl[1], 1);
    rl[1] += __shfl_xor_sync(0xffffffffu, rl[1], 2);
    __syncthreads();

    float* Cs = (float*)(smem_ + KS_OFF);     // [128][68]
    {
        float inv0 = 1.f / rl[0], inv1 = 1.f / rl[1];
        int r0 = w * 16 + gr;
        #pragma unroll
        for (int no = 0; no < 8; no++) {
            int col = no * 8 + gc2;
            Cs[r0 * 68 + col]           = acc_o[no][0] * inv0;
            Cs[r0 * 68 + col + 1]       = acc_o[no][1] * inv0;
            Cs[(r0 + 8) * 68 + col]     = acc_o[no][2] * inv1;
            Cs[(r0 + 8) * 68 + col + 1] = acc_o[no][3] * inv1;
        }
    }
    __syncthreads();
    for (int idx = tid; idx < 128 * 16; idx += 256) {
        int r = idx >> 4, c4 = (idx & 15) << 2;
        float4 vv = *(const float4*)(Cs + r * 68 + c4);
        float v[4] = {vv.x, vv.y, vv.z, vv.w};
        long dst = ((long)(b * SS + q0 + r)) * DD + h * DKK + c4;
        store_hl4(ch, cl, dst, v);
    }
}

// --------------------------- elementwise kernels -----------------------------
__device__ __forceinline__ float bsum(float v, float* sh) {
    int lane = threadIdx.x & 31, w = threadIdx.x >> 5;
    #pragma unroll
    for (int o = 16; o > 0; o >>= 1) v += __shfl_xor_sync(0xffffffffu, v, o);
    if (lane == 0) sh[w] = v;
    __syncthreads();
    float r = 0.f;
    #pragma unroll
    for (int i = 0; i < 8; i++) r += sh[i];
    __syncthreads();
    return r;
}
__device__ __forceinline__ void wsplit(bf16* H, bf16* L, long i, float v) {
    bf16 h = __float2bfloat16_rn(v);
    H[i] = h;
    L[i] = __float2bfloat16_rn(v - __bfloat162float(h));
}

#define S1 ((long)LL*DD*DD)
#define S2 ((long)LL*FF*DD)
__global__ void cvt_all_kernel(const float* __restrict__ Wq, const float* __restrict__ Wk,
                               const float* __restrict__ Wv, const float* __restrict__ Wo,
                               const float* __restrict__ W1, const float* __restrict__ W2,
                               bf16* __restrict__ qkvh, bf16* __restrict__ qkvl,
                               bf16* __restrict__ woh, bf16* __restrict__ wol,
                               bf16* __restrict__ w1h, bf16* __restrict__ w1l,
                               bf16* __restrict__ w2h, bf16* __restrict__ w2l) {
    const long total = 4 * S1 + 2 * S2;
    long i = (long)blockIdx.x * 256 + threadIdx.x;
    long stride = (long)gridDim.x * 256;
    for (; i < total; i += stride) {
        long j = i;
        if (j < 3 * S1) {
            int seg = (int)(j / S1);
            long r = j - (long)seg * S1;
            const float* src = (seg == 0) ? Wq : (seg == 1) ? Wk : Wv;
            long l = r / (DD * DD);
            long rem = r - l * (DD * DD);
            long n = rem / DD, k = rem - n * DD;
            long dst = (l * NQKV + seg * DD + n) * DD + k;
            wsplit(qkvh, qkvl, dst, src[r]);
        } else if (j < 4 * S1) {
            long r = j - 3 * S1;
            wsplit(woh, wol, r, Wo[r]);
        } else if (j < 4 * S1 + S2) {
            long r = j - 4 * S1;
            wsplit(w1h, w1l, r, W1[r]);
        } else {
            long r = j - 4 * S1 - S2;
            wsplit(w2h, w2l, r, W2[r]);
        }
    }
}

__global__ void embed_ln_kernel(const int* __restrict__ ids, const int* __restrict__ tt,
                                const float* __restrict__ we, const float* __restrict__ pe,
                                const float* __restrict__ te, const float* __restrict__ gamma,
                                const float* __restrict__ beta, float* __restrict__ outF,
                                bf16* __restrict__ outH, bf16* __restrict__ outL) {
    __shared__ float sh[8];
    int m = blockIdx.x, s = m & (SS - 1);
    int id = ids[m], ty = tt[m], t = threadIdx.x;
    float v[3];
    #pragma unroll
    for (int i = 0; i < 3; i++) {
        int d = t + i * 256;
        v[i] = we[(long)id * DD + d] + te[(long)ty * DD + d] + pe[(long)s * DD + d];
    }
    float mu = bsum(v[0] + v[1] + v[2], sh) * (1.f / DD);
    float qs = 0.f;
    #pragma unroll
    for (int i = 0; i < 3; i++) { float d0 = v[i] - mu; qs += d0 * d0; }
    float rstd = rsqrtf(bsum(qs, sh) * (1.f / DD) + 1e-12f);
    #pragma unroll
    for (int i = 0; i < 3; i++) {
        int d = t + i * 256;
        float y = (v[i] - mu) * rstd * gamma[d] + beta[d];
        outF[(long)m * DD + d] = y;
        wsplit(outH, outL, (long)m * DD + d, y);
    }
}

__global__ void ln768_kernel(const float* __restrict__ in, const float* __restrict__ resid,
                             const float* __restrict__ bias, const float* __restrict__ gamma,
                             const float* __restrict__ beta, float* __restrict__ outF,
                             bf16* __restrict__ outH, bf16* __restrict__ outL, float eps) {
    __shared__ float sh[8];
    long m = blockIdx.x;
    int t = threadIdx.x;
    float v[3];
    #pragma unroll
    for (int i = 0; i < 3; i++) {
        int d = t + i * 256;
        float x = in[m * DD + d];
        if (bias) x += bias[d];
        if (resid) x += resid[m * DD + d];
        v[i] = x;
    }
    float mu = bsum(v[0] + v[1] + v[2], sh) * (1.f / DD);
    float qs = 0.f;
    #pragma unroll
    for (int i = 0; i < 3; i++) { float d0 = v[i] - mu; qs += d0 * d0; }
    float rstd = rsqrtf(bsum(qs, sh) * (1.f / DD) + eps);
    #pragma unroll
    for (int i = 0; i < 3; i++) {
        int d = t + i * 256;
        float y = (v[i] - mu) * rstd * gamma[d] + beta[d];
        if (outF) outF[m * DD + d] = y;
        wsplit(outH, outL, m * DD + d, y);
    }
}

// ------------------------------- launch --------------------------------------
extern "C" void kernel_launch(void* const* d_in, const int* in_sizes, int n_in,
                              void* d_out, int out_size) {
    const int*   input_ids = (const int*)  d_in[0];
    const int*   type_ids  = (const int*)  d_in[1];
    const float* amask     = (const float*)d_in[2];
    const float* word_emb  = (const float*)d_in[3];
    const float* pos_emb   = (const float*)d_in[4];
    const float* type_emb  = (const float*)d_in[5];
    const float* emb_g     = (const float*)d_in[6];
    const float* emb_b     = (const float*)d_in[7];
    const float* Wq = (const float*)d_in[8];  const float* bq = (const float*)d_in[9];
    const float* Wk = (const float*)d_in[10]; const float* bk = (const float*)d_in[11];
    const float* Wv = (const float*)d_in[12]; const float* bv = (const float*)d_in[13];
    const float* Wo = (const float*)d_in[14]; const float* bo = (const float*)d_in[15];
    const float* ag = (const float*)d_in[16]; const float* ab = (const float*)d_in[17];
    const float* W1 = (const float*)d_in[18]; const float* b1 = (const float*)d_in[19];
    const float* W2 = (const float*)d_in[20]; const float* b2 = (const float*)d_in[21];
    const float* fg = (const float*)d_in[22]; const float* fb = (const float*)d_in[23];

    static int smem_set = 0;
    if (!smem_set) {
        cudaFuncSetAttribute(mm_kernel, cudaFuncAttributeMaxDynamicSharedMemorySize, MMSMEM);
        cudaFuncSetAttribute(mm64m_kernel, cudaFuncAttributeMaxDynamicSharedMemorySize, MM64MSMEM);
        cudaFuncSetAttribute(flash_kernel, cudaFuncAttributeMaxDynamicSharedMemorySize, FSMEM);
        smem_set = 1;
    }

    float *x, *t;
    bf16 *xh, *xl, *ah, *al, *qh, *ql, *kh, *kl, *vth, *vtl, *ch, *cl, *hh, *hl;
    bf16 *qkvh, *qkvl, *woh, *wol, *w1h, *w1l, *w2h, *w2l;
    cudaGetSymbolAddress((void**)&x, g_x);     cudaGetSymbolAddress((void**)&t, g_t);
    cudaGetSymbolAddress((void**)&xh, g_xh);   cudaGetSymbolAddress((void**)&xl, g_xl);
    cudaGetSymbolAddress((void**)&ah, g_ah);   cudaGetSymbolAddress((void**)&al, g_al);
    cudaGetSymbolAddress((void**)&qh, g_qh);   cudaGetSymbolAddress((void**)&ql, g_ql);
    cudaGetSymbolAddress((void**)&kh, g_kh);   cudaGetSymbolAddress((void**)&kl, g_kl);
    cudaGetSymbolAddress((void**)&vth, g_vth); cudaGetSymbolAddress((void**)&vtl, g_vtl);
    cudaGetSymbolAddress((void**)&ch, g_ch);   cudaGetSymbolAddress((void**)&cl, g_cl);
    cudaGetSymbolAddress((void**)&hh, g_hh);   cudaGetSymbolAddress((void**)&hl, g_hl);
    cudaGetSymbolAddress((void**)&qkvh, g_wqkvh); cudaGetSymbolAddress((void**)&qkvl, g_wqkvl);
    cudaGetSymbolAddress((void**)&woh, g_woh); cudaGetSymbolAddress((void**)&wol, g_wol);
    cudaGetSymbolAddress((void**)&w1h, g_w1h); cudaGetSymbolAddress((void**)&w1l, g_w1l);
    cudaGetSymbolAddress((void**)&w2h, g_w2h); cudaGetSymbolAddress((void**)&w2l, g_w2l);

    cvt_all_kernel<<<8192, 256>>>(Wq, Wk, Wv, Wo, W1, W2,
                                  qkvh, qkvl, woh, wol, w1h, w1l, w2h, w2l);

    embed_ln_kernel<<<MTOK, 256>>>(input_ids, type_ids, word_emb, pos_emb,
                                   type_emb, emb_g, emb_b, x, xh, xl);

    for (int l = 0; l < LL; l++) {
        const bf16* qkh = qkvh + (long)l * NQKV * DD;
        const bf16* qkl = qkvl + (long)l * NQKV * DD;
        // fused QKV (576 CTAs)
        mm_kernel<<<dim3(18, 32), 128, MMSMEM>>>(xh, xl, 0, qkh, qkl, 0,
            bq + l * DD, bk + l * DD, bv + l * DD, 1.f, MTOK, NQKV, DD,
            nullptr, qh, ql, kh, kl, vth, vtl, 0, 5);
        // fused attention
        flash_kernel<<<dim3(4, NHB), 256, FSMEM>>>(qh, ql, kh, kl, vth, vtl,
                                                   amask, ch, cl);
        // O projection -> fp32 t (BM=64: 384 CTAs for wave packing)
        mm64m_kernel<<<dim3(6, 64), 128, MM64MSMEM>>>(ch, cl,
            woh + (long)l * DD * DD, wol + (long)l * DD * DD, MTOK, DD, DD, t);
        ln768_kernel<<<MTOK, 256>>>(t, x, bo + l * DD, ag + l * DD, ab + l * DD,
                                    nullptr, ah, al, 1e-5f);
        // FFN1 -> hi/lo h (+bias) (768 CTAs)
        mm_kernel<<<dim3(24, 32), 128, MMSMEM>>>(ah, al, 0,
            w1h + (long)l * FF * DD, w1l + (long)l * FF * DD, 0,
            b1 + l * FF, nullptr, nullptr, 1.f, MTOK, FF, DD,
            nullptr, hh, hl, nullptr, nullptr, nullptr, nullptr, 0, 1);
        // FFN2 -> fp32 t (BM=64: 384 CTAs)
        mm64m_kernel<<<dim3(6, 64), 128, MM64MSMEM>>>(hh, hl,
            w2h + (long)l * DD * FF, w2l + (long)l * DD * FF, MTOK, DD, FF, t);
        ln768_kernel<<<MTOK, 256>>>(t, nullptr, b2 + l * DD, fg + l * DD,
                                    fb + l * DD, x, xh, xl, 1e-5f);
    }

    cudaMemcpyAsync(d_out, x, (size_t)MTOK * DD * sizeof(float),
                    cudaMemcpyDeviceToDevice);
}